// round 2
// baseline (speedup 1.0000x reference)
#include <cuda_runtime.h>
#include <cuda_bf16.h>
#include <math.h>
#include <stdint.h>

#define BB 4
#define TT 1024
#define CC 1024
#define HH 16
#define DD 64
#define NE 4194304     // B*T*C
#define LOG_DECAY (-0.6065306597126334f)
#define GN_EPS 64e-5f

// ---------------- static scratch (100M floats = 400MB) ----------------
__device__ float gScratch[104857600];

// float offsets within gScratch
#define OXR  ((size_t)0*NE)
#define OXW  ((size_t)1*NE)
#define OXK  ((size_t)2*NE)
#define OXV  ((size_t)3*NE)
#define OXA  ((size_t)4*NE)
#define OXG  ((size_t)5*NE)
#define ORB  ((size_t)6*NE)
#define OKB  ((size_t)7*NE)
#define OVB  ((size_t)8*NE)
#define OAB  ((size_t)9*NE)
#define OGB  ((size_t)10*NE)
#define OWL  ((size_t)11*NE)
#define OVMX ((size_t)12*NE)
#define OHW  ((size_t)13*NE)
#define OHA  (OHW + 262144)
#define OHV  (OHA + 262144)
#define OHG  (OHV + 131072)
#define OEW  ((size_t)14*NE)
#define OBBA ((size_t)15*NE)
#define OAAA ((size_t)16*NE)
#define OKK2 ((size_t)17*NE)
#define ORRA ((size_t)18*NE)
#define OVVA ((size_t)19*NE)
#define OOB  ((size_t)20*NE)
#define OZB  ((size_t)21*NE)
#define OW1T ((size_t)22*NE)
#define OW2T (OW1T + 65536)
#define OA1T (OW2T + 65536)
#define OA2T (OA1T + 65536)
#define OV1T (OA2T + 65536)
#define OV2T (OV1T + 32768)
#define OG1T (OV2T + 32768)
#define OG2T (OG1T + 131072)

__device__ __forceinline__ float sigm_(float x){ return 1.f/(1.f+expf(-x)); }

// ---------------- token-shift mix ----------------
__global__ __launch_bounds__(256) void mix_kernel(
    const float* __restrict__ x,
    const float* __restrict__ mr, const float* __restrict__ mw, const float* __restrict__ mk,
    const float* __restrict__ mv, const float* __restrict__ ma, const float* __restrict__ mg,
    float* __restrict__ XR, float* __restrict__ XW, float* __restrict__ XK,
    float* __restrict__ XV, float* __restrict__ XA, float* __restrict__ XG)
{
    int row = blockIdx.x;            // b*T + t
    int t = row & (TT-1);
    int c4 = threadIdx.x;            // float4 index within row (0..255)
    const float4* xv4 = (const float4*)x;
    float4 xc = xv4[(size_t)row*256 + c4];
    float4 xp = make_float4(0.f,0.f,0.f,0.f);
    if (t > 0) xp = xv4[(size_t)(row-1)*256 + c4];
    float4 dx = make_float4(xp.x-xc.x, xp.y-xc.y, xp.z-xc.z, xp.w-xc.w);
    size_t o = (size_t)row*256 + c4;
    float4 m;
    m = ((const float4*)mr)[c4];
    ((float4*)XR)[o] = make_float4(xc.x+dx.x*m.x, xc.y+dx.y*m.y, xc.z+dx.z*m.z, xc.w+dx.w*m.w);
    m = ((const float4*)mw)[c4];
    ((float4*)XW)[o] = make_float4(xc.x+dx.x*m.x, xc.y+dx.y*m.y, xc.z+dx.z*m.z, xc.w+dx.w*m.w);
    m = ((const float4*)mk)[c4];
    ((float4*)XK)[o] = make_float4(xc.x+dx.x*m.x, xc.y+dx.y*m.y, xc.z+dx.z*m.z, xc.w+dx.w*m.w);
    m = ((const float4*)mv)[c4];
    ((float4*)XV)[o] = make_float4(xc.x+dx.x*m.x, xc.y+dx.y*m.y, xc.z+dx.z*m.z, xc.w+dx.w*m.w);
    m = ((const float4*)ma)[c4];
    ((float4*)XA)[o] = make_float4(xc.x+dx.x*m.x, xc.y+dx.y*m.y, xc.z+dx.z*m.z, xc.w+dx.w*m.w);
    m = ((const float4*)mg)[c4];
    ((float4*)XG)[o] = make_float4(xc.x+dx.x*m.x, xc.y+dx.y*m.y, xc.z+dx.z*m.z, xc.w+dx.w*m.w);
}

// ---------------- small transpose: dst(cols,rows) = src(rows,cols)^T ----------------
__global__ void transpose_k(const float* __restrict__ src, float* __restrict__ dst,
                            int rows, int cols)
{
    int i = blockIdx.x*256 + threadIdx.x;
    if (i < rows*cols){
        int r = i / cols, c = i - r*cols;
        dst[(size_t)c*rows + r] = src[i];
    }
}

// ---------------- tf32 GEMM: C[M,N] = A[M,K] * B[N,K]^T (+bias, act) ----------------
__device__ __forceinline__ float to_tf32(float x){
    uint32_t u; asm("cvt.rna.tf32.f32 %0, %1;" : "=r"(u) : "f"(x));
    return __uint_as_float(u);
}
__device__ __forceinline__ void mma8(float* d, const uint32_t* a, const uint32_t* b){
    asm volatile("mma.sync.aligned.m16n8k8.row.col.f32.tf32.tf32.f32 "
        "{%0,%1,%2,%3}, {%4,%5,%6,%7}, {%8,%9}, {%0,%1,%2,%3};"
        : "+f"(d[0]), "+f"(d[1]), "+f"(d[2]), "+f"(d[3])
        : "r"(a[0]), "r"(a[1]), "r"(a[2]), "r"(a[3]), "r"(b[0]), "r"(b[1]));
}
__device__ __forceinline__ int swz(int r, int c){
    return r*32 + (int)((((((unsigned)c>>2) ^ ((unsigned)r & 7u)) << 2)) | ((unsigned)c & 3u));
}

// mode: 0 = plain(+bias), 1 = tanh, 2 = scale*sigmoid(x+bias)
__global__ __launch_bounds__(256) void gemm_tf32(
    const float* __restrict__ A, const float* __restrict__ B, float* __restrict__ C,
    int M, int N, int K, const float* __restrict__ bias, int mode, float scale)
{
    __shared__ float As[128*32];
    __shared__ float Bs[64*32];
    int bm0 = blockIdx.x * 128, bn0 = blockIdx.y * 64;
    int tid = threadIdx.x;
    int wid = tid >> 5, lane = tid & 31;
    int wm = (wid & 3) * 32, wn = (wid >> 2) * 32;
    int grp = lane >> 2, thr = lane & 3;
    float acc[2][4][4];
    #pragma unroll
    for (int i=0;i<2;i++)
      #pragma unroll
      for (int j=0;j<4;j++)
        #pragma unroll
        for (int l=0;l<4;l++) acc[i][j][l]=0.f;

    for (int k0 = 0; k0 < K; k0 += 32){
        #pragma unroll
        for (int i=0;i<4;i++){
            int id = tid + 256*i;
            int r = id >> 3, cc4 = (id & 7)*4;
            float4 v = *(const float4*)(A + (size_t)(bm0+r)*K + k0 + cc4);
            float4 tv = make_float4(to_tf32(v.x), to_tf32(v.y), to_tf32(v.z), to_tf32(v.w));
            *(float4*)(&As[swz(r, cc4)]) = tv;
        }
        #pragma unroll
        for (int i=0;i<2;i++){
            int id = tid + 256*i;
            int r = id >> 3, cc4 = (id & 7)*4;
            float4 v = make_float4(0.f,0.f,0.f,0.f);
            if (bn0 + r < N) v = *(const float4*)(B + (size_t)(bn0+r)*K + k0 + cc4);
            float4 tv = make_float4(to_tf32(v.x), to_tf32(v.y), to_tf32(v.z), to_tf32(v.w));
            *(float4*)(&Bs[swz(r, cc4)]) = tv;
        }
        __syncthreads();
        #pragma unroll
        for (int kk=0; kk<4; kk++){
            uint32_t af[2][4], bf[4][2];
            #pragma unroll
            for (int mt=0;mt<2;mt++){
                int m = wm + mt*16;
                af[mt][0]=__float_as_uint(As[swz(m+grp  , kk*8+thr  )]);
                af[mt][1]=__float_as_uint(As[swz(m+grp+8, kk*8+thr  )]);
                af[mt][2]=__float_as_uint(As[swz(m+grp  , kk*8+thr+4)]);
                af[mt][3]=__float_as_uint(As[swz(m+grp+8, kk*8+thr+4)]);
            }
            #pragma unroll
            for (int nt=0;nt<4;nt++){
                int n = wn + nt*8;
                bf[nt][0]=__float_as_uint(Bs[swz(n+grp, kk*8+thr  )]);
                bf[nt][1]=__float_as_uint(Bs[swz(n+grp, kk*8+thr+4)]);
            }
            #pragma unroll
            for (int mt=0;mt<2;mt++)
                #pragma unroll
                for (int nt=0;nt<4;nt++)
                    mma8(acc[mt][nt], af[mt], bf[nt]);
        }
        __syncthreads();
    }
    #pragma unroll
    for (int mt=0;mt<2;mt++){
        #pragma unroll
        for (int nt=0;nt<4;nt++){
            #pragma unroll
            for (int half=0; half<2; half++){
                int row = bm0 + wm + mt*16 + grp + half*8;
                int col = bn0 + wn + nt*8 + thr*2;
                if (col < N){
                    float v0 = acc[mt][nt][half*2+0];
                    float v1 = acc[mt][nt][half*2+1];
                    if (bias){ v0 += bias[col]; v1 += bias[col+1]; }
                    if (mode==1){ v0 = tanhf(v0); v1 = tanhf(v1); }
                    else if (mode==2){ v0 = scale*sigm_(v0); v1 = scale*sigm_(v1); }
                    float* cp = C + (size_t)row*N + col;
                    cp[0] = v0; cp[1] = v1;
                }
            }
        }
    }
}

// ---------------- scan-operand prep ----------------
__global__ __launch_bounds__(256) void prep_kernel(
    const float* __restrict__ K, const float* __restrict__ A, const float* __restrict__ V,
    const float* __restrict__ WL, const float* __restrict__ VMIX, const float* __restrict__ vfirst,
    const float* __restrict__ R,
    const float* __restrict__ k_k, const float* __restrict__ k_a,
    float* __restrict__ EW, float* __restrict__ BBo, float* __restrict__ AAo,
    float* __restrict__ K2o, float* __restrict__ Ro, float* __restrict__ Vo)
{
    int gw = (blockIdx.x*256 + threadIdx.x) >> 5;   // warp per (b,t,h)
    int lane = threadIdx.x & 31;
    int h = gw & 15, t = (gw >> 4) & 1023, b = gw >> 14;
    int c = h*64 + lane*2;
    size_t btc = ((size_t)(b*TT + t))*CC + c;
    float2 k  = *(const float2*)&K[btc];
    float2 kw = *(const float2*)&k_k[c];
    float2 ka = *(const float2*)&k_a[c];
    float2 a  = *(const float2*)&A[btc];
    float kk0 = k.x*kw.x, kk1 = k.y*kw.y;
    float ss = kk0*kk0 + kk1*kk1;
    #pragma unroll
    for (int off=16; off>0; off>>=1) ss += __shfl_xor_sync(0xffffffffu, ss, off);
    float inv = 1.f / fmaxf(sqrtf(ss), 1e-12f);
    kk0 *= inv; kk1 *= inv;
    float2 wl = *(const float2*)&WL[btc];
    float2 v  = *(const float2*)&V[btc];
    float2 vf = *(const float2*)&vfirst[btc];
    float2 vm = *(const float2*)&VMIX[btc];
    v.x = v.x + (vf.x - v.x)*vm.x;
    v.y = v.y + (vf.y - v.y)*vm.y;
    float2 r = *(const float2*)&R[btc];
    float k20 = k.x*(1.f + (a.x-1.f)*ka.x);
    float k21 = k.y*(1.f + (a.y-1.f)*ka.y);
    size_t bhtd = ((size_t)((b*HH + h)*TT + t))*64 + lane*2;
    *(float2*)&EW[bhtd]  = make_float2(expf(wl.x), expf(wl.y));
    *(float2*)&BBo[bhtd] = make_float2(kk0*a.x, kk1*a.y);
    *(float2*)&AAo[bhtd] = make_float2(-kk0, -kk1);
    *(float2*)&K2o[bhtd] = make_float2(k20, k21);
    *(float2*)&Ro[bhtd]  = r;
    *(float2*)&Vo[bhtd]  = v;
}

// ---------------- sequential RWKV7 scan ----------------
__device__ __forceinline__ float red8(float v){
    v += __shfl_xor_sync(0xffffffffu, v, 1);
    v += __shfl_xor_sync(0xffffffffu, v, 2);
    v += __shfl_xor_sync(0xffffffffu, v, 4);
    return v;
}

__global__ __launch_bounds__(256) void scan_kernel(
    const float* __restrict__ EW, const float* __restrict__ BBp, const float* __restrict__ AAp,
    const float* __restrict__ K2p, const float* __restrict__ Rp, const float* __restrict__ Vp,
    float* __restrict__ O)
{
    __shared__ float sm[4*6*64];   // 4 stages x 6 arrays x 64
    int bh = blockIdx.x >> 1;
    int rowBase = (blockIdx.x & 1) * 32;
    int tid = threadIdx.x;
    int row = rowBase + (tid >> 3);
    int col0 = (tid & 7) * 8;
    size_t base = (size_t)bh * TT * 64;

    const float* src0 = EW  + base;
    const float* src1 = BBp + base;
    const float* src2 = AAp + base;
    const float* src3 = K2p + base;
    const float* src4 = Rp  + base;
    const float* src5 = Vp  + base;

    int arr = tid >> 4, seg = tid & 15;  // for tid < 96
    const float* mysrc = (arr==0)?src0:(arr==1)?src1:(arr==2)?src2:(arr==3)?src3:(arr==4)?src4:src5;

    // prefill stages 0..2
    #pragma unroll
    for (int s=0; s<3; s++){
        if (tid < 96){
            const float* g = mysrc + (size_t)s*64 + seg*4;
            unsigned sa = (unsigned)__cvta_generic_to_shared(&sm[s*384 + arr*64 + seg*4]);
            asm volatile("cp.async.ca.shared.global [%0], [%1], 16;"::"r"(sa),"l"(g));
        }
        asm volatile("cp.async.commit_group;");
    }

    float S[8];
    #pragma unroll
    for (int i=0;i<8;i++) S[i]=0.f;

    for (int t=0; t<TT; t++){
        asm volatile("cp.async.wait_group 2;");
        __syncthreads();
        const float* st = &sm[(t & 3) * 384];
        float ew[8], bb[8], aa[8], kk[8], rr[8];
        *(float4*)&ew[0] = *(const float4*)&st[  0 + col0];
        *(float4*)&ew[4] = *(const float4*)&st[  0 + col0 + 4];
        *(float4*)&bb[0] = *(const float4*)&st[ 64 + col0];
        *(float4*)&bb[4] = *(const float4*)&st[ 64 + col0 + 4];
        *(float4*)&aa[0] = *(const float4*)&st[128 + col0];
        *(float4*)&aa[4] = *(const float4*)&st[128 + col0 + 4];
        *(float4*)&kk[0] = *(const float4*)&st[192 + col0];
        *(float4*)&kk[4] = *(const float4*)&st[192 + col0 + 4];
        *(float4*)&rr[0] = *(const float4*)&st[256 + col0];
        *(float4*)&rr[4] = *(const float4*)&st[256 + col0 + 4];
        float vv = st[320 + row];

        float sab = 0.f;
        #pragma unroll
        for (int i=0;i<8;i++) sab += S[i]*aa[i];
        sab = red8(sab);

        float oo = 0.f;
        #pragma unroll
        for (int i=0;i<8;i++){
            S[i] = S[i]*ew[i] + sab*bb[i] + vv*kk[i];
            oo += S[i]*rr[i];
        }
        oo = red8(oo);
        if ((tid & 7) == 0) O[base + (size_t)t*64 + row] = oo;
        __syncthreads();

        int tn = t + 3; if (tn > TT-1) tn = TT-1;
        if (tid < 96){
            const float* g = mysrc + (size_t)tn*64 + seg*4;
            unsigned sa = (unsigned)__cvta_generic_to_shared(&sm[((t+3)&3)*384 + arr*64 + seg*4]);
            asm volatile("cp.async.ca.shared.global [%0], [%1], 16;"::"r"(sa),"l"(g));
        }
        asm volatile("cp.async.commit_group;");
    }
}

// ---------------- post: groupnorm + bonus + gate ----------------
__global__ __launch_bounds__(256) void post_kernel(
    const float* __restrict__ O, const float* __restrict__ Rp, const float* __restrict__ K2p,
    const float* __restrict__ Vp, const float* __restrict__ G,
    const float* __restrict__ r_k, const float* __restrict__ gn_w, const float* __restrict__ gn_b,
    float* __restrict__ Z)
{
    int gw = (blockIdx.x*256 + threadIdx.x) >> 5;
    int lane = threadIdx.x & 31;
    int h = gw & 15, t = (gw >> 4) & 1023, b = gw >> 14;
    size_t bhtd = ((size_t)((b*HH + h)*TT + t))*64 + lane*2;
    float2 o = *(const float2*)&O[bhtd];
    float sm = o.x + o.y;
    #pragma unroll
    for (int off=16; off>0; off>>=1) sm += __shfl_xor_sync(0xffffffffu, sm, off);
    float mean = sm * (1.f/64.f);
    float dx = o.x - mean, dy = o.y - mean;
    float vs = dx*dx + dy*dy;
    #pragma unroll
    for (int off=16; off>0; off>>=1) vs += __shfl_xor_sync(0xffffffffu, vs, off);
    float inv = rsqrtf(vs*(1.f/64.f) + GN_EPS);

    float2 r  = *(const float2*)&Rp[bhtd];
    float2 k2 = *(const float2*)&K2p[bhtd];
    float2 v  = *(const float2*)&Vp[bhtd];
    int c = h*64 + lane*2;
    float2 rk = *(const float2*)&r_k[c];
    float bs = r.x*k2.x*rk.x + r.y*k2.y*rk.y;
    #pragma unroll
    for (int off=16; off>0; off>>=1) bs += __shfl_xor_sync(0xffffffffu, bs, off);

    size_t btc = ((size_t)(b*TT + t))*CC + c;
    float2 g  = *(const float2*)&G[btc];
    float2 w  = *(const float2*)&gn_w[c];
    float2 bb = *(const float2*)&gn_b[c];
    float z0 = ((dx*inv)*w.x + bb.x + bs*v.x) * g.x;
    float z1 = ((dy*inv)*w.y + bb.y + bs*v.y) * g.y;
    *(float2*)&Z[btc] = make_float2(z0, z1);
}

// ---------------- driver ----------------
extern "C" void kernel_launch(void* const* d_in, const int* in_sizes, int n_in,
                              void* d_out, int out_size) {
    const float* x   = (const float*)d_in[0];
    const float* vfi = (const float*)d_in[1];
    const float* x_r = (const float*)d_in[2];
    const float* x_w = (const float*)d_in[3];
    const float* x_k = (const float*)d_in[4];
    const float* x_v = (const float*)d_in[5];
    const float* x_a = (const float*)d_in[6];
    const float* x_g = (const float*)d_in[7];
    const float* Wr  = (const float*)d_in[8];
    const float* Wk  = (const float*)d_in[9];
    const float* Wv  = (const float*)d_in[10];
    const float* Wo  = (const float*)d_in[11];
    const float* w0  = (const float*)d_in[12];
    const float* w1  = (const float*)d_in[13];
    const float* w2  = (const float*)d_in[14];
    const float* a0  = (const float*)d_in[15];
    const float* a1  = (const float*)d_in[16];
    const float* a2  = (const float*)d_in[17];
    const float* v0  = (const float*)d_in[18];
    const float* v1  = (const float*)d_in[19];
    const float* v2  = (const float*)d_in[20];
    const float* g1  = (const float*)d_in[21];
    const float* g2  = (const float*)d_in[22];
    const float* k_k = (const float*)d_in[23];
    const float* k_a = (const float*)d_in[24];
    const float* r_k = (const float*)d_in[25];
    const float* gnw = (const float*)d_in[26];
    const float* gnb = (const float*)d_in[27];
    float* out = (float*)d_out;

    float* S;
    cudaGetSymbolAddress((void**)&S, gScratch);

    // small weight transposes -> (N,K) layouts
    transpose_k<<<(1024*64+255)/256,256>>>(w1, S+OW1T, 1024, 64);
    transpose_k<<<(64*1024+255)/256,256>>>(w2, S+OW2T, 64, 1024);
    transpose_k<<<(1024*64+255)/256,256>>>(a1, S+OA1T, 1024, 64);
    transpose_k<<<(64*1024+255)/256,256>>>(a2, S+OA2T, 64, 1024);
    transpose_k<<<(1024*32+255)/256,256>>>(v1, S+OV1T, 1024, 32);
    transpose_k<<<(32*1024+255)/256,256>>>(v2, S+OV2T, 32, 1024);
    transpose_k<<<(1024*128+255)/256,256>>>(g1, S+OG1T, 1024, 128);
    transpose_k<<<(128*1024+255)/256,256>>>(g2, S+OG2T, 128, 1024);

    // token-shift mixes
    mix_kernel<<<BB*TT,256>>>(x, x_r, x_w, x_k, x_v, x_a, x_g,
                              S+OXR, S+OXW, S+OXK, S+OXV, S+OXA, S+OXG);

    const int M = BB*TT;
    dim3 blk(256);
    // big projections
    gemm_tf32<<<dim3(M/128, 1024/64), blk>>>(S+OXR, Wr, S+ORB, M, 1024, 1024, nullptr, 0, 1.f);
    gemm_tf32<<<dim3(M/128, 1024/64), blk>>>(S+OXK, Wk, S+OKB, M, 1024, 1024, nullptr, 0, 1.f);
    gemm_tf32<<<dim3(M/128, 1024/64), blk>>>(S+OXV, Wv, S+OVB, M, 1024, 1024, nullptr, 0, 1.f);
    // decay chain: hw = tanh(XW @ w1); WL = LOG_DECAY * sigmoid(w0 + hw @ w2)
    gemm_tf32<<<dim3(M/128, 1), blk>>>(S+OXW, S+OW1T, S+OHW, M, 64, 1024, nullptr, 1, 1.f);
    gemm_tf32<<<dim3(M/128, 1024/64), blk>>>(S+OHW, S+OW2T, S+OWL, M, 1024, 64, w0, 2, LOG_DECAY);
    // a chain
    gemm_tf32<<<dim3(M/128, 1), blk>>>(S+OXA, S+OA1T, S+OHA, M, 64, 1024, nullptr, 0, 1.f);
    gemm_tf32<<<dim3(M/128, 1024/64), blk>>>(S+OHA, S+OA2T, S+OAB, M, 1024, 64, a0, 2, 1.f);
    // v-mix chain
    gemm_tf32<<<dim3(M/128, 1), blk>>>(S+OXV, S+OV1T, S+OHV, M, 32, 1024, nullptr, 0, 1.f);
    gemm_tf32<<<dim3(M/128, 1024/64), blk>>>(S+OHV, S+OV2T, S+OVMX, M, 1024, 32, v0, 2, 1.f);
    // gate chain
    gemm_tf32<<<dim3(M/128, 128/64), blk>>>(S+OXG, S+OG1T, S+OHG, M, 128, 1024, nullptr, 2, 1.f);
    gemm_tf32<<<dim3(M/128, 1024/64), blk>>>(S+OHG, S+OG2T, S+OGB, M, 1024, 128, nullptr, 0, 1.f);

    // scan operand prep
    prep_kernel<<<(BB*TT*HH*32)/256, 256>>>(S+OKB, S+OAB, S+OVB, S+OWL, S+OVMX, vfi, S+ORB,
                                            k_k, k_a,
                                            S+OEW, S+OBBA, S+OAAA, S+OKK2, S+ORRA, S+OVVA);
    // sequential scan
    scan_kernel<<<BB*HH*2, 256>>>(S+OEW, S+OBBA, S+OAAA, S+OKK2, S+ORRA, S+OVVA, S+OOB);
    // groupnorm + bonus + gate
    post_kernel<<<(BB*TT*HH*32)/256, 256>>>(S+OOB, S+ORRA, S+OKK2, S+OVVA, S+OGB,
                                            r_k, gnw, gnb, S+OZB);
    // output projection
    gemm_tf32<<<dim3(M/128, 1024/64), blk>>>(S+OZB, Wo, out, M, 1024, 1024, nullptr, 0, 1.f);

    // second output element (v_first passthrough), if requested
    if (out_size >= 2*NE){
        cudaMemcpyAsync(out + NE, vfi, (size_t)NE*sizeof(float), cudaMemcpyDeviceToDevice);
    }
}

// round 4
// speedup vs baseline: 1.5853x; 1.5853x over previous
#include <cuda_runtime.h>
#include <math.h>
#include <stdint.h>

#define BB 4
#define TT 1024
#define CC 1024
#define HH 16
#define DD 64
#define NE 4194304     // B*T*C
#define LOG_DECAY (-0.6065306597126334f)
#define GN_EPS 64e-5f

// ---------------- static scratch ----------------
__device__ float gScratch[104857600];

#define OXR  ((size_t)0*NE)
#define OXW  ((size_t)1*NE)
#define OXK  ((size_t)2*NE)
#define OXV  ((size_t)3*NE)
#define OXA  ((size_t)4*NE)
#define OXG  ((size_t)5*NE)
#define ORB  ((size_t)6*NE)
#define OKB  ((size_t)7*NE)
#define OVB  ((size_t)8*NE)
#define OAB  ((size_t)9*NE)
#define OGB  ((size_t)10*NE)
#define OWL  ((size_t)11*NE)
#define OVMX ((size_t)12*NE)
#define OHW  ((size_t)13*NE)
#define OHA  (OHW + 262144)
#define OHV  (OHA + 262144)
#define OHG  (OHV + 131072)
#define OEW  ((size_t)14*NE)
#define OBBA ((size_t)15*NE)
#define OAAA ((size_t)16*NE)
#define OKK2 ((size_t)17*NE)
#define ORRA ((size_t)18*NE)
#define OVVA ((size_t)19*NE)
#define OOB  ((size_t)20*NE)
#define OZB  ((size_t)21*NE)
#define OW1T ((size_t)22*NE)
#define OW2T (OW1T + 65536)
#define OA1T (OW2T + 65536)
#define OA2T (OA1T + 65536)
#define OV1T (OA2T + 65536)
#define OV2T (OV1T + 32768)
#define OG1T (OV2T + 32768)
#define OG2T (OG1T + 131072)
#define OWRr (OG2T + 131072)
#define OWKr (OWRr + 1048576)
#define OWVr (OWKr + 1048576)
#define OWOr (OWVr + 1048576)

__device__ __forceinline__ float to_tf32(float x){
    uint32_t u; asm("cvt.rna.tf32.f32 %0, %1;" : "=r"(u) : "f"(x));
    return __uint_as_float(u);
}
__device__ __forceinline__ float sigm_(float x){ return 1.f/(1.f+expf(-x)); }

__device__ __forceinline__ void mma8(float* d, const uint32_t* a, const uint32_t* b){
    asm volatile("mma.sync.aligned.m16n8k8.row.col.f32.tf32.tf32.f32 "
        "{%0,%1,%2,%3}, {%4,%5,%6,%7}, {%8,%9}, {%0,%1,%2,%3};"
        : "+f"(d[0]), "+f"(d[1]), "+f"(d[2]), "+f"(d[3])
        : "r"(a[0]), "r"(a[1]), "r"(a[2]), "r"(a[3]), "r"(b[0]), "r"(b[1]));
}
// word-index XOR swizzle within 32-float rows
__device__ __forceinline__ int swz(int r, int c){
    return r*32 + (int)((((((unsigned)c>>2) ^ ((unsigned)r & 7u)) << 2)) | ((unsigned)c & 3u));
}

// ---------------- tf32 GEMM (mma.sync): C[M,N] = A[M,K] * B[N,K]^T ----------------
// CTA tile 128 x NT, k-block 32, cp.async double buffered.
// mode: 0 plain(+bias), 1 tanh, 2 scale*sigmoid(x+bias)
template<int NT>
__global__ void __launch_bounds__(256) gemm_mma(
    const float* __restrict__ A, const float* __restrict__ Bm, float* __restrict__ C,
    int M, int N, int K, const float* __restrict__ bias, int mode, float scale, int round_out)
{
    extern __shared__ float sm[];
    const int AS = 128*32;
    const int BS = NT*32;
    const int STG = AS + BS;
    const int NTN = (NT==128) ? 8 : 4;   // n-subtiles per warp

    int tid = threadIdx.x, wid = tid >> 5, lane = tid & 31;
    int bm0 = blockIdx.x * 128, bn0 = blockIdx.y * NT;
    int grp = lane >> 2, thr = lane & 3;
    int wm = (wid & 3) * 32;
    int wn = (NT==128) ? (wid >> 2) * 64 : (NT==64) ? (wid >> 2) * 32 : 0;
    bool active = (NT >= 64) || (wid < 4);
    int NC = K >> 5;

    float acc[2][NTN][4];
    #pragma unroll
    for (int i=0;i<2;i++)
      #pragma unroll
      for (int j=0;j<NTN;j++)
        #pragma unroll
        for (int l=0;l<4;l++) acc[i][j][l]=0.f;

    auto load_stage = [&](int stg, int c){
        float* as = sm + stg*STG;
        const float* Ag = A + (size_t)bm0*K + c*32;
        #pragma unroll
        for (int i=0;i<4;i++){
            int idx = tid + 256*i; int r = idx>>3, j = idx&7;
            unsigned dst = (unsigned)__cvta_generic_to_shared(&as[swz(r, j*4)]);
            const float* src = Ag + (size_t)r*K + j*4;
            asm volatile("cp.async.cg.shared.global [%0], [%1], 16;"::"r"(dst),"l"(src));
        }
        float* bs = sm + stg*STG + AS;
        const float* Bg = Bm + (size_t)bn0*K + c*32;
        #pragma unroll
        for (int i=0;i<NT/32;i++){
            int idx = tid + 256*i; int r = idx>>3, j = idx&7;
            unsigned dst = (unsigned)__cvta_generic_to_shared(&bs[swz(r, j*4)]);
            const float* src = Bg + (size_t)r*K + j*4;
            asm volatile("cp.async.cg.shared.global [%0], [%1], 16;"::"r"(dst),"l"(src));
        }
    };

    load_stage(0, 0);
    asm volatile("cp.async.commit_group;");

    for (int c = 0; c < NC; c++){
        if (c+1 < NC) load_stage((c+1)&1, c+1);
        asm volatile("cp.async.commit_group;");
        if (c+1 < NC) asm volatile("cp.async.wait_group 1;");
        else          asm volatile("cp.async.wait_group 0;");
        __syncthreads();

        const float* as = sm + (c&1)*STG;
        const float* bs = as + AS;
        if (active){
            #pragma unroll
            for (int kk=0; kk<4; kk++){
                uint32_t af[2][4], bf[NTN][2];
                #pragma unroll
                for (int mt=0;mt<2;mt++){
                    int m = wm + mt*16;
                    af[mt][0]=__float_as_uint(as[swz(m+grp  , kk*8+thr  )]);
                    af[mt][1]=__float_as_uint(as[swz(m+grp+8, kk*8+thr  )]);
                    af[mt][2]=__float_as_uint(as[swz(m+grp  , kk*8+thr+4)]);
                    af[mt][3]=__float_as_uint(as[swz(m+grp+8, kk*8+thr+4)]);
                }
                #pragma unroll
                for (int nt=0;nt<NTN;nt++){
                    int n = wn + nt*8;
                    bf[nt][0]=__float_as_uint(bs[swz(n+grp, kk*8+thr  )]);
                    bf[nt][1]=__float_as_uint(bs[swz(n+grp, kk*8+thr+4)]);
                }
                #pragma unroll
                for (int mt=0;mt<2;mt++)
                    #pragma unroll
                    for (int nt=0;nt<NTN;nt++)
                        mma8(acc[mt][nt], af[mt], bf[nt]);
            }
        }
        __syncthreads();
    }

    if (!active) return;
    #pragma unroll
    for (int mt=0;mt<2;mt++){
        #pragma unroll
        for (int nt=0;nt<NTN;nt++){
            #pragma unroll
            for (int half=0; half<2; half++){
                int row = bm0 + wm + mt*16 + grp + half*8;
                int col = bn0 + wn + nt*8 + thr*2;
                float v0 = acc[mt][nt][half*2+0];
                float v1 = acc[mt][nt][half*2+1];
                if (bias){ v0 += bias[col]; v1 += bias[col+1]; }
                if (mode==1){ v0 = tanhf(v0); v1 = tanhf(v1); }
                else if (mode==2){ v0 = scale*sigm_(v0); v1 = scale*sigm_(v1); }
                if (round_out){ v0 = to_tf32(v0); v1 = to_tf32(v1); }
                float* cp = C + (size_t)row*N + col;
                cp[0] = v0; cp[1] = v1;
            }
        }
    }
}

// ---------------- weight rounding (rna to tf32) ----------------
__global__ __launch_bounds__(256) void round_weights(
    const float* __restrict__ Wr, const float* __restrict__ Wk,
    const float* __restrict__ Wv, const float* __restrict__ Wo, float* __restrict__ Sg)
{
    int idx = blockIdx.x * 256 + threadIdx.x;
    int m = idx >> 20;
    int i = idx & 1048575;
    const float* src = (m == 0) ? Wr : (m == 1) ? Wk : (m == 2) ? Wv : Wo;
    float* dst = Sg + ((m == 0) ? OWRr : (m == 1) ? OWKr : (m == 2) ? OWVr : OWOr);
    dst[i] = to_tf32(src[i]);
}

// ---------------- fused transpose+round of small weights ----------------
__device__ __forceinline__ void do_tr(const float* src, float* dst, int rows, int cols, int li){
    int r = li / cols, c = li - r * cols;
    dst[(size_t)c * rows + r] = to_tf32(src[li]);
}
__global__ __launch_bounds__(256) void transpose_round_all(
    const float* __restrict__ w1, const float* __restrict__ w2,
    const float* __restrict__ a1, const float* __restrict__ a2,
    const float* __restrict__ v1, const float* __restrict__ v2,
    const float* __restrict__ g1, const float* __restrict__ g2, float* __restrict__ Sg)
{
    int idx = blockIdx.x * 256 + threadIdx.x;
    if      (idx < 65536 )  do_tr(w1, Sg+OW1T, 1024, 64,  idx);
    else if (idx < 131072)  do_tr(w2, Sg+OW2T, 64, 1024,  idx-65536);
    else if (idx < 196608)  do_tr(a1, Sg+OA1T, 1024, 64,  idx-131072);
    else if (idx < 262144)  do_tr(a2, Sg+OA2T, 64, 1024,  idx-196608);
    else if (idx < 294912)  do_tr(v1, Sg+OV1T, 1024, 32,  idx-262144);
    else if (idx < 327680)  do_tr(v2, Sg+OV2T, 32, 1024,  idx-294912);
    else if (idx < 458752)  do_tr(g1, Sg+OG1T, 1024, 128, idx-327680);
    else                    do_tr(g2, Sg+OG2T, 128, 1024, idx-458752);
}

// ---------------- token-shift mix (outputs rounded to tf32) ----------------
__global__ __launch_bounds__(256) void mix_kernel(
    const float* __restrict__ x,
    const float* __restrict__ mr, const float* __restrict__ mw, const float* __restrict__ mk,
    const float* __restrict__ mv, const float* __restrict__ ma, const float* __restrict__ mg,
    float* __restrict__ XR, float* __restrict__ XW, float* __restrict__ XK,
    float* __restrict__ XV, float* __restrict__ XA, float* __restrict__ XG)
{
    int row = blockIdx.x;
    int t = row & (TT-1);
    int c4 = threadIdx.x;
    const float4* xv4 = (const float4*)x;
    float4 xc = xv4[(size_t)row*256 + c4];
    float4 xp = make_float4(0.f,0.f,0.f,0.f);
    if (t > 0) xp = xv4[(size_t)(row-1)*256 + c4];
    float4 dx = make_float4(xp.x-xc.x, xp.y-xc.y, xp.z-xc.z, xp.w-xc.w);
    size_t o = (size_t)row*256 + c4;
    float4 m;
    #define MIXOUT(dst, mp) \
        m = ((const float4*)mp)[c4]; \
        ((float4*)dst)[o] = make_float4(to_tf32(xc.x+dx.x*m.x), to_tf32(xc.y+dx.y*m.y), \
                                        to_tf32(xc.z+dx.z*m.z), to_tf32(xc.w+dx.w*m.w));
    MIXOUT(XR, mr) MIXOUT(XW, mw) MIXOUT(XK, mk)
    MIXOUT(XV, mv) MIXOUT(XA, ma) MIXOUT(XG, mg)
    #undef MIXOUT
}

// ---------------- scan-operand prep ----------------
__global__ __launch_bounds__(256) void prep_kernel(
    const float* __restrict__ K, const float* __restrict__ A, const float* __restrict__ V,
    const float* __restrict__ WL, const float* __restrict__ VMIX, const float* __restrict__ vfirst,
    const float* __restrict__ R,
    const float* __restrict__ k_k, const float* __restrict__ k_a,
    float* __restrict__ EW, float* __restrict__ BBo, float* __restrict__ AAo,
    float* __restrict__ K2o, float* __restrict__ Ro, float* __restrict__ Vo)
{
    int gw = (blockIdx.x*256 + threadIdx.x) >> 5;
    int lane = threadIdx.x & 31;
    int h = gw & 15, t = (gw >> 4) & 1023, b = gw >> 14;
    int c = h*64 + lane*2;
    size_t btc = ((size_t)(b*TT + t))*CC + c;
    float2 k  = *(const float2*)&K[btc];
    float2 kw = *(const float2*)&k_k[c];
    float2 ka = *(const float2*)&k_a[c];
    float2 a  = *(const float2*)&A[btc];
    float kk0 = k.x*kw.x, kk1 = k.y*kw.y;
    float ss = kk0*kk0 + kk1*kk1;
    #pragma unroll
    for (int off=16; off>0; off>>=1) ss += __shfl_xor_sync(0xffffffffu, ss, off);
    float inv = 1.f / fmaxf(sqrtf(ss), 1e-12f);
    kk0 *= inv; kk1 *= inv;
    float2 wl = *(const float2*)&WL[btc];
    float2 v  = *(const float2*)&V[btc];
    float2 vf = *(const float2*)&vfirst[btc];
    float2 vm = *(const float2*)&VMIX[btc];
    v.x = v.x + (vf.x - v.x)*vm.x;
    v.y = v.y + (vf.y - v.y)*vm.y;
    float2 r = *(const float2*)&R[btc];
    float k20 = k.x*(1.f + (a.x-1.f)*ka.x);
    float k21 = k.y*(1.f + (a.y-1.f)*ka.y);
    size_t bhtd = ((size_t)((b*HH + h)*TT + t))*64 + lane*2;
    *(float2*)&EW[bhtd]  = make_float2(expf(wl.x), expf(wl.y));
    *(float2*)&BBo[bhtd] = make_float2(kk0*a.x, kk1*a.y);
    *(float2*)&AAo[bhtd] = make_float2(-kk0, -kk1);
    *(float2*)&K2o[bhtd] = make_float2(k20, k21);
    *(float2*)&Ro[bhtd]  = r;
    *(float2*)&Vo[bhtd]  = v;
}

// ---------------- sequential RWKV7 scan (single barrier per step) ----------------
__device__ __forceinline__ float red8(float v){
    v += __shfl_xor_sync(0xffffffffu, v, 1);
    v += __shfl_xor_sync(0xffffffffu, v, 2);
    v += __shfl_xor_sync(0xffffffffu, v, 4);
    return v;
}

__global__ __launch_bounds__(256) void scan_kernel(
    const float* __restrict__ EW, const float* __restrict__ BBp, const float* __restrict__ AAp,
    const float* __restrict__ K2p, const float* __restrict__ Rp, const float* __restrict__ Vp,
    float* __restrict__ O)
{
    __shared__ float sm[4*6*64];
    int bh = blockIdx.x >> 1;
    int rowBase = (blockIdx.x & 1) * 32;
    int tid = threadIdx.x;
    int row = rowBase + (tid >> 3);
    int col0 = (tid & 7) * 8;
    size_t base = (size_t)bh * TT * 64;

    const float* src0 = EW  + base;
    const float* src1 = BBp + base;
    const float* src2 = AAp + base;
    const float* src3 = K2p + base;
    const float* src4 = Rp  + base;
    const float* src5 = Vp  + base;

    int arr = tid >> 4, seg = tid & 15;
    const float* mysrc = (arr==0)?src0:(arr==1)?src1:(arr==2)?src2:(arr==3)?src3:(arr==4)?src4:src5;

    #pragma unroll
    for (int s=0; s<3; s++){
        if (tid < 96){
            const float* g = mysrc + (size_t)s*64 + seg*4;
            unsigned sa = (unsigned)__cvta_generic_to_shared(&sm[s*384 + arr*64 + seg*4]);
            asm volatile("cp.async.ca.shared.global [%0], [%1], 16;"::"r"(sa),"l"(g));
        }
        asm volatile("cp.async.commit_group;");
    }

    float S[8];
    #pragma unroll
    for (int i=0;i<8;i++) S[i]=0.f;

    for (int t=0; t<TT; t++){
        asm volatile("cp.async.wait_group 2;");
        __syncthreads();

        int tn = t + 3; if (tn > TT-1) tn = TT-1;
        if (tid < 96){
            const float* g = mysrc + (size_t)tn*64 + seg*4;
            unsigned sa = (unsigned)__cvta_generic_to_shared(&sm[((t+3)&3)*384 + arr*64 + seg*4]);
            asm volatile("cp.async.ca.shared.global [%0], [%1], 16;"::"r"(sa),"l"(g));
        }
        asm volatile("cp.async.commit_group;");

        const float* st = &sm[(t & 3) * 384];
        float ew[8], bb[8], aa[8], kk[8], rr[8];
        *(float4*)&ew[0] = *(const float4*)&st[  0 + col0];
        *(float4*)&ew[4] = *(const float4*)&st[  0 + col0 + 4];
        *(float4*)&bb[0] = *(const float4*)&st[ 64 + col0];
        *(float4*)&bb[4] = *(const float4*)&st[ 64 + col0 + 4];
        *(float4*)&aa[0] = *(const float4*)&st[128 + col0];
        *(float4*)&aa[4] = *(const float4*)&st[128 + col0 + 4];
        *(float4*)&kk[0] = *(const float4*)&st[192 + col0];
        *(float4*)&kk[4] = *(const float4*)&st[192 + col0 + 4];
        *(float4*)&rr[0] = *(const float4*)&st[256 + col0];
        *(float4*)&rr[4] = *(const float4*)&st[256 + col0 + 4];
        float vv = st[320 + row];

        float sab = 0.f;
        #pragma unroll
        for (int i=0;i<8;i++) sab += S[i]*aa[i];
        sab = red8(sab);

        float oo = 0.f;
        #pragma unroll
        for (int i=0;i<8;i++){
            S[i] = S[i]*ew[i] + sab*bb[i] + vv*kk[i];
            oo += S[i]*rr[i];
        }
        oo = red8(oo);
        if ((tid & 7) == 0) O[base + (size_t)t*64 + row] = oo;
    }
}

// ---------------- post: groupnorm + bonus + gate (output rounded to tf32) ----------------
__global__ __launch_bounds__(256) void post_kernel(
    const float* __restrict__ O, const float* __restrict__ Rp, const float* __restrict__ K2p,
    const float* __restrict__ Vp, const float* __restrict__ G,
    const float* __restrict__ r_k, const float* __restrict__ gn_w, const float* __restrict__ gn_b,
    float* __restrict__ Z)
{
    int gw = (blockIdx.x*256 + threadIdx.x) >> 5;
    int lane = threadIdx.x & 31;
    int h = gw & 15, t = (gw >> 4) & 1023, b = gw >> 14;
    size_t bhtd = ((size_t)((b*HH + h)*TT + t))*64 + lane*2;
    float2 o = *(const float2*)&O[bhtd];
    float sm = o.x + o.y;
    #pragma unroll
    for (int off=16; off>0; off>>=1) sm += __shfl_xor_sync(0xffffffffu, sm, off);
    float mean = sm * (1.f/64.f);
    float dx = o.x - mean, dy = o.y - mean;
    float vs = dx*dx + dy*dy;
    #pragma unroll
    for (int off=16; off>0; off>>=1) vs += __shfl_xor_sync(0xffffffffu, vs, off);
    float inv = rsqrtf(vs*(1.f/64.f) + GN_EPS);

    float2 r  = *(const float2*)&Rp[bhtd];
    float2 k2 = *(const float2*)&K2p[bhtd];
    float2 v  = *(const float2*)&Vp[bhtd];
    int c = h*64 + lane*2;
    float2 rk = *(const float2*)&r_k[c];
    float bs = r.x*k2.x*rk.x + r.y*k2.y*rk.y;
    #pragma unroll
    for (int off=16; off>0; off>>=1) bs += __shfl_xor_sync(0xffffffffu, bs, off);

    size_t btc = ((size_t)(b*TT + t))*CC + c;
    float2 g  = *(const float2*)&G[btc];
    float2 w  = *(const float2*)&gn_w[c];
    float2 bb = *(const float2*)&gn_b[c];
    float z0 = ((dx*inv)*w.x + bb.x + bs*v.x) * g.x;
    float z1 = ((dy*inv)*w.y + bb.y + bs*v.y) * g.y;
    *(float2*)&Z[btc] = make_float2(to_tf32(z0), to_tf32(z1));
}

// ---------------- driver ----------------
extern "C" void kernel_launch(void* const* d_in, const int* in_sizes, int n_in,
                              void* d_out, int out_size) {
    const float* x   = (const float*)d_in[0];
    const float* vfi = (const float*)d_in[1];
    const float* x_r = (const float*)d_in[2];
    const float* x_w = (const float*)d_in[3];
    const float* x_k = (const float*)d_in[4];
    const float* x_v = (const float*)d_in[5];
    const float* x_a = (const float*)d_in[6];
    const float* x_g = (const float*)d_in[7];
    const float* Wr  = (const float*)d_in[8];
    const float* Wk  = (const float*)d_in[9];
    const float* Wv  = (const float*)d_in[10];
    const float* Wo  = (const float*)d_in[11];
    const float* w0  = (const float*)d_in[12];
    const float* w1  = (const float*)d_in[13];
    const float* w2  = (const float*)d_in[14];
    const float* a0  = (const float*)d_in[15];
    const float* a1  = (const float*)d_in[16];
    const float* a2  = (const float*)d_in[17];
    const float* v0  = (const float*)d_in[18];
    const float* v1  = (const float*)d_in[19];
    const float* v2  = (const float*)d_in[20];
    const float* g1  = (const float*)d_in[21];
    const float* g2  = (const float*)d_in[22];
    const float* k_k = (const float*)d_in[23];
    const float* k_a = (const float*)d_in[24];
    const float* r_k = (const float*)d_in[25];
    const float* gnw = (const float*)d_in[26];
    const float* gnb = (const float*)d_in[27];
    float* out = (float*)d_out;

    float* S;
    cudaGetSymbolAddress((void**)&S, gScratch);

    const int SM128 = 2*(128+128)*32*4;   // 65536
    const int SM64  = 2*(128+64)*32*4;    // 49152
    const int SM32  = 2*(128+32)*32*4;    // 40960
    cudaFuncSetAttribute(gemm_mma<128>, cudaFuncAttributeMaxDynamicSharedMemorySize, SM128);
    cudaFuncSetAttribute(gemm_mma<64>,  cudaFuncAttributeMaxDynamicSharedMemorySize, SM64);
    cudaFuncSetAttribute(gemm_mma<32>,  cudaFuncAttributeMaxDynamicSharedMemorySize, SM32);

    const int M = BB*TT;

    // 0: round big weights to tf32
    round_weights<<<16384, 256>>>(Wr, Wk, Wv, Wo, S);
    // 1: transpose+round small weights
    transpose_round_all<<<2304, 256>>>(w1, w2, a1, a2, v1, v2, g1, g2, S);
    // 2: token-shift mixes (rounded)
    mix_kernel<<<BB*TT, 256>>>(x, x_r, x_w, x_k, x_v, x_a, x_g,
                               S+OXR, S+OXW, S+OXK, S+OXV, S+OXA, S+OXG);
    // 3: decay stage1: tanh(XW @ w1)
    gemm_mma<64><<<dim3(M/128,1), 256, SM64>>>(S+OXW, S+OW1T, S+OHW, M, 64, 1024, nullptr, 1, 1.f, 1);
    // 4: a stage1
    gemm_mma<64><<<dim3(M/128,1), 256, SM64>>>(S+OXA, S+OA1T, S+OHA, M, 64, 1024, nullptr, 0, 1.f, 1);
    // 5: R = XR @ Wr^T   <-- ncu-profiled launch (-s 5)
    gemm_mma<128><<<dim3(M/128,8), 256, SM128>>>(S+OXR, S+OWRr, S+ORB, M, 1024, 1024, nullptr, 0, 1.f, 0);
    // 6: v stage1
    gemm_mma<32><<<dim3(M/128,1), 256, SM32>>>(S+OXV, S+OV1T, S+OHV, M, 32, 1024, nullptr, 0, 1.f, 1);
    // 7: gate stage1: sigmoid(XG @ g1)
    gemm_mma<128><<<dim3(M/128,1), 256, SM128>>>(S+OXG, S+OG1T, S+OHG, M, 128, 1024, nullptr, 2, 1.f, 1);
    // 8,9: K, V projections
    gemm_mma<128><<<dim3(M/128,8), 256, SM128>>>(S+OXK, S+OWKr, S+OKB, M, 1024, 1024, nullptr, 0, 1.f, 0);
    gemm_mma<128><<<dim3(M/128,8), 256, SM128>>>(S+OXV, S+OWVr, S+OVB, M, 1024, 1024, nullptr, 0, 1.f, 0);
    // 10: WL = LOG_DECAY * sigmoid(w0 + hw @ w2)
    gemm_mma<128><<<dim3(M/128,8), 256, SM128>>>(S+OHW, S+OW2T, S+OWL, M, 1024, 64, w0, 2, LOG_DECAY, 0);
    // 11: a = sigmoid(a0 + ha @ a2)
    gemm_mma<128><<<dim3(M/128,8), 256, SM128>>>(S+OHA, S+OA2T, S+OAB, M, 1024, 64, a0, 2, 1.f, 0);
    // 12: vmix = sigmoid(v0 + hv @ v2)
    gemm_mma<128><<<dim3(M/128,8), 256, SM128>>>(S+OHV, S+OV2T, S+OVMX, M, 1024, 32, v0, 2, 1.f, 0);
    // 13: g = hg @ g2
    gemm_mma<128><<<dim3(M/128,8), 256, SM128>>>(S+OHG, S+OG2T, S+OGB, M, 1024, 128, nullptr, 0, 1.f, 0);
    // 14: scan operand prep
    prep_kernel<<<(BB*TT*HH*32)/256, 256>>>(S+OKB, S+OAB, S+OVB, S+OWL, S+OVMX, vfi, S+ORB,
                                            k_k, k_a,
                                            S+OEW, S+OBBA, S+OAAA, S+OKK2, S+ORRA, S+OVVA);
    // 15: sequential scan
    scan_kernel<<<BB*HH*2, 256>>>(S+OEW, S+OBBA, S+OAAA, S+OKK2, S+ORRA, S+OVVA, S+OOB);
    // 16: groupnorm + bonus + gate
    post_kernel<<<(BB*TT*HH*32)/256, 256>>>(S+OOB, S+ORRA, S+OKK2, S+OVVA, S+OGB,
                                            r_k, gnw, gnb, S+OZB);
    // 17: out = Z @ Wo^T
    gemm_mma<128><<<dim3(M/128,8), 256, SM128>>>(S+OZB, S+OWOr, out, M, 1024, 1024, nullptr, 0, 1.f, 0);

    // v_first passthrough
    if (out_size >= 2*NE){
        cudaMemcpyAsync(out + NE, vfi, (size_t)NE*sizeof(float), cudaMemcpyDeviceToDevice);
    }
}

// round 5
// speedup vs baseline: 1.7733x; 1.1186x over previous
#include <cuda_runtime.h>
#include <math.h>
#include <stdint.h>

#define BB 4
#define TT 1024
#define CC 1024
#define HH 16
#define DD 64
#define NE 4194304     // B*T*C
#define LOG_DECAY (-0.6065306597126334f)
#define GN_EPS 64e-5f

typedef unsigned long long u64;

// ---------------- static scratch ----------------
__device__ float gScratch[104857600];

#define OXR  ((size_t)0*NE)
#define OXK  ((size_t)2*NE)
#define OXV  ((size_t)3*NE)
#define OXC  ((size_t)4*NE)            // [x | xx] 4096 x 2048 (spans 2*NE)
#define ORB  ((size_t)6*NE)
#define OKB  ((size_t)7*NE)
#define OVB  ((size_t)8*NE)
#define OAB  ((size_t)9*NE)
#define OGB  ((size_t)10*NE)
#define OWL  ((size_t)11*NE)
#define OVMX ((size_t)12*NE)
#define OHST ((size_t)13*NE)           // stage-1 fused output H: 4096 x 320
#define OEW  ((size_t)14*NE)
#define OBBA ((size_t)15*NE)
#define OAAA ((size_t)16*NE)
#define OKK2 ((size_t)17*NE)
#define ORRA ((size_t)18*NE)
#define OVVA ((size_t)19*NE)
#define OOB  ((size_t)20*NE)
#define OZB  ((size_t)21*NE)
#define OW2T ((size_t)22*NE)
#define OA2T (OW2T + 65536)
#define OV2T (OA2T + 65536)
#define OG2T (OV2T + 32768)
#define OWRr (OG2T + 131072)
#define OWKr (OWRr + 1048576)
#define OWVr (OWKr + 1048576)
#define OWOr (OWVr + 1048576)
#define OBU  (OWOr + 1048576)          // stacked stage-1 weights: 320 x 2048

__device__ __forceinline__ float to_tf32(float x){
    uint32_t u; asm("cvt.rna.tf32.f32 %0, %1;" : "=r"(u) : "f"(x));
    return __uint_as_float(u);
}
__device__ __forceinline__ float sigm_(float x){ return 1.f/(1.f+expf(-x)); }

__device__ __forceinline__ void mma8(float* d, const uint32_t* a, const uint32_t* b){
    asm volatile("mma.sync.aligned.m16n8k8.row.col.f32.tf32.tf32.f32 "
        "{%0,%1,%2,%3}, {%4,%5,%6,%7}, {%8,%9}, {%0,%1,%2,%3};"
        : "+f"(d[0]), "+f"(d[1]), "+f"(d[2]), "+f"(d[3])
        : "r"(a[0]), "r"(a[1]), "r"(a[2]), "r"(a[3]), "r"(b[0]), "r"(b[1]));
}
__device__ __forceinline__ void ldsm4(uint32_t* r, uint32_t a){
    asm volatile("ldmatrix.sync.aligned.m8n8.x4.shared.b16 {%0,%1,%2,%3}, [%4];"
        : "=r"(r[0]),"=r"(r[1]),"=r"(r[2]),"=r"(r[3]) : "r"(a));
}
// word-index XOR swizzle within 32-float rows
__device__ __forceinline__ int swz(int r, int c){
    return r*32 + (int)((((((unsigned)c>>2) ^ ((unsigned)r & 7u)) << 2)) | ((unsigned)c & 3u));
}

// f32x2 packed math helpers
__device__ __forceinline__ u64 FMA2(u64 a, u64 b, u64 c){
    u64 d; asm("fma.rn.f32x2 %0, %1, %2, %3;" : "=l"(d) : "l"(a), "l"(b), "l"(c)); return d;
}
__device__ __forceinline__ u64 MUL2(u64 a, u64 b){
    u64 d; asm("mul.rn.f32x2 %0, %1, %2;" : "=l"(d) : "l"(a), "l"(b)); return d;
}
__device__ __forceinline__ u64 PK2(float x){
    u64 d; asm("mov.b64 %0, {%1, %1};" : "=l"(d) : "f"(x)); return d;
}
__device__ __forceinline__ float HADD2(u64 d){
    float a, b; asm("mov.b64 {%0, %1}, %2;" : "=f"(a), "=f"(b) : "l"(d)); return a + b;
}

// ---------------- tf32 GEMM (mma.sync + ldmatrix): C[M,N] = A[M,K] * B[N,K]^T ----------------
// 3-stage cp.async, single barrier per k-iter.
// mode: 0 plain(+bias), 1 tanh, 2 scale*sigmoid(x+bias), 3 per-col stage1 (tanh/plain/sigmoid)
template<int NT>
__global__ void __launch_bounds__(256) gemm_mma(
    const float* __restrict__ A, int lda, const float* __restrict__ Bm,
    float* __restrict__ C, int ldc, int M, int N, int K,
    const float* __restrict__ bias, int mode, float scale, int round_out)
{
    extern __shared__ float sm[];
    const int AS  = 128*32;
    const int STG = (128+NT)*32;
    const int NTN = (NT==128) ? 8 : 4;
    const int NLD = NTN/2;

    int tid = threadIdx.x, wid = tid >> 5, lane = tid & 31;
    int bm0 = blockIdx.x * 128, bn0 = blockIdx.y * NT;
    int grp = lane >> 2, thr = lane & 3;
    int wm = (wid & 3) * 32;
    int wn = (NT==128) ? (wid >> 2) * 64 : (wid >> 2) * 32;
    int NC = K >> 5;

    float acc[2][NTN][4];
    #pragma unroll
    for (int i=0;i<2;i++)
      #pragma unroll
      for (int j=0;j<NTN;j++)
        #pragma unroll
        for (int l=0;l<4;l++) acc[i][j][l]=0.f;

    uint32_t smb = (uint32_t)__cvta_generic_to_shared(sm);

    // precomputed ldmatrix byte offsets within one stage
    uint32_t aoff[2][4], boff[NLD][4];
    #pragma unroll
    for (int mt=0;mt<2;mt++)
      #pragma unroll
      for (int kk=0;kk<4;kk++){
        int row = wm + mt*16 + (lane & 15);
        int col = kk*8 + (lane >> 4) * 4;
        aoff[mt][kk] = 4u * (uint32_t)swz(row, col);
      }
    #pragma unroll
    for (int np=0;np<NLD;np++)
      #pragma unroll
      for (int kk=0;kk<4;kk++){
        int row = wn + np*16 + (lane & 7) + ((lane >> 4) & 1) * 8;
        int col = kk*8 + ((lane >> 3) & 1) * 4;
        boff[np][kk] = 4u * (uint32_t)(AS + swz(row, col));
      }

    auto load_stage = [&](int stg, int c){
        const float* Ag = A + (size_t)bm0 * lda + c*32;
        #pragma unroll
        for (int i=0;i<4;i++){
            int idx = tid + 256*i; int r = idx>>3, j = idx&7;
            unsigned dst = smb + 4u*(uint32_t)(stg*STG + swz(r, j*4));
            const float* src = Ag + (size_t)r*lda + j*4;
            asm volatile("cp.async.cg.shared.global [%0], [%1], 16;"::"r"(dst),"l"(src));
        }
        const float* Bg = Bm + (size_t)bn0 * K + c*32;
        #pragma unroll
        for (int i=0;i<NT/32;i++){
            int idx = tid + 256*i; int r = idx>>3, j = idx&7;
            unsigned dst = smb + 4u*(uint32_t)(stg*STG + AS + swz(r, j*4));
            const float* src = Bg + (size_t)r*K + j*4;
            asm volatile("cp.async.cg.shared.global [%0], [%1], 16;"::"r"(dst),"l"(src));
        }
    };

    load_stage(0, 0);
    asm volatile("cp.async.commit_group;");
    if (NC > 1) load_stage(1, 1);
    asm volatile("cp.async.commit_group;");

    for (int c = 0; c < NC; c++){
        asm volatile("cp.async.wait_group 1;");
        __syncthreads();
        uint32_t sb = smb + 4u*(uint32_t)((c % 3) * STG);
        #pragma unroll
        for (int kk=0; kk<4; kk++){
            uint32_t af[2][4];
            ldsm4(af[0], sb + aoff[0][kk]);
            ldsm4(af[1], sb + aoff[1][kk]);
            uint32_t bf[NLD][4];
            #pragma unroll
            for (int np=0;np<NLD;np++) ldsm4(bf[np], sb + boff[np][kk]);
            #pragma unroll
            for (int mt=0;mt<2;mt++)
                #pragma unroll
                for (int nt=0;nt<NTN;nt++)
                    mma8(acc[mt][nt], af[mt], &bf[nt>>1][(nt&1)*2]);
        }
        if (c + 2 < NC) load_stage((c+2) % 3, c+2);
        asm volatile("cp.async.commit_group;");
    }

    #pragma unroll
    for (int mt=0;mt<2;mt++){
        #pragma unroll
        for (int nt=0;nt<NTN;nt++){
            #pragma unroll
            for (int half=0; half<2; half++){
                int row = bm0 + wm + mt*16 + grp + half*8;
                int col = bn0 + wn + nt*8 + thr*2;
                float v0 = acc[mt][nt][half*2+0];
                float v1 = acc[mt][nt][half*2+1];
                if (bias){ v0 += bias[col]; v1 += bias[col+1]; }
                if (mode==1){ v0 = tanhf(v0); v1 = tanhf(v1); }
                else if (mode==2){ v0 = scale*sigm_(v0); v1 = scale*sigm_(v1); }
                else if (mode==3){
                    v0 = (col   < 64) ? tanhf(v0) : (col   < 192 ? v0 : sigm_(v0));
                    v1 = (col+1 < 64) ? tanhf(v1) : (col+1 < 192 ? v1 : sigm_(v1));
                }
                if (round_out){ v0 = to_tf32(v0); v1 = to_tf32(v1); }
                float* cp = C + (size_t)row*ldc + col;
                cp[0] = v0; cp[1] = v1;
            }
        }
    }
}

// ---------------- weight rounding (rna to tf32) ----------------
__global__ __launch_bounds__(256) void round_weights(
    const float* __restrict__ Wr, const float* __restrict__ Wk,
    const float* __restrict__ Wv, const float* __restrict__ Wo, float* __restrict__ Sg)
{
    int idx = blockIdx.x * 256 + threadIdx.x;
    int m = idx >> 20;
    int i = idx & 1048575;
    const float* src = (m == 0) ? Wr : (m == 1) ? Wk : (m == 2) ? Wv : Wo;
    float* dst = Sg + ((m == 0) ? OWRr : (m == 1) ? OWKr : (m == 2) ? OWVr : OWOr);
    dst[i] = to_tf32(src[i]);
}

// ---------------- build stacked stage-1 weights BU[320][2048] ----------------
__global__ __launch_bounds__(256) void build_U(
    const float* __restrict__ w1, const float* __restrict__ a1,
    const float* __restrict__ v1, const float* __restrict__ g1,
    const float* __restrict__ x_w, const float* __restrict__ x_a,
    const float* __restrict__ x_v, const float* __restrict__ x_g,
    float* __restrict__ BU)
{
    int idx = blockIdx.x * 256 + threadIdx.x;      // 320*2048
    int n = idx >> 11;
    int k = idx & 2047;
    int kk = k & 1023;
    float val = 0.f;
    if (n < 64){
        float w = w1[kk*64 + n];
        val = (k < 1024) ? w : x_w[kk]*w;
    } else if (n < 128){
        float w = a1[kk*64 + (n-64)];
        val = (k < 1024) ? w : x_a[kk]*w;
    } else if (n < 160){
        float w = v1[kk*32 + (n-128)];
        val = (k < 1024) ? w : x_v[kk]*w;
    } else if (n >= 192){
        float w = g1[kk*128 + (n-192)];
        val = (k < 1024) ? w : x_g[kk]*w;
    }
    BU[idx] = to_tf32(val);
}

// ---------------- transpose+round stage-2 weights ----------------
__device__ __forceinline__ void do_tr(const float* src, float* dst, int rows, int cols, int li){
    int r = li / cols, c = li - r * cols;
    dst[(size_t)c * rows + r] = to_tf32(src[li]);
}
__global__ __launch_bounds__(256) void transpose2(
    const float* __restrict__ w2, const float* __restrict__ a2,
    const float* __restrict__ v2, const float* __restrict__ g2, float* __restrict__ Sg)
{
    int idx = blockIdx.x * 256 + threadIdx.x;   // 294912 total
    if      (idx < 65536 )  do_tr(w2, Sg+OW2T, 64, 1024,  idx);
    else if (idx < 131072)  do_tr(a2, Sg+OA2T, 64, 1024,  idx-65536);
    else if (idx < 163840)  do_tr(v2, Sg+OV2T, 32, 1024,  idx-131072);
    else                    do_tr(g2, Sg+OG2T, 128, 1024, idx-163840);
}

// ---------------- token-shift mix: XR/XK/XV + [x|xx] (all tf32-rounded) ----------------
__global__ __launch_bounds__(256) void mix_kernel(
    const float* __restrict__ x,
    const float* __restrict__ mr, const float* __restrict__ mk, const float* __restrict__ mv,
    float* __restrict__ XR, float* __restrict__ XK, float* __restrict__ XV,
    float* __restrict__ XC)
{
    int row = blockIdx.x;
    int t = row & (TT-1);
    int c4 = threadIdx.x;
    const float4* xv4 = (const float4*)x;
    float4 xc = xv4[(size_t)row*256 + c4];
    float4 xp = make_float4(0.f,0.f,0.f,0.f);
    if (t > 0) xp = xv4[(size_t)(row-1)*256 + c4];
    float4 dx = make_float4(xp.x-xc.x, xp.y-xc.y, xp.z-xc.z, xp.w-xc.w);
    size_t o = (size_t)row*256 + c4;
    float4 m;
    #define MIXOUT(dst, mp) \
        m = ((const float4*)mp)[c4]; \
        ((float4*)dst)[o] = make_float4(to_tf32(xc.x+dx.x*m.x), to_tf32(xc.y+dx.y*m.y), \
                                        to_tf32(xc.z+dx.z*m.z), to_tf32(xc.w+dx.w*m.w));
    MIXOUT(XR, mr) MIXOUT(XK, mk) MIXOUT(XV, mv)
    #undef MIXOUT
    float4* xcp = (float4*)(XC + (size_t)row*2048);
    xcp[c4]       = make_float4(to_tf32(xc.x), to_tf32(xc.y), to_tf32(xc.z), to_tf32(xc.w));
    xcp[256 + c4] = make_float4(to_tf32(dx.x), to_tf32(dx.y), to_tf32(dx.z), to_tf32(dx.w));
}

// ---------------- scan-operand prep ----------------
__global__ __launch_bounds__(256) void prep_kernel(
    const float* __restrict__ K, const float* __restrict__ A, const float* __restrict__ V,
    const float* __restrict__ WL, const float* __restrict__ VMIX, const float* __restrict__ vfirst,
    const float* __restrict__ R,
    const float* __restrict__ k_k, const float* __restrict__ k_a,
    float* __restrict__ EW, float* __restrict__ BBo, float* __restrict__ AAo,
    float* __restrict__ K2o, float* __restrict__ Ro, float* __restrict__ Vo)
{
    int gw = (blockIdx.x*256 + threadIdx.x) >> 5;
    int lane = threadIdx.x & 31;
    int h = gw & 15, t = (gw >> 4) & 1023, b = gw >> 14;
    int c = h*64 + lane*2;
    size_t btc = ((size_t)(b*TT + t))*CC + c;
    float2 k  = *(const float2*)&K[btc];
    float2 kw = *(const float2*)&k_k[c];
    float2 ka = *(const float2*)&k_a[c];
    float2 a  = *(const float2*)&A[btc];
    float kk0 = k.x*kw.x, kk1 = k.y*kw.y;
    float ss = kk0*kk0 + kk1*kk1;
    #pragma unroll
    for (int off=16; off>0; off>>=1) ss += __shfl_xor_sync(0xffffffffu, ss, off);
    float inv = 1.f / fmaxf(sqrtf(ss), 1e-12f);
    kk0 *= inv; kk1 *= inv;
    float2 wl = *(const float2*)&WL[btc];
    float2 v  = *(const float2*)&V[btc];
    float2 vf = *(const float2*)&vfirst[btc];
    float2 vm = *(const float2*)&VMIX[btc];
    v.x = v.x + (vf.x - v.x)*vm.x;
    v.y = v.y + (vf.y - v.y)*vm.y;
    float2 r = *(const float2*)&R[btc];
    float k20 = k.x*(1.f + (a.x-1.f)*ka.x);
    float k21 = k.y*(1.f + (a.y-1.f)*ka.y);
    size_t bhtd = ((size_t)((b*HH + h)*TT + t))*64 + lane*2;
    *(float2*)&EW[bhtd]  = make_float2(expf(wl.x), expf(wl.y));
    *(float2*)&BBo[bhtd] = make_float2(kk0*a.x, kk1*a.y);
    *(float2*)&AAo[bhtd] = make_float2(-kk0, -kk1);
    *(float2*)&K2o[bhtd] = make_float2(k20, k21);
    *(float2*)&Ro[bhtd]  = r;
    *(float2*)&Vo[bhtd]  = v;
}

// ---------------- sequential RWKV7 scan (f32x2 packed) ----------------
__device__ __forceinline__ float red8(float v){
    v += __shfl_xor_sync(0xffffffffu, v, 1);
    v += __shfl_xor_sync(0xffffffffu, v, 2);
    v += __shfl_xor_sync(0xffffffffu, v, 4);
    return v;
}

__global__ __launch_bounds__(256) void scan_kernel(
    const float* __restrict__ EW, const float* __restrict__ BBp, const float* __restrict__ AAp,
    const float* __restrict__ K2p, const float* __restrict__ Rp, const float* __restrict__ Vp,
    float* __restrict__ O)
{
    __shared__ float sm[4*6*64];
    int bh = blockIdx.x >> 1;
    int rowBase = (blockIdx.x & 1) * 32;
    int tid = threadIdx.x;
    int row = rowBase + (tid >> 3);
    int col0 = (tid & 7) * 8;
    size_t base = (size_t)bh * TT * 64;

    const float* src0 = EW  + base;
    const float* src1 = BBp + base;
    const float* src2 = AAp + base;
    const float* src3 = K2p + base;
    const float* src4 = Rp  + base;
    const float* src5 = Vp  + base;

    int arr = tid >> 4, seg = tid & 15;
    const float* mysrc = (arr==0)?src0:(arr==1)?src1:(arr==2)?src2:(arr==3)?src3:(arr==4)?src4:src5;

    #pragma unroll
    for (int s=0; s<3; s++){
        if (tid < 96){
            const float* g = mysrc + (size_t)s*64 + seg*4;
            unsigned sa = (unsigned)__cvta_generic_to_shared(&sm[s*384 + arr*64 + seg*4]);
            asm volatile("cp.async.ca.shared.global [%0], [%1], 16;"::"r"(sa),"l"(g));
        }
        asm volatile("cp.async.commit_group;");
    }

    u64 S2[4];
    #pragma unroll
    for (int i=0;i<4;i++) S2[i] = 0ull;

    for (int t=0; t<TT; t++){
        asm volatile("cp.async.wait_group 2;");
        __syncthreads();

        int tn = t + 3; if (tn > TT-1) tn = TT-1;
        if (tid < 96){
            const float* g = mysrc + (size_t)tn*64 + seg*4;
            unsigned sa = (unsigned)__cvta_generic_to_shared(&sm[((t+3)&3)*384 + arr*64 + seg*4]);
            asm volatile("cp.async.ca.shared.global [%0], [%1], 16;"::"r"(sa),"l"(g));
        }
        asm volatile("cp.async.commit_group;");

        const float* st = &sm[(t & 3) * 384];
        u64 ew2[4], bb2[4], aa2[4], kk2[4], rr2[4];
        #define LD2(dst, off) { \
            ulonglong2 q0 = *(const ulonglong2*)&st[(off)+col0]; \
            ulonglong2 q1 = *(const ulonglong2*)&st[(off)+col0+4]; \
            dst[0]=q0.x; dst[1]=q0.y; dst[2]=q1.x; dst[3]=q1.y; }
        LD2(ew2,   0) LD2(bb2,  64) LD2(aa2, 128) LD2(kk2, 192) LD2(rr2, 256)
        #undef LD2
        float vv = st[320 + row];

        u64 acc = 0ull;
        #pragma unroll
        for (int i=0;i<4;i++) acc = FMA2(S2[i], aa2[i], acc);
        float sab = red8(HADD2(acc));

        u64 sab2 = PK2(sab), vv2 = PK2(vv);
        u64 oacc = 0ull;
        #pragma unroll
        for (int i=0;i<4;i++){
            S2[i] = FMA2(kk2[i], vv2, FMA2(bb2[i], sab2, MUL2(S2[i], ew2[i])));
            oacc = FMA2(S2[i], rr2[i], oacc);
        }
        float oo = red8(HADD2(oacc));
        if ((tid & 7) == 0) O[base + (size_t)t*64 + row] = oo;
    }
}

// ---------------- post: groupnorm + bonus + gate (output rounded to tf32) ----------------
__global__ __launch_bounds__(256) void post_kernel(
    const float* __restrict__ O, const float* __restrict__ Rp, const float* __restrict__ K2p,
    const float* __restrict__ Vp, const float* __restrict__ G,
    const float* __restrict__ r_k, const float* __restrict__ gn_w, const float* __restrict__ gn_b,
    float* __restrict__ Z)
{
    int gw = (blockIdx.x*256 + threadIdx.x) >> 5;
    int lane = threadIdx.x & 31;
    int h = gw & 15, t = (gw >> 4) & 1023, b = gw >> 14;
    size_t bhtd = ((size_t)((b*HH + h)*TT + t))*64 + lane*2;
    float2 o = *(const float2*)&O[bhtd];
    float sm = o.x + o.y;
    #pragma unroll
    for (int off=16; off>0; off>>=1) sm += __shfl_xor_sync(0xffffffffu, sm, off);
    float mean = sm * (1.f/64.f);
    float dx = o.x - mean, dy = o.y - mean;
    float vs = dx*dx + dy*dy;
    #pragma unroll
    for (int off=16; off>0; off>>=1) vs += __shfl_xor_sync(0xffffffffu, vs, off);
    float inv = rsqrtf(vs*(1.f/64.f) + GN_EPS);

    float2 r  = *(const float2*)&Rp[bhtd];
    float2 k2 = *(const float2*)&K2p[bhtd];
    float2 v  = *(const float2*)&Vp[bhtd];
    int c = h*64 + lane*2;
    float2 rk = *(const float2*)&r_k[c];
    float bs = r.x*k2.x*rk.x + r.y*k2.y*rk.y;
    #pragma unroll
    for (int off=16; off>0; off>>=1) bs += __shfl_xor_sync(0xffffffffu, bs, off);

    size_t btc = ((size_t)(b*TT + t))*CC + c;
    float2 g  = *(const float2*)&G[btc];
    float2 w  = *(const float2*)&gn_w[c];
    float2 bb = *(const float2*)&gn_b[c];
    float z0 = ((dx*inv)*w.x + bb.x + bs*v.x) * g.x;
    float z1 = ((dy*inv)*w.y + bb.y + bs*v.y) * g.y;
    *(float2*)&Z[btc] = make_float2(to_tf32(z0), to_tf32(z1));
}

// ---------------- driver ----------------
extern "C" void kernel_launch(void* const* d_in, const int* in_sizes, int n_in,
                              void* d_out, int out_size) {
    const float* x   = (const float*)d_in[0];
    const float* vfi = (const float*)d_in[1];
    const float* x_r = (const float*)d_in[2];
    const float* x_w = (const float*)d_in[3];
    const float* x_k = (const float*)d_in[4];
    const float* x_v = (const float*)d_in[5];
    const float* x_a = (const float*)d_in[6];
    const float* x_g = (const float*)d_in[7];
    const float* Wr  = (const float*)d_in[8];
    const float* Wk  = (const float*)d_in[9];
    const float* Wv  = (const float*)d_in[10];
    const float* Wo  = (const float*)d_in[11];
    const float* w0  = (const float*)d_in[12];
    const float* w1  = (const float*)d_in[13];
    const float* w2  = (const float*)d_in[14];
    const float* a0  = (const float*)d_in[15];
    const float* a1  = (const float*)d_in[16];
    const float* a2  = (const float*)d_in[17];
    const float* v0  = (const float*)d_in[18];
    const float* v1  = (const float*)d_in[19];
    const float* v2  = (const float*)d_in[20];
    const float* g1  = (const float*)d_in[21];
    const float* g2  = (const float*)d_in[22];
    const float* k_k = (const float*)d_in[23];
    const float* k_a = (const float*)d_in[24];
    const float* r_k = (const float*)d_in[25];
    const float* gnw = (const float*)d_in[26];
    const float* gnb = (const float*)d_in[27];
    float* out = (float*)d_out;

    float* S;
    cudaGetSymbolAddress((void**)&S, gScratch);

    const int SM128 = 3*(128+128)*32*4;   // 98304
    const int SM64  = 3*(128+64)*32*4;    // 73728
    cudaFuncSetAttribute(gemm_mma<128>, cudaFuncAttributeMaxDynamicSharedMemorySize, SM128);
    cudaFuncSetAttribute(gemm_mma<64>,  cudaFuncAttributeMaxDynamicSharedMemorySize, SM64);

    const int M = BB*TT;
    float* H = S + OHST;   // 4096 x 320

    // 0: round big weights to tf32
    round_weights<<<16384, 256>>>(Wr, Wk, Wv, Wo, S);
    // 1: stacked stage-1 weights BU (320 x 2048)
    build_U<<<2560, 256>>>(w1, a1, v1, g1, x_w, x_a, x_v, x_g, S+OBU);
    // 2: stage-2 weight transposes
    transpose2<<<1152, 256>>>(w2, a2, v2, g2, S);
    // 3: token-shift mixes + [x|xx]
    mix_kernel<<<BB*TT, 256>>>(x, x_r, x_k, x_v, S+OXR, S+OXK, S+OXV, S+OXC);
    // 4: fused stage-1: H = [x|xx] @ BU^T  (per-col tanh/plain/sigmoid)
    gemm_mma<64><<<dim3(M/128,5), 256, SM64>>>(S+OXC, 2048, S+OBU, H, 320, M, 320, 2048,
                                               nullptr, 3, 1.f, 1);
    // 5: R = XR @ Wr^T   <-- ncu-profiled launch (-s 5)
    gemm_mma<128><<<dim3(M/128,8), 256, SM128>>>(S+OXR, 1024, S+OWRr, S+ORB, 1024, M, 1024, 1024,
                                                 nullptr, 0, 1.f, 0);
    // 6: WL = LOG_DECAY * sigmoid(w0 + Hw @ w2)
    gemm_mma<128><<<dim3(M/128,8), 256, SM128>>>(H+0, 320, S+OW2T, S+OWL, 1024, M, 1024, 64,
                                                 w0, 2, LOG_DECAY, 0);
    // 7: a = sigmoid(a0 + Ha @ a2)
    gemm_mma<128><<<dim3(M/128,8), 256, SM128>>>(H+64, 320, S+OA2T, S+OAB, 1024, M, 1024, 64,
                                                 a0, 2, 1.f, 0);
    // 8: vmix = sigmoid(v0 + Hv @ v2)
    gemm_mma<128><<<dim3(M/128,8), 256, SM128>>>(H+128, 320, S+OV2T, S+OVMX, 1024, M, 1024, 32,
                                                 v0, 2, 1.f, 0);
    // 9: g = Hg @ g2
    gemm_mma<128><<<dim3(M/128,8), 256, SM128>>>(H+192, 320, S+OG2T, S+OGB, 1024, M, 1024, 128,
                                                 nullptr, 0, 1.f, 0);
    // 10,11: K, V projections
    gemm_mma<128><<<dim3(M/128,8), 256, SM128>>>(S+OXK, 1024, S+OWKr, S+OKB, 1024, M, 1024, 1024,
                                                 nullptr, 0, 1.f, 0);
    gemm_mma<128><<<dim3(M/128,8), 256, SM128>>>(S+OXV, 1024, S+OWVr, S+OVB, 1024, M, 1024, 1024,
                                                 nullptr, 0, 1.f, 0);
    // 12: scan operand prep
    prep_kernel<<<(BB*TT*HH*32)/256, 256>>>(S+OKB, S+OAB, S+OVB, S+OWL, S+OVMX, vfi, S+ORB,
                                            k_k, k_a,
                                            S+OEW, S+OBBA, S+OAAA, S+OKK2, S+ORRA, S+OVVA);
    // 13: sequential scan
    scan_kernel<<<BB*HH*2, 256>>>(S+OEW, S+OBBA, S+OAAA, S+OKK2, S+ORRA, S+OVVA, S+OOB);
    // 14: groupnorm + bonus + gate
    post_kernel<<<(BB*TT*HH*32)/256, 256>>>(S+OOB, S+ORRA, S+OKK2, S+OVVA, S+OGB,
                                            r_k, gnw, gnb, S+OZB);
    // 15: out = Z @ Wo^T
    gemm_mma<128><<<dim3(M/128,8), 256, SM128>>>(S+OZB, 1024, S+OWOr, out, 1024, M, 1024, 1024,
                                                 nullptr, 0, 1.f, 0);

    // v_first passthrough
    if (out_size >= 2*NE){
        cudaMemcpyAsync(out + NE, vfi, (size_t)NE*sizeof(float), cudaMemcpyDeviceToDevice);
    }
}

// round 6
// speedup vs baseline: 1.9035x; 1.0734x over previous
#include <cuda_runtime.h>
#include <math.h>
#include <stdint.h>

#define BB 4
#define TT 1024
#define CC 1024
#define HH 16
#define DD 64
#define NE 4194304     // B*T*C
#define LOG_DECAY (-0.6065306597126334f)
#define GN_EPS 64e-5f

typedef unsigned long long u64;

// ---------------- static scratch ----------------
__device__ float gScratch[104857600];

#define OXR  ((size_t)0*NE)
#define OXK  ((size_t)2*NE)
#define OXV  ((size_t)3*NE)
#define OXC  ((size_t)4*NE)            // [x | xx] 4096 x 2048 (spans 2*NE)
#define ORB  ((size_t)6*NE)
#define OKB  ((size_t)7*NE)
#define OVB  ((size_t)8*NE)
#define OAB  ((size_t)9*NE)
#define OGB  ((size_t)10*NE)
#define OWL  ((size_t)11*NE)
#define OVMX ((size_t)12*NE)
#define OHST ((size_t)13*NE)           // stage-1 fused output H: 4096 x 320
#define OEW  ((size_t)14*NE)
#define OBBA ((size_t)15*NE)
#define OAAA ((size_t)16*NE)
#define OKK2 ((size_t)17*NE)
#define ORRA ((size_t)18*NE)
#define OVVA ((size_t)19*NE)
#define OOB  ((size_t)20*NE)
#define OZB  ((size_t)21*NE)
#define OW2T ((size_t)22*NE)
#define OA2T (OW2T + 65536)
#define OV2T (OA2T + 65536)
#define OG2T (OV2T + 32768)
#define OWRr (OG2T + 131072)
#define OWKr (OWRr + 1048576)
#define OWVr (OWKr + 1048576)
#define OWOr (OWVr + 1048576)
#define OBU  (OWOr + 1048576)          // stacked stage-1 weights: 320 x 2048

__device__ __forceinline__ float to_tf32(float x){
    uint32_t u; asm("cvt.rna.tf32.f32 %0, %1;" : "=r"(u) : "f"(x));
    return __uint_as_float(u);
}
__device__ __forceinline__ float sigm_(float x){ return 1.f/(1.f+expf(-x)); }

__device__ __forceinline__ void mma8(float* d, const uint32_t* a, const uint32_t* b){
    asm volatile("mma.sync.aligned.m16n8k8.row.col.f32.tf32.tf32.f32 "
        "{%0,%1,%2,%3}, {%4,%5,%6,%7}, {%8,%9}, {%0,%1,%2,%3};"
        : "+f"(d[0]), "+f"(d[1]), "+f"(d[2]), "+f"(d[3])
        : "r"(a[0]), "r"(a[1]), "r"(a[2]), "r"(a[3]), "r"(b[0]), "r"(b[1]));
}
__device__ __forceinline__ void ldsm4(uint32_t* r, uint32_t a){
    asm volatile("ldmatrix.sync.aligned.m8n8.x4.shared.b16 {%0,%1,%2,%3}, [%4];"
        : "=r"(r[0]),"=r"(r[1]),"=r"(r[2]),"=r"(r[3]) : "r"(a));
}
__device__ __forceinline__ int swz(int r, int c){
    return r*32 + (int)((((((unsigned)c>>2) ^ ((unsigned)r & 7u)) << 2)) | ((unsigned)c & 3u));
}

// f32x2 packed math helpers
__device__ __forceinline__ u64 FMA2(u64 a, u64 b, u64 c){
    u64 d; asm("fma.rn.f32x2 %0, %1, %2, %3;" : "=l"(d) : "l"(a), "l"(b), "l"(c)); return d;
}
__device__ __forceinline__ u64 MUL2(u64 a, u64 b){
    u64 d; asm("mul.rn.f32x2 %0, %1, %2;" : "=l"(d) : "l"(a), "l"(b)); return d;
}
__device__ __forceinline__ u64 ADD2(u64 a, u64 b){
    u64 d; asm("add.rn.f32x2 %0, %1, %2;" : "=l"(d) : "l"(a), "l"(b)); return d;
}
__device__ __forceinline__ u64 PK2(float x){
    u64 d; asm("mov.b64 %0, {%1, %1};" : "=l"(d) : "f"(x)); return d;
}
__device__ __forceinline__ float HADD2(u64 d){
    float a, b; asm("mov.b64 {%0, %1}, %2;" : "=f"(a), "=f"(b) : "l"(d)); return a + b;
}

// ---------------- job descriptor for batched GEMM ----------------
struct GJob {
    const float* A; const float* B; float* C; const float* bias;
    int lda, ldc, N, K, mode; float scale; int round_out;
};

// ---------------- tf32 GEMM (mma.sync + ldmatrix): C = A * B^T, z-batched ----------------
// mode: 0 plain(+bias), 1 tanh, 2 scale*sigmoid(x+bias), 3 per-col stage1
template<int NT>
__global__ void __launch_bounds__(256) gemm_mma(GJob j0, GJob j1, GJob j2, GJob j3)
{
    extern __shared__ float sm[];
    const int AS  = 128*32;
    const int STG = (128+NT)*32;
    const int NTN = (NT==128) ? 8 : 4;
    const int NLD = NTN/2;

    GJob jb = j0;
    if (blockIdx.z == 1) jb = j1;
    else if (blockIdx.z == 2) jb = j2;
    else if (blockIdx.z == 3) jb = j3;

    int tid = threadIdx.x, wid = tid >> 5, lane = tid & 31;
    int bm0 = blockIdx.x * 128, bn0 = blockIdx.y * NT;
    int grp = lane >> 2, thr = lane & 3;
    int wm = (wid & 3) * 32;
    int wn = (NT==128) ? (wid >> 2) * 64 : (wid >> 2) * 32;
    int NC = jb.K >> 5;

    float acc[2][NTN][4];
    #pragma unroll
    for (int i=0;i<2;i++)
      #pragma unroll
      for (int j=0;j<NTN;j++)
        #pragma unroll
        for (int l=0;l<4;l++) acc[i][j][l]=0.f;

    uint32_t smb = (uint32_t)__cvta_generic_to_shared(sm);

    uint32_t aoff[2][4], boff[NLD][4];
    #pragma unroll
    for (int mt=0;mt<2;mt++)
      #pragma unroll
      for (int kk=0;kk<4;kk++){
        int row = wm + mt*16 + (lane & 15);
        int col = kk*8 + (lane >> 4) * 4;
        aoff[mt][kk] = 4u * (uint32_t)swz(row, col);
      }
    #pragma unroll
    for (int np=0;np<NLD;np++)
      #pragma unroll
      for (int kk=0;kk<4;kk++){
        int row = wn + np*16 + (lane & 7) + ((lane >> 4) & 1) * 8;
        int col = kk*8 + ((lane >> 3) & 1) * 4;
        boff[np][kk] = 4u * (uint32_t)(AS + swz(row, col));
      }

    auto load_stage = [&](int stg, int c){
        const float* Ag = jb.A + (size_t)bm0 * jb.lda + c*32;
        #pragma unroll
        for (int i=0;i<4;i++){
            int idx = tid + 256*i; int r = idx>>3, j = idx&7;
            unsigned dst = smb + 4u*(uint32_t)(stg*STG + swz(r, j*4));
            const float* src = Ag + (size_t)r*jb.lda + j*4;
            asm volatile("cp.async.cg.shared.global [%0], [%1], 16;"::"r"(dst),"l"(src));
        }
        const float* Bg = jb.B + (size_t)bn0 * jb.K + c*32;
        #pragma unroll
        for (int i=0;i<NT/32;i++){
            int idx = tid + 256*i; int r = idx>>3, j = idx&7;
            unsigned dst = smb + 4u*(uint32_t)(stg*STG + AS + swz(r, j*4));
            const float* src = Bg + (size_t)r*jb.K + j*4;
            asm volatile("cp.async.cg.shared.global [%0], [%1], 16;"::"r"(dst),"l"(src));
        }
    };

    load_stage(0, 0);
    asm volatile("cp.async.commit_group;");
    if (NC > 1) load_stage(1, 1);
    asm volatile("cp.async.commit_group;");

    for (int c = 0; c < NC; c++){
        asm volatile("cp.async.wait_group 1;");
        __syncthreads();
        uint32_t sb = smb + 4u*(uint32_t)((c % 3) * STG);
        #pragma unroll
        for (int kk=0; kk<4; kk++){
            uint32_t af[2][4];
            ldsm4(af[0], sb + aoff[0][kk]);
            ldsm4(af[1], sb + aoff[1][kk]);
            uint32_t bf[NLD][4];
            #pragma unroll
            for (int np=0;np<NLD;np++) ldsm4(bf[np], sb + boff[np][kk]);
            #pragma unroll
            for (int mt=0;mt<2;mt++)
                #pragma unroll
                for (int nt=0;nt<NTN;nt++)
                    mma8(acc[mt][nt], af[mt], &bf[nt>>1][(nt&1)*2]);
        }
        if (c + 2 < NC) load_stage((c+2) % 3, c+2);
        asm volatile("cp.async.commit_group;");
    }

    #pragma unroll
    for (int mt=0;mt<2;mt++){
        #pragma unroll
        for (int nt=0;nt<NTN;nt++){
            #pragma unroll
            for (int half=0; half<2; half++){
                int row = bm0 + wm + mt*16 + grp + half*8;
                int col = bn0 + wn + nt*8 + thr*2;
                float v0 = acc[mt][nt][half*2+0];
                float v1 = acc[mt][nt][half*2+1];
                if (jb.bias){ v0 += jb.bias[col]; v1 += jb.bias[col+1]; }
                if (jb.mode==1){ v0 = tanhf(v0); v1 = tanhf(v1); }
                else if (jb.mode==2){ v0 = jb.scale*sigm_(v0); v1 = jb.scale*sigm_(v1); }
                else if (jb.mode==3){
                    v0 = (col   < 64) ? tanhf(v0) : (col   < 192 ? v0 : sigm_(v0));
                    v1 = (col+1 < 64) ? tanhf(v1) : (col+1 < 192 ? v1 : sigm_(v1));
                }
                if (jb.round_out){ v0 = to_tf32(v0); v1 = to_tf32(v1); }
                float* cp = jb.C + (size_t)row*jb.ldc + col;
                cp[0] = v0; cp[1] = v1;
            }
        }
    }
}

// ---------------- weight rounding (rna to tf32) ----------------
__global__ __launch_bounds__(256) void round_weights(
    const float* __restrict__ Wr, const float* __restrict__ Wk,
    const float* __restrict__ Wv, const float* __restrict__ Wo, float* __restrict__ Sg)
{
    int idx = blockIdx.x * 256 + threadIdx.x;
    int m = idx >> 20;
    int i = idx & 1048575;
    const float* src = (m == 0) ? Wr : (m == 1) ? Wk : (m == 2) ? Wv : Wo;
    float* dst = Sg + ((m == 0) ? OWRr : (m == 1) ? OWKr : (m == 2) ? OWVr : OWOr);
    dst[i] = to_tf32(src[i]);
}

// ---------------- build BU + transpose stage-2 weights (fused) ----------------
__device__ __forceinline__ void do_tr(const float* src, float* dst, int rows, int cols, int li){
    int r = li / cols, c = li - r * cols;
    dst[(size_t)c * rows + r] = to_tf32(src[li]);
}
__global__ __launch_bounds__(256) void build_weights2(
    const float* __restrict__ w1, const float* __restrict__ a1,
    const float* __restrict__ v1, const float* __restrict__ g1,
    const float* __restrict__ w2, const float* __restrict__ a2,
    const float* __restrict__ v2, const float* __restrict__ g2,
    const float* __restrict__ x_w, const float* __restrict__ x_a,
    const float* __restrict__ x_v, const float* __restrict__ x_g,
    float* __restrict__ Sg)
{
    int idx = blockIdx.x * 256 + threadIdx.x;
    if (idx < 655360){
        // BU[320][2048]
        int n = idx >> 11;
        int k = idx & 2047;
        int kk = k & 1023;
        float val = 0.f;
        if (n < 64){
            float w = w1[kk*64 + n];
            val = (k < 1024) ? w : x_w[kk]*w;
        } else if (n < 128){
            float w = a1[kk*64 + (n-64)];
            val = (k < 1024) ? w : x_a[kk]*w;
        } else if (n < 160){
            float w = v1[kk*32 + (n-128)];
            val = (k < 1024) ? w : x_v[kk]*w;
        } else if (n >= 192){
            float w = g1[kk*128 + (n-192)];
            val = (k < 1024) ? w : x_g[kk]*w;
        }
        Sg[OBU + idx] = to_tf32(val);
    } else {
        int j = idx - 655360;   // 0 .. 294911
        if      (j < 65536 )  do_tr(w2, Sg+OW2T, 64, 1024,  j);
        else if (j < 131072)  do_tr(a2, Sg+OA2T, 64, 1024,  j-65536);
        else if (j < 163840)  do_tr(v2, Sg+OV2T, 32, 1024,  j-131072);
        else                  do_tr(g2, Sg+OG2T, 128, 1024, j-163840);
    }
}

// ---------------- token-shift mix: XR/XK/XV + [x|xx] (all tf32-rounded) ----------------
__global__ __launch_bounds__(256) void mix_kernel(
    const float* __restrict__ x,
    const float* __restrict__ mr, const float* __restrict__ mk, const float* __restrict__ mv,
    float* __restrict__ XR, float* __restrict__ XK, float* __restrict__ XV,
    float* __restrict__ XC)
{
    int row = blockIdx.x;
    int t = row & (TT-1);
    int c4 = threadIdx.x;
    const float4* xv4 = (const float4*)x;
    float4 xc = xv4[(size_t)row*256 + c4];
    float4 xp = make_float4(0.f,0.f,0.f,0.f);
    if (t > 0) xp = xv4[(size_t)(row-1)*256 + c4];
    float4 dx = make_float4(xp.x-xc.x, xp.y-xc.y, xp.z-xc.z, xp.w-xc.w);
    size_t o = (size_t)row*256 + c4;
    float4 m;
    #define MIXOUT(dst, mp) \
        m = ((const float4*)mp)[c4]; \
        ((float4*)dst)[o] = make_float4(to_tf32(xc.x+dx.x*m.x), to_tf32(xc.y+dx.y*m.y), \
                                        to_tf32(xc.z+dx.z*m.z), to_tf32(xc.w+dx.w*m.w));
    MIXOUT(XR, mr) MIXOUT(XK, mk) MIXOUT(XV, mv)
    #undef MIXOUT
    float4* xcp = (float4*)(XC + (size_t)row*2048);
    xcp[c4]       = make_float4(to_tf32(xc.x), to_tf32(xc.y), to_tf32(xc.z), to_tf32(xc.w));
    xcp[256 + c4] = make_float4(to_tf32(dx.x), to_tf32(dx.y), to_tf32(dx.z), to_tf32(dx.w));
}

// ---------------- scan-operand prep ----------------
__global__ __launch_bounds__(256) void prep_kernel(
    const float* __restrict__ K, const float* __restrict__ A, const float* __restrict__ V,
    const float* __restrict__ WL, const float* __restrict__ VMIX, const float* __restrict__ vfirst,
    const float* __restrict__ R,
    const float* __restrict__ k_k, const float* __restrict__ k_a,
    float* __restrict__ EW, float* __restrict__ BBo, float* __restrict__ AAo,
    float* __restrict__ K2o, float* __restrict__ Ro, float* __restrict__ Vo)
{
    int gw = (blockIdx.x*256 + threadIdx.x) >> 5;
    int lane = threadIdx.x & 31;
    int h = gw & 15, t = (gw >> 4) & 1023, b = gw >> 14;
    int c = h*64 + lane*2;
    size_t btc = ((size_t)(b*TT + t))*CC + c;
    float2 k  = *(const float2*)&K[btc];
    float2 kw = *(const float2*)&k_k[c];
    float2 ka = *(const float2*)&k_a[c];
    float2 a  = *(const float2*)&A[btc];
    float kk0 = k.x*kw.x, kk1 = k.y*kw.y;
    float ss = kk0*kk0 + kk1*kk1;
    #pragma unroll
    for (int off=16; off>0; off>>=1) ss += __shfl_xor_sync(0xffffffffu, ss, off);
    float inv = 1.f / fmaxf(sqrtf(ss), 1e-12f);
    kk0 *= inv; kk1 *= inv;
    float2 wl = *(const float2*)&WL[btc];
    float2 v  = *(const float2*)&V[btc];
    float2 vf = *(const float2*)&vfirst[btc];
    float2 vm = *(const float2*)&VMIX[btc];
    v.x = v.x + (vf.x - v.x)*vm.x;
    v.y = v.y + (vf.y - v.y)*vm.y;
    float2 r = *(const float2*)&R[btc];
    float k20 = k.x*(1.f + (a.x-1.f)*ka.x);
    float k21 = k.y*(1.f + (a.y-1.f)*ka.y);
    size_t bhtd = ((size_t)((b*HH + h)*TT + t))*64 + lane*2;
    *(float2*)&EW[bhtd]  = make_float2(expf(wl.x), expf(wl.y));
    *(float2*)&BBo[bhtd] = make_float2(kk0*a.x, kk1*a.y);
    *(float2*)&AAo[bhtd] = make_float2(-kk0, -kk1);
    *(float2*)&K2o[bhtd] = make_float2(k20, k21);
    *(float2*)&Ro[bhtd]  = r;
    *(float2*)&Vo[bhtd]  = v;
}

// ---------------- sequential RWKV7 scan (f32x2, 2 steps/iter, 8-stage ring) ----------------
__device__ __forceinline__ float red8(float v){
    v += __shfl_xor_sync(0xffffffffu, v, 1);
    v += __shfl_xor_sync(0xffffffffu, v, 2);
    v += __shfl_xor_sync(0xffffffffu, v, 4);
    return v;
}

__global__ __launch_bounds__(256) void scan_kernel(
    const float* __restrict__ EW, const float* __restrict__ BBp, const float* __restrict__ AAp,
    const float* __restrict__ K2p, const float* __restrict__ Rp, const float* __restrict__ Vp,
    float* __restrict__ O)
{
    __shared__ float sm[8*6*64];   // 8 stages x 6 arrays x 64
    int bh = blockIdx.x >> 1;
    int rowBase = (blockIdx.x & 1) * 32;
    int tid = threadIdx.x;
    int row = rowBase + (tid >> 3);
    int col0 = (tid & 7) * 8;
    size_t base = (size_t)bh * TT * 64;

    const float* src0 = EW  + base;
    const float* src1 = BBp + base;
    const float* src2 = AAp + base;
    const float* src3 = K2p + base;
    const float* src4 = Rp  + base;
    const float* src5 = Vp  + base;

    int arr = tid >> 4, seg = tid & 15;
    const float* mysrc = (arr==0)?src0:(arr==1)?src1:(arr==2)?src2:(arr==3)?src3:(arr==4)?src4:src5;

    auto pf = [&](int t){
        if (tid < 96){
            const float* g = mysrc + (size_t)t*64 + seg*4;
            unsigned sa = (unsigned)__cvta_generic_to_shared(&sm[(t&7)*384 + arr*64 + seg*4]);
            asm volatile("cp.async.ca.shared.global [%0], [%1], 16;"::"r"(sa),"l"(g));
        }
        asm volatile("cp.async.commit_group;");
    };

    #pragma unroll
    for (int s=0; s<4; s++) pf(s);

    u64 S2[4];
    #pragma unroll
    for (int i=0;i<4;i++) S2[i] = 0ull;

    for (int t=0; t<TT; t+=2){
        asm volatile("cp.async.wait_group 2;");
        __syncthreads();
        int p0 = t+4, p1 = t+5;
        if (p0 > TT-1) p0 = TT-1;
        if (p1 > TT-1) p1 = TT-1;
        pf(p0); pf(p1);

        #pragma unroll
        for (int u=0; u<2; u++){
            const float* st = &sm[((t+u) & 7) * 384];
            u64 ew2[4], bb2[4], aa2[4], kk2[4], rr2[4];
            #define LD2(dst, off) { \
                ulonglong2 q0 = *(const ulonglong2*)&st[(off)+col0]; \
                ulonglong2 q1 = *(const ulonglong2*)&st[(off)+col0+4]; \
                dst[0]=q0.x; dst[1]=q0.y; dst[2]=q1.x; dst[3]=q1.y; }
            LD2(ew2,   0) LD2(bb2,  64) LD2(aa2, 128) LD2(kk2, 192) LD2(rr2, 256)
            #undef LD2
            float vv = st[320 + row];

            // decay products (independent of sab) — issue first
            u64 d0 = MUL2(S2[0], ew2[0]);
            u64 d1 = MUL2(S2[1], ew2[1]);
            u64 d2 = MUL2(S2[2], ew2[2]);
            u64 d3 = MUL2(S2[3], ew2[3]);

            // sab dot (tree)
            u64 q0 = MUL2(S2[0], aa2[0]);
            u64 q1 = MUL2(S2[1], aa2[1]);
            q0 = FMA2(S2[2], aa2[2], q0);
            q1 = FMA2(S2[3], aa2[3], q1);
            float sab = red8(HADD2(ADD2(q0, q1)));

            u64 sab2 = PK2(sab), vv2 = PK2(vv);
            S2[0] = FMA2(kk2[0], vv2, FMA2(bb2[0], sab2, d0));
            S2[1] = FMA2(kk2[1], vv2, FMA2(bb2[1], sab2, d1));
            S2[2] = FMA2(kk2[2], vv2, FMA2(bb2[2], sab2, d2));
            S2[3] = FMA2(kk2[3], vv2, FMA2(bb2[3], sab2, d3));

            u64 o0 = MUL2(S2[0], rr2[0]);
            u64 o1 = MUL2(S2[1], rr2[1]);
            o0 = FMA2(S2[2], rr2[2], o0);
            o1 = FMA2(S2[3], rr2[3], o1);
            float oo = red8(HADD2(ADD2(o0, o1)));
            if ((tid & 7) == 0) O[base + (size_t)(t+u)*64 + row] = oo;
        }
    }
}

// ---------------- post: groupnorm + bonus + gate (output rounded to tf32) ----------------
__global__ __launch_bounds__(256) void post_kernel(
    const float* __restrict__ O, const float* __restrict__ Rp, const float* __restrict__ K2p,
    const float* __restrict__ Vp, const float* __restrict__ G,
    const float* __restrict__ r_k, const float* __restrict__ gn_w, const float* __restrict__ gn_b,
    float* __restrict__ Z)
{
    int gw = (blockIdx.x*256 + threadIdx.x) >> 5;
    int lane = threadIdx.x & 31;
    int h = gw & 15, t = (gw >> 4) & 1023, b = gw >> 14;
    size_t bhtd = ((size_t)((b*HH + h)*TT + t))*64 + lane*2;
    float2 o = *(const float2*)&O[bhtd];
    float sm = o.x + o.y;
    #pragma unroll
    for (int off=16; off>0; off>>=1) sm += __shfl_xor_sync(0xffffffffu, sm, off);
    float mean = sm * (1.f/64.f);
    float dx = o.x - mean, dy = o.y - mean;
    float vs = dx*dx + dy*dy;
    #pragma unroll
    for (int off=16; off>0; off>>=1) vs += __shfl_xor_sync(0xffffffffu, vs, off);
    float inv = rsqrtf(vs*(1.f/64.f) + GN_EPS);

    float2 r  = *(const float2*)&Rp[bhtd];
    float2 k2 = *(const float2*)&K2p[bhtd];
    float2 v  = *(const float2*)&Vp[bhtd];
    int c = h*64 + lane*2;
    float2 rk = *(const float2*)&r_k[c];
    float bs = r.x*k2.x*rk.x + r.y*k2.y*rk.y;
    #pragma unroll
    for (int off=16; off>0; off>>=1) bs += __shfl_xor_sync(0xffffffffu, bs, off);

    size_t btc = ((size_t)(b*TT + t))*CC + c;
    float2 g  = *(const float2*)&G[btc];
    float2 w  = *(const float2*)&gn_w[c];
    float2 bb = *(const float2*)&gn_b[c];
    float z0 = ((dx*inv)*w.x + bb.x + bs*v.x) * g.x;
    float z1 = ((dy*inv)*w.y + bb.y + bs*v.y) * g.y;
    *(float2*)&Z[btc] = make_float2(to_tf32(z0), to_tf32(z1));
}

// ---------------- driver ----------------
static inline GJob mkjob(const float* A, int lda, const float* B, float* C, int ldc,
                         int N, int K, const float* bias, int mode, float scale, int ro){
    GJob j; j.A=A; j.B=B; j.C=C; j.bias=bias; j.lda=lda; j.ldc=ldc;
    j.N=N; j.K=K; j.mode=mode; j.scale=scale; j.round_out=ro; return j;
}

extern "C" void kernel_launch(void* const* d_in, const int* in_sizes, int n_in,
                              void* d_out, int out_size) {
    const float* x   = (const float*)d_in[0];
    const float* vfi = (const float*)d_in[1];
    const float* x_r = (const float*)d_in[2];
    const float* x_w = (const float*)d_in[3];
    const float* x_k = (const float*)d_in[4];
    const float* x_v = (const float*)d_in[5];
    const float* x_a = (const float*)d_in[6];
    const float* x_g = (const float*)d_in[7];
    const float* Wr  = (const float*)d_in[8];
    const float* Wk  = (const float*)d_in[9];
    const float* Wv  = (const float*)d_in[10];
    const float* Wo  = (const float*)d_in[11];
    const float* w0  = (const float*)d_in[12];
    const float* w1  = (const float*)d_in[13];
    const float* w2  = (const float*)d_in[14];
    const float* a0  = (const float*)d_in[15];
    const float* a1  = (const float*)d_in[16];
    const float* a2  = (const float*)d_in[17];
    const float* v0  = (const float*)d_in[18];
    const float* v1  = (const float*)d_in[19];
    const float* v2  = (const float*)d_in[20];
    const float* g1  = (const float*)d_in[21];
    const float* g2  = (const float*)d_in[22];
    const float* k_k = (const float*)d_in[23];
    const float* k_a = (const float*)d_in[24];
    const float* r_k = (const float*)d_in[25];
    const float* gnw = (const float*)d_in[26];
    const float* gnb = (const float*)d_in[27];
    float* out = (float*)d_out;

    float* S;
    cudaGetSymbolAddress((void**)&S, gScratch);

    const int SM128 = 3*(128+128)*32*4;   // 98304
    const int SM64  = 3*(128+64)*32*4;    // 73728
    cudaFuncSetAttribute(gemm_mma<128>, cudaFuncAttributeMaxDynamicSharedMemorySize, SM128);
    cudaFuncSetAttribute(gemm_mma<64>,  cudaFuncAttributeMaxDynamicSharedMemorySize, SM64);

    const int M = BB*TT;
    float* H = S + OHST;   // 4096 x 320

    // 0: round big weights to tf32
    round_weights<<<16384, 256>>>(Wr, Wk, Wv, Wo, S);
    // 1: BU + stage-2 weight transposes (fused)
    build_weights2<<<3712, 256>>>(w1, a1, v1, g1, w2, a2, v2, g2,
                                  x_w, x_a, x_v, x_g, S);
    // 2: token-shift mixes + [x|xx]
    mix_kernel<<<BB*TT, 256>>>(x, x_r, x_k, x_v, S+OXR, S+OXK, S+OXV, S+OXC);
    // 3: R/K/V projections, z-batched  <-- profiled launch
    {
        GJob jr = mkjob(S+OXR, 1024, S+OWRr, S+ORB, 1024, 1024, 1024, nullptr, 0, 1.f, 0);
        GJob jk = mkjob(S+OXK, 1024, S+OWKr, S+OKB, 1024, 1024, 1024, nullptr, 0, 1.f, 0);
        GJob jv = mkjob(S+OXV, 1024, S+OWVr, S+OVB, 1024, 1024, 1024, nullptr, 0, 1.f, 0);
        gemm_mma<128><<<dim3(M/128,8,3), 256, SM128>>>(jr, jk, jv, jr);
    }
    // 4: fused stage-1: H = [x|xx] @ BU^T
    {
        GJob js = mkjob(S+OXC, 2048, S+OBU, H, 320, 320, 2048, nullptr, 3, 1.f, 1);
        gemm_mma<64><<<dim3(M/128,5,1), 256, SM64>>>(js, js, js, js);
    }
    // 5: stage-2 low-rank outputs, z-batched (WL, a, vmix, g)
    {
        GJob jw = mkjob(H+0,   320, S+OW2T, S+OWL,  1024, 1024, 64,  w0, 2, LOG_DECAY, 0);
        GJob ja = mkjob(H+64,  320, S+OA2T, S+OAB,  1024, 1024, 64,  a0, 2, 1.f, 0);
        GJob jv = mkjob(H+128, 320, S+OV2T, S+OVMX, 1024, 1024, 32,  v0, 2, 1.f, 0);
        GJob jg = mkjob(H+192, 320, S+OG2T, S+OGB,  1024, 1024, 128, nullptr, 0, 1.f, 0);
        gemm_mma<128><<<dim3(M/128,8,4), 256, SM128>>>(jw, ja, jv, jg);
    }
    // 6: scan operand prep
    prep_kernel<<<(BB*TT*HH*32)/256, 256>>>(S+OKB, S+OAB, S+OVB, S+OWL, S+OVMX, vfi, S+ORB,
                                            k_k, k_a,
                                            S+OEW, S+OBBA, S+OAAA, S+OKK2, S+ORRA, S+OVVA);
    // 7: sequential scan
    scan_kernel<<<BB*HH*2, 256>>>(S+OEW, S+OBBA, S+OAAA, S+OKK2, S+ORRA, S+OVVA, S+OOB);
    // 8: groupnorm + bonus + gate
    post_kernel<<<(BB*TT*HH*32)/256, 256>>>(S+OOB, S+ORRA, S+OKK2, S+OVVA, S+OGB,
                                            r_k, gnw, gnb, S+OZB);
    // 9: out = Z @ Wo^T
    {
        GJob jo = mkjob(S+OZB, 1024, S+OWOr, out, 1024, 1024, 1024, nullptr, 0, 1.f, 0);
        gemm_mma<128><<<dim3(M/128,8,1), 256, SM128>>>(jo, jo, jo, jo);
    }
    // v_first passthrough
    if (out_size >= 2*NE){
        cudaMemcpyAsync(out + NE, vfi, (size_t)NE*sizeof(float), cudaMemcpyDeviceToDevice);
    }
}

// round 7
// speedup vs baseline: 1.9782x; 1.0392x over previous
#include <cuda_runtime.h>
#include <math.h>
#include <stdint.h>

#define BB 4
#define TT 1024
#define CC 1024
#define HH 16
#define DD 64
#define NE 4194304     // B*T*C
#define LOG_DECAY (-0.6065306597126334f)
#define GN_EPS 64e-5f

typedef unsigned long long u64;

// ---------------- static scratch ----------------
__device__ float gScratch[104857600];

#define OXR  ((size_t)0*NE)
#define OXK  ((size_t)2*NE)
#define OXV  ((size_t)3*NE)
#define OXC  ((size_t)4*NE)            // [x | xx] 4096 x 2048 (spans 2*NE)
#define ORB  ((size_t)6*NE)
#define OKB  ((size_t)7*NE)
#define OVB  ((size_t)8*NE)
#define OAB  ((size_t)9*NE)
#define OGB  ((size_t)10*NE)
#define OWL  ((size_t)11*NE)
#define OVMX ((size_t)12*NE)
#define OHST ((size_t)13*NE)           // stage-1 fused output H: 4096 x 320
#define OEW  ((size_t)14*NE)
#define OBBA ((size_t)15*NE)
#define OAAA ((size_t)16*NE)
#define OKK2 ((size_t)17*NE)
#define OVVA ((size_t)19*NE)
#define OOB  ((size_t)20*NE)
#define OZB  ((size_t)21*NE)
#define OW2T ((size_t)22*NE)
#define OA2T (OW2T + 65536)
#define OV2T (OA2T + 65536)
#define OG2T (OV2T + 32768)
#define OWRr (OG2T + 131072)
#define OWKr (OWRr + 1048576)
#define OWVr (OWKr + 1048576)
#define OWOr (OWVr + 1048576)
#define OBU  (OWOr + 1048576)          // stacked stage-1 weights: 320 x 2048

__device__ __forceinline__ float to_tf32(float x){
    uint32_t u; asm("cvt.rna.tf32.f32 %0, %1;" : "=r"(u) : "f"(x));
    return __uint_as_float(u);
}
__device__ __forceinline__ float sigm_(float x){ return 1.f/(1.f+expf(-x)); }

__device__ __forceinline__ void mma8(float* d, const uint32_t* a, const uint32_t* b){
    asm volatile("mma.sync.aligned.m16n8k8.row.col.f32.tf32.tf32.f32 "
        "{%0,%1,%2,%3}, {%4,%5,%6,%7}, {%8,%9}, {%0,%1,%2,%3};"
        : "+f"(d[0]), "+f"(d[1]), "+f"(d[2]), "+f"(d[3])
        : "r"(a[0]), "r"(a[1]), "r"(a[2]), "r"(a[3]), "r"(b[0]), "r"(b[1]));
}
__device__ __forceinline__ void ldsm4(uint32_t* r, uint32_t a){
    asm volatile("ldmatrix.sync.aligned.m8n8.x4.shared.b16 {%0,%1,%2,%3}, [%4];"
        : "=r"(r[0]),"=r"(r[1]),"=r"(r[2]),"=r"(r[3]) : "r"(a));
}
__device__ __forceinline__ int swz(int r, int c){
    return r*32 + (int)((((((unsigned)c>>2) ^ ((unsigned)r & 7u)) << 2)) | ((unsigned)c & 3u));
}

// f32x2 packed math helpers
__device__ __forceinline__ u64 FMA2(u64 a, u64 b, u64 c){
    u64 d; asm("fma.rn.f32x2 %0, %1, %2, %3;" : "=l"(d) : "l"(a), "l"(b), "l"(c)); return d;
}
__device__ __forceinline__ u64 MUL2(u64 a, u64 b){
    u64 d; asm("mul.rn.f32x2 %0, %1, %2;" : "=l"(d) : "l"(a), "l"(b)); return d;
}
__device__ __forceinline__ u64 ADD2(u64 a, u64 b){
    u64 d; asm("add.rn.f32x2 %0, %1, %2;" : "=l"(d) : "l"(a), "l"(b)); return d;
}
__device__ __forceinline__ u64 PK2(float x){
    u64 d; asm("mov.b64 %0, {%1, %1};" : "=l"(d) : "f"(x)); return d;
}
__device__ __forceinline__ float HADD2(u64 d){
    float a, b; asm("mov.b64 {%0, %1}, %2;" : "=f"(a), "=f"(b) : "l"(d)); return a + b;
}

// ---------------- job descriptor for batched GEMM ----------------
struct GJob {
    const float* A; const float* B; float* C; const float* bias;
    int lda, ldc, N, K, mode; float scale; int round_out;
};

// ---------------- tf32 GEMM (mma.sync + ldmatrix): C = A * B^T, z-batched ----------------
// mode: 0 plain(+bias), 1 tanh, 2 scale*sigmoid(x+bias), 3 per-col stage1
template<int NT>
__global__ void __launch_bounds__(256,2) gemm_mma(GJob j0, GJob j1, GJob j2, GJob j3)
{
    extern __shared__ float sm[];
    const int AS  = 128*32;
    const int STG = (128+NT)*32;
    const int NTN = (NT==128) ? 8 : 4;
    const int NLD = NTN/2;

    GJob jb = j0;
    if (blockIdx.z == 1) jb = j1;
    else if (blockIdx.z == 2) jb = j2;
    else if (blockIdx.z == 3) jb = j3;

    int tid = threadIdx.x, wid = tid >> 5, lane = tid & 31;
    int bm0 = blockIdx.x * 128, bn0 = blockIdx.y * NT;
    int grp = lane >> 2, thr = lane & 3;
    int wm = (wid & 3) * 32;
    int wn = (NT==128) ? (wid >> 2) * 64 : (wid >> 2) * 32;
    int NC = jb.K >> 5;

    float acc[2][NTN][4];
    #pragma unroll
    for (int i=0;i<2;i++)
      #pragma unroll
      for (int j=0;j<NTN;j++)
        #pragma unroll
        for (int l=0;l<4;l++) acc[i][j][l]=0.f;

    uint32_t smb = (uint32_t)__cvta_generic_to_shared(sm);

    uint32_t aoff[2][4], boff[NLD][4];
    #pragma unroll
    for (int mt=0;mt<2;mt++)
      #pragma unroll
      for (int kk=0;kk<4;kk++){
        int row = wm + mt*16 + (lane & 15);
        int col = kk*8 + (lane >> 4) * 4;
        aoff[mt][kk] = 4u * (uint32_t)swz(row, col);
      }
    #pragma unroll
    for (int np=0;np<NLD;np++)
      #pragma unroll
      for (int kk=0;kk<4;kk++){
        int row = wn + np*16 + (lane & 7) + ((lane >> 4) & 1) * 8;
        int col = kk*8 + ((lane >> 3) & 1) * 4;
        boff[np][kk] = 4u * (uint32_t)(AS + swz(row, col));
      }

    auto load_stage = [&](int stg, int c){
        const float* Ag = jb.A + (size_t)bm0 * jb.lda + c*32;
        #pragma unroll
        for (int i=0;i<4;i++){
            int idx = tid + 256*i; int r = idx>>3, j = idx&7;
            unsigned dst = smb + 4u*(uint32_t)(stg*STG + swz(r, j*4));
            const float* src = Ag + (size_t)r*jb.lda + j*4;
            asm volatile("cp.async.cg.shared.global [%0], [%1], 16;"::"r"(dst),"l"(src));
        }
        const float* Bg = jb.B + (size_t)bn0 * jb.K + c*32;
        #pragma unroll
        for (int i=0;i<NT/32;i++){
            int idx = tid + 256*i; int r = idx>>3, j = idx&7;
            unsigned dst = smb + 4u*(uint32_t)(stg*STG + AS + swz(r, j*4));
            const float* src = Bg + (size_t)r*jb.K + j*4;
            asm volatile("cp.async.cg.shared.global [%0], [%1], 16;"::"r"(dst),"l"(src));
        }
    };

    load_stage(0, 0);
    asm volatile("cp.async.commit_group;");
    if (NC > 1) load_stage(1, 1);
    asm volatile("cp.async.commit_group;");

    for (int c = 0; c < NC; c++){
        asm volatile("cp.async.wait_group 1;");
        __syncthreads();
        uint32_t sb = smb + 4u*(uint32_t)((c % 3) * STG);
        #pragma unroll
        for (int kk=0; kk<4; kk++){
            uint32_t af[2][4];
            ldsm4(af[0], sb + aoff[0][kk]);
            ldsm4(af[1], sb + aoff[1][kk]);
            uint32_t bf[NLD][4];
            #pragma unroll
            for (int np=0;np<NLD;np++) ldsm4(bf[np], sb + boff[np][kk]);
            #pragma unroll
            for (int mt=0;mt<2;mt++)
                #pragma unroll
                for (int nt=0;nt<NTN;nt++)
                    mma8(acc[mt][nt], af[mt], &bf[nt>>1][(nt&1)*2]);
        }
        if (c + 2 < NC) load_stage((c+2) % 3, c+2);
        asm volatile("cp.async.commit_group;");
    }

    #pragma unroll
    for (int mt=0;mt<2;mt++){
        #pragma unroll
        for (int nt=0;nt<NTN;nt++){
            #pragma unroll
            for (int half=0; half<2; half++){
                int row = bm0 + wm + mt*16 + grp + half*8;
                int col = bn0 + wn + nt*8 + thr*2;
                float v0 = acc[mt][nt][half*2+0];
                float v1 = acc[mt][nt][half*2+1];
                if (jb.bias){ v0 += jb.bias[col]; v1 += jb.bias[col+1]; }
                if (jb.mode==1){ v0 = tanhf(v0); v1 = tanhf(v1); }
                else if (jb.mode==2){ v0 = jb.scale*sigm_(v0); v1 = jb.scale*sigm_(v1); }
                else if (jb.mode==3){
                    v0 = (col   < 64) ? tanhf(v0) : (col   < 192 ? v0 : sigm_(v0));
                    v1 = (col+1 < 64) ? tanhf(v1) : (col+1 < 192 ? v1 : sigm_(v1));
                }
                if (jb.round_out){ v0 = to_tf32(v0); v1 = to_tf32(v1); }
                float* cp = jb.C + (size_t)row*jb.ldc + col;
                cp[0] = v0; cp[1] = v1;
            }
        }
    }
}

// ---------------- all weight prep fused: round big + BU + stage-2 transposes ----------------
__device__ __forceinline__ void do_tr(const float* src, float* dst, int rows, int cols, int li){
    int r = li / cols, c = li - r * cols;
    dst[(size_t)c * rows + r] = to_tf32(src[li]);
}
__global__ __launch_bounds__(256) void prep_weights(
    const float* __restrict__ Wr, const float* __restrict__ Wk,
    const float* __restrict__ Wv, const float* __restrict__ Wo,
    const float* __restrict__ w1, const float* __restrict__ a1,
    const float* __restrict__ v1, const float* __restrict__ g1,
    const float* __restrict__ w2, const float* __restrict__ a2,
    const float* __restrict__ v2, const float* __restrict__ g2,
    const float* __restrict__ x_w, const float* __restrict__ x_a,
    const float* __restrict__ x_v, const float* __restrict__ x_g,
    float* __restrict__ Sg)
{
    int idx = blockIdx.x * 256 + threadIdx.x;
    if (idx < 4194304){
        int m = idx >> 20;
        int i = idx & 1048575;
        const float* src = (m == 0) ? Wr : (m == 1) ? Wk : (m == 2) ? Wv : Wo;
        float* dst = Sg + ((m == 0) ? OWRr : (m == 1) ? OWKr : (m == 2) ? OWVr : OWOr);
        dst[i] = to_tf32(src[i]);
        return;
    }
    idx -= 4194304;
    if (idx < 655360){
        int n = idx >> 11;
        int k = idx & 2047;
        int kk = k & 1023;
        float val = 0.f;
        if (n < 64){
            float w = w1[kk*64 + n];
            val = (k < 1024) ? w : x_w[kk]*w;
        } else if (n < 128){
            float w = a1[kk*64 + (n-64)];
            val = (k < 1024) ? w : x_a[kk]*w;
        } else if (n < 160){
            float w = v1[kk*32 + (n-128)];
            val = (k < 1024) ? w : x_v[kk]*w;
        } else if (n >= 192){
            float w = g1[kk*128 + (n-192)];
            val = (k < 1024) ? w : x_g[kk]*w;
        }
        Sg[OBU + idx] = to_tf32(val);
        return;
    }
    int j = idx - 655360;
    if (j >= 294912) return;
    if      (j < 65536 )  do_tr(w2, Sg+OW2T, 64, 1024,  j);
    else if (j < 131072)  do_tr(a2, Sg+OA2T, 64, 1024,  j-65536);
    else if (j < 163840)  do_tr(v2, Sg+OV2T, 32, 1024,  j-131072);
    else                  do_tr(g2, Sg+OG2T, 128, 1024, j-163840);
}

// ---------------- token-shift mix: XR/XK/XV + [x|xx] (all tf32-rounded) ----------------
__global__ __launch_bounds__(256) void mix_kernel(
    const float* __restrict__ x,
    const float* __restrict__ mr, const float* __restrict__ mk, const float* __restrict__ mv,
    float* __restrict__ XR, float* __restrict__ XK, float* __restrict__ XV,
    float* __restrict__ XC)
{
    int row = blockIdx.x;
    int t = row & (TT-1);
    int c4 = threadIdx.x;
    const float4* xv4 = (const float4*)x;
    float4 xc = xv4[(size_t)row*256 + c4];
    float4 xp = make_float4(0.f,0.f,0.f,0.f);
    if (t > 0) xp = xv4[(size_t)(row-1)*256 + c4];
    float4 dx = make_float4(xp.x-xc.x, xp.y-xc.y, xp.z-xc.z, xp.w-xc.w);
    size_t o = (size_t)row*256 + c4;
    float4 m;
    #define MIXOUT(dst, mp) \
        m = ((const float4*)mp)[c4]; \
        ((float4*)dst)[o] = make_float4(to_tf32(xc.x+dx.x*m.x), to_tf32(xc.y+dx.y*m.y), \
                                        to_tf32(xc.z+dx.z*m.z), to_tf32(xc.w+dx.w*m.w));
    MIXOUT(XR, mr) MIXOUT(XK, mk) MIXOUT(XV, mv)
    #undef MIXOUT
    float4* xcp = (float4*)(XC + (size_t)row*2048);
    xcp[c4]       = make_float4(to_tf32(xc.x), to_tf32(xc.y), to_tf32(xc.z), to_tf32(xc.w));
    xcp[256 + c4] = make_float4(to_tf32(dx.x), to_tf32(dx.y), to_tf32(dx.z), to_tf32(dx.w));
}

// ---------------- scan-operand prep (no r copy) ----------------
__global__ __launch_bounds__(256) void prep_kernel(
    const float* __restrict__ K, const float* __restrict__ A, const float* __restrict__ V,
    const float* __restrict__ WL, const float* __restrict__ VMIX, const float* __restrict__ vfirst,
    const float* __restrict__ k_k, const float* __restrict__ k_a,
    float* __restrict__ EW, float* __restrict__ BBo, float* __restrict__ AAo,
    float* __restrict__ K2o, float* __restrict__ Vo)
{
    int gw = (blockIdx.x*256 + threadIdx.x) >> 5;
    int lane = threadIdx.x & 31;
    int h = gw & 15, t = (gw >> 4) & 1023, b = gw >> 14;
    int c = h*64 + lane*2;
    size_t btc = ((size_t)(b*TT + t))*CC + c;
    float2 k  = *(const float2*)&K[btc];
    float2 kw = *(const float2*)&k_k[c];
    float2 ka = *(const float2*)&k_a[c];
    float2 a  = *(const float2*)&A[btc];
    float kk0 = k.x*kw.x, kk1 = k.y*kw.y;
    float ss = kk0*kk0 + kk1*kk1;
    #pragma unroll
    for (int off=16; off>0; off>>=1) ss += __shfl_xor_sync(0xffffffffu, ss, off);
    float inv = 1.f / fmaxf(sqrtf(ss), 1e-12f);
    kk0 *= inv; kk1 *= inv;
    float2 wl = *(const float2*)&WL[btc];
    float2 v  = *(const float2*)&V[btc];
    float2 vf = *(const float2*)&vfirst[btc];
    float2 vm = *(const float2*)&VMIX[btc];
    v.x = v.x + (vf.x - v.x)*vm.x;
    v.y = v.y + (vf.y - v.y)*vm.y;
    float k20 = k.x*(1.f + (a.x-1.f)*ka.x);
    float k21 = k.y*(1.f + (a.y-1.f)*ka.y);
    size_t bhtd = ((size_t)((b*HH + h)*TT + t))*64 + lane*2;
    *(float2*)&EW[bhtd]  = make_float2(expf(wl.x), expf(wl.y));
    *(float2*)&BBo[bhtd] = make_float2(kk0*a.x, kk1*a.y);
    *(float2*)&AAo[bhtd] = make_float2(-kk0, -kk1);
    *(float2*)&K2o[bhtd] = make_float2(k20, k21);
    *(float2*)&Vo[bhtd]  = v;
}

// ---------------- sequential RWKV7 scan (f32x2, 16-stage ring, 4 steps/barrier) ----------------
__device__ __forceinline__ float red8(float v){
    v += __shfl_xor_sync(0xffffffffu, v, 1);
    v += __shfl_xor_sync(0xffffffffu, v, 2);
    v += __shfl_xor_sync(0xffffffffu, v, 4);
    return v;
}

__global__ __launch_bounds__(256) void scan_kernel(
    const float* __restrict__ EW, const float* __restrict__ BBp, const float* __restrict__ AAp,
    const float* __restrict__ K2p, const float* __restrict__ RB, const float* __restrict__ Vp,
    float* __restrict__ O)
{
    __shared__ float sm[16*6*64];   // 16 stages x 6 arrays x 64 = 24KB
    int bh = blockIdx.x >> 1;
    int b = bh >> 4, h = bh & 15;
    int rowBase = (blockIdx.x & 1) * 32;
    int tid = threadIdx.x;
    int row = rowBase + (tid >> 3);
    int col0 = (tid & 7) * 8;
    size_t base = (size_t)bh * TT * 64;

    int arr = tid >> 4, seg = tid & 15;
    const float* mysrc = nullptr; int mystride = 64;
    if (tid < 96){
        switch (arr){
            case 0: mysrc = EW  + base; break;
            case 1: mysrc = BBp + base; break;
            case 2: mysrc = AAp + base; break;
            case 3: mysrc = K2p + base; break;
            case 4: mysrc = RB + (size_t)b*TT*CC + h*64; mystride = CC; break;
            case 5: mysrc = Vp  + base; break;
        }
    }
    uint32_t smb = (uint32_t)__cvta_generic_to_shared(sm);

    auto pf4 = [&](int batch){
        if (tid < 96){
            #pragma unroll
            for (int u=0; u<4; u++){
                int t = batch*4 + u;
                const float* g = mysrc + (size_t)t*mystride + seg*4;
                unsigned sa = smb + 4u*(uint32_t)(((t&15)*384) + arr*64 + seg*4);
                asm volatile("cp.async.ca.shared.global [%0], [%1], 16;"::"r"(sa),"l"(g));
            }
        }
        asm volatile("cp.async.commit_group;");
    };

    pf4(0); pf4(1); pf4(2);

    u64 S2[4];
    #pragma unroll
    for (int i=0;i<4;i++) S2[i] = 0ull;

    for (int i=0; i<256; i++){
        asm volatile("cp.async.wait_group 2;");
        __syncthreads();
        if (i+3 < 256) pf4(i+3);
        else asm volatile("cp.async.commit_group;");
        int tb = i*4;

        #pragma unroll
        for (int u=0; u<4; u++){
            const float* st = &sm[((tb+u) & 15) * 384];
            u64 ew2[4], bb2[4], aa2[4], kk2[4], rr2[4];
            #define LD2(dst, off) { \
                ulonglong2 q0 = *(const ulonglong2*)&st[(off)+col0]; \
                ulonglong2 q1 = *(const ulonglong2*)&st[(off)+col0+4]; \
                dst[0]=q0.x; dst[1]=q0.y; dst[2]=q1.x; dst[3]=q1.y; }
            LD2(ew2,   0) LD2(bb2,  64) LD2(aa2, 128) LD2(kk2, 192) LD2(rr2, 256)
            #undef LD2
            float vv = st[320 + row];

            u64 d0 = MUL2(S2[0], ew2[0]);
            u64 d1 = MUL2(S2[1], ew2[1]);
            u64 d2 = MUL2(S2[2], ew2[2]);
            u64 d3 = MUL2(S2[3], ew2[3]);

            u64 q0 = MUL2(S2[0], aa2[0]);
            u64 q1 = MUL2(S2[1], aa2[1]);
            q0 = FMA2(S2[2], aa2[2], q0);
            q1 = FMA2(S2[3], aa2[3], q1);
            float sab = red8(HADD2(ADD2(q0, q1)));

            u64 sab2 = PK2(sab), vv2 = PK2(vv);
            S2[0] = FMA2(kk2[0], vv2, FMA2(bb2[0], sab2, d0));
            S2[1] = FMA2(kk2[1], vv2, FMA2(bb2[1], sab2, d1));
            S2[2] = FMA2(kk2[2], vv2, FMA2(bb2[2], sab2, d2));
            S2[3] = FMA2(kk2[3], vv2, FMA2(bb2[3], sab2, d3));

            u64 o0 = MUL2(S2[0], rr2[0]);
            u64 o1 = MUL2(S2[1], rr2[1]);
            o0 = FMA2(S2[2], rr2[2], o0);
            o1 = FMA2(S2[3], rr2[3], o1);
            float oo = red8(HADD2(ADD2(o0, o1)));
            if ((tid & 7) == 0) O[base + (size_t)(tb+u)*64 + row] = oo;
        }
    }
}

// ---------------- post: groupnorm + bonus + gate (output rounded to tf32) ----------------
__global__ __launch_bounds__(256) void post_kernel(
    const float* __restrict__ O, const float* __restrict__ RB, const float* __restrict__ K2p,
    const float* __restrict__ Vp, const float* __restrict__ G,
    const float* __restrict__ r_k, const float* __restrict__ gn_w, const float* __restrict__ gn_b,
    float* __restrict__ Z)
{
    int gw = (blockIdx.x*256 + threadIdx.x) >> 5;
    int lane = threadIdx.x & 31;
    int h = gw & 15, t = (gw >> 4) & 1023, b = gw >> 14;
    size_t bhtd = ((size_t)((b*HH + h)*TT + t))*64 + lane*2;
    int c = h*64 + lane*2;
    size_t btc = ((size_t)(b*TT + t))*CC + c;

    float2 o = *(const float2*)&O[bhtd];
    float sm = o.x + o.y;
    #pragma unroll
    for (int off=16; off>0; off>>=1) sm += __shfl_xor_sync(0xffffffffu, sm, off);
    float mean = sm * (1.f/64.f);
    float dx = o.x - mean, dy = o.y - mean;
    float vs = dx*dx + dy*dy;
    #pragma unroll
    for (int off=16; off>0; off>>=1) vs += __shfl_xor_sync(0xffffffffu, vs, off);
    float inv = rsqrtf(vs*(1.f/64.f) + GN_EPS);

    float2 r  = *(const float2*)&RB[btc];
    float2 k2 = *(const float2*)&K2p[bhtd];
    float2 v  = *(const float2*)&Vp[bhtd];
    float2 rk = *(const float2*)&r_k[c];
    float bs = r.x*k2.x*rk.x + r.y*k2.y*rk.y;
    #pragma unroll
    for (int off=16; off>0; off>>=1) bs += __shfl_xor_sync(0xffffffffu, bs, off);

    float2 g  = *(const float2*)&G[btc];
    float2 w  = *(const float2*)&gn_w[c];
    float2 bb = *(const float2*)&gn_b[c];
    float z0 = ((dx*inv)*w.x + bb.x + bs*v.x) * g.x;
    float z1 = ((dy*inv)*w.y + bb.y + bs*v.y) * g.y;
    *(float2*)&Z[btc] = make_float2(to_tf32(z0), to_tf32(z1));
}

// ---------------- driver ----------------
static inline GJob mkjob(const float* A, int lda, const float* B, float* C, int ldc,
                         int N, int K, const float* bias, int mode, float scale, int ro){
    GJob j; j.A=A; j.B=B; j.C=C; j.bias=bias; j.lda=lda; j.ldc=ldc;
    j.N=N; j.K=K; j.mode=mode; j.scale=scale; j.round_out=ro; return j;
}

extern "C" void kernel_launch(void* const* d_in, const int* in_sizes, int n_in,
                              void* d_out, int out_size) {
    const float* x   = (const float*)d_in[0];
    const float* vfi = (const float*)d_in[1];
    const float* x_r = (const float*)d_in[2];
    const float* x_w = (const float*)d_in[3];
    const float* x_k = (const float*)d_in[4];
    const float* x_v = (const float*)d_in[5];
    const float* x_a = (const float*)d_in[6];
    const float* x_g = (const float*)d_in[7];
    const float* Wr  = (const float*)d_in[8];
    const float* Wk  = (const float*)d_in[9];
    const float* Wv  = (const float*)d_in[10];
    const float* Wo  = (const float*)d_in[11];
    const float* w0  = (const float*)d_in[12];
    const float* w1  = (const float*)d_in[13];
    const float* w2  = (const float*)d_in[14];
    const float* a0  = (const float*)d_in[15];
    const float* a1  = (const float*)d_in[16];
    const float* a2  = (const float*)d_in[17];
    const float* v0  = (const float*)d_in[18];
    const float* v1  = (const float*)d_in[19];
    const float* v2  = (const float*)d_in[20];
    const float* g1  = (const float*)d_in[21];
    const float* g2  = (const float*)d_in[22];
    const float* k_k = (const float*)d_in[23];
    const float* k_a = (const float*)d_in[24];
    const float* r_k = (const float*)d_in[25];
    const float* gnw = (const float*)d_in[26];
    const float* gnb = (const float*)d_in[27];
    float* out = (float*)d_out;

    float* S;
    cudaGetSymbolAddress((void**)&S, gScratch);

    const int SM128 = 3*(128+128)*32*4;   // 98304
    const int SM64  = 3*(128+64)*32*4;    // 73728
    cudaFuncSetAttribute(gemm_mma<128>, cudaFuncAttributeMaxDynamicSharedMemorySize, SM128);
    cudaFuncSetAttribute(gemm_mma<64>,  cudaFuncAttributeMaxDynamicSharedMemorySize, SM64);

    const int M = BB*TT;
    float* H = S + OHST;   // 4096 x 320

    // 0: all weight prep (round + BU + stage-2 transposes)
    prep_weights<<<20096, 256>>>(Wr, Wk, Wv, Wo, w1, a1, v1, g1, w2, a2, v2, g2,
                                 x_w, x_a, x_v, x_g, S);
    // 1: token-shift mixes + [x|xx]
    mix_kernel<<<BB*TT, 256>>>(x, x_r, x_k, x_v, S+OXR, S+OXK, S+OXV, S+OXC);
    // 2: fused stage-1: H = [x|xx] @ BU^T
    {
        GJob js = mkjob(S+OXC, 2048, S+OBU, H, 320, 320, 2048, nullptr, 3, 1.f, 1);
        gemm_mma<64><<<dim3(M/128,5,1), 256, SM64>>>(js, js, js, js);
    }
    // 3: R/K/V projections, z-batched  <-- profiled launch (idx 3)
    {
        GJob jr = mkjob(S+OXR, 1024, S+OWRr, S+ORB, 1024, 1024, 1024, nullptr, 0, 1.f, 0);
        GJob jk = mkjob(S+OXK, 1024, S+OWKr, S+OKB, 1024, 1024, 1024, nullptr, 0, 1.f, 0);
        GJob jv = mkjob(S+OXV, 1024, S+OWVr, S+OVB, 1024, 1024, 1024, nullptr, 0, 1.f, 0);
        gemm_mma<128><<<dim3(M/128,8,3), 256, SM128>>>(jr, jk, jv, jr);
    }
    // 4: stage-2 low-rank outputs, z-batched (WL, a, vmix, g)
    {
        GJob jw = mkjob(H+0,   320, S+OW2T, S+OWL,  1024, 1024, 64,  w0, 2, LOG_DECAY, 0);
        GJob ja = mkjob(H+64,  320, S+OA2T, S+OAB,  1024, 1024, 64,  a0, 2, 1.f, 0);
        GJob jv = mkjob(H+128, 320, S+OV2T, S+OVMX, 1024, 1024, 32,  v0, 2, 1.f, 0);
        GJob jg = mkjob(H+192, 320, S+OG2T, S+OGB,  1024, 1024, 128, nullptr, 0, 1.f, 0);
        gemm_mma<128><<<dim3(M/128,8,4), 256, SM128>>>(jw, ja, jv, jg);
    }
    // 5: scan operand prep
    prep_kernel<<<(BB*TT*HH*32)/256, 256>>>(S+OKB, S+OAB, S+OVB, S+OWL, S+OVMX, vfi,
                                            k_k, k_a,
                                            S+OEW, S+OBBA, S+OAAA, S+OKK2, S+OVVA);
    // 6: sequential scan (reads r directly from ORB)
    scan_kernel<<<BB*HH*2, 256>>>(S+OEW, S+OBBA, S+OAAA, S+OKK2, S+ORB, S+OVVA, S+OOB);
    // 7: groupnorm + bonus + gate
    post_kernel<<<(BB*TT*HH*32)/256, 256>>>(S+OOB, S+ORB, S+OKK2, S+OVVA, S+OGB,
                                            r_k, gnw, gnb, S+OZB);
    // 8: out = Z @ Wo^T
    {
        GJob jo = mkjob(S+OZB, 1024, S+OWOr, out, 1024, 1024, 1024, nullptr, 0, 1.f, 0);
        gemm_mma<128><<<dim3(M/128,8,1), 256, SM128>>>(jo, jo, jo, jo);
    }
    // v_first passthrough
    if (out_size >= 2*NE){
        cudaMemcpyAsync(out + NE, vfi, (size_t)NE*sizeof(float), cudaMemcpyDeviceToDevice);
    }
}

// round 8
// speedup vs baseline: 2.0090x; 1.0156x over previous
#include <cuda_runtime.h>
#include <math.h>
#include <stdint.h>

#define BB 4
#define TT 1024
#define CC 1024
#define HH 16
#define DD 64
#define NE 4194304     // B*T*C
#define LOG_DECAY (-0.6065306597126334f)
#define GN_EPS 64e-5f

typedef unsigned long long u64;

// ---------------- static scratch ----------------
__device__ float gScratch[104857600];

#define OO4  ((size_t)0)               // scan partials: 64bh x 1024t x 256 = 4*NE (slots 0-3)
#define OXR  ((size_t)0*NE)            // mix outputs (dead before scan)
#define OXK  ((size_t)2*NE)
#define OXV  ((size_t)3*NE)
#define OXC  ((size_t)4*NE)            // [x | xx] 4096 x 2048 (slots 4-5)
#define ORB  ((size_t)6*NE)
#define OKB  ((size_t)7*NE)
#define OVB  ((size_t)8*NE)
#define OAB  ((size_t)9*NE)
#define OGB  ((size_t)10*NE)
#define OWL  ((size_t)11*NE)
#define OVMX ((size_t)12*NE)
#define OHST ((size_t)13*NE)           // stage-1 H: 4096 x 320
#define OHLO ((size_t)14*NE)           // stage-1 half products
#define OHHI ((size_t)15*NE)
#define OEW  ((size_t)16*NE)
#define OBBA ((size_t)17*NE)
#define OAAA ((size_t)18*NE)
#define OKK2 ((size_t)19*NE)
#define OVVA ((size_t)20*NE)
#define OZB  ((size_t)21*NE)
#define OW2T ((size_t)22*NE)
#define OA2T (OW2T + 65536)
#define OV2T (OA2T + 65536)
#define OG2T (OV2T + 32768)
#define OWRr (OG2T + 131072)
#define OWKr (OWRr + 1048576)
#define OWVr (OWKr + 1048576)
#define OWOr (OWVr + 1048576)
#define OBU  (OWOr + 1048576)          // stacked stage-1 weights: 320 x 2048

__device__ __forceinline__ float to_tf32(float x){
    uint32_t u; asm("cvt.rna.tf32.f32 %0, %1;" : "=r"(u) : "f"(x));
    return __uint_as_float(u);
}
__device__ __forceinline__ float sigm_(float x){ return 1.f/(1.f+expf(-x)); }

__device__ __forceinline__ void mma8(float* d, const uint32_t* a, const uint32_t* b){
    asm volatile("mma.sync.aligned.m16n8k8.row.col.f32.tf32.tf32.f32 "
        "{%0,%1,%2,%3}, {%4,%5,%6,%7}, {%8,%9}, {%0,%1,%2,%3};"
        : "+f"(d[0]), "+f"(d[1]), "+f"(d[2]), "+f"(d[3])
        : "r"(a[0]), "r"(a[1]), "r"(a[2]), "r"(a[3]), "r"(b[0]), "r"(b[1]));
}
__device__ __forceinline__ void ldsm4(uint32_t* r, uint32_t a){
    asm volatile("ldmatrix.sync.aligned.m8n8.x4.shared.b16 {%0,%1,%2,%3}, [%4];"
        : "=r"(r[0]),"=r"(r[1]),"=r"(r[2]),"=r"(r[3]) : "r"(a));
}
__device__ __forceinline__ int swz(int r, int c){
    return r*32 + (int)((((((unsigned)c>>2) ^ ((unsigned)r & 7u)) << 2)) | ((unsigned)c & 3u));
}

// f32x2 packed math helpers
__device__ __forceinline__ u64 FMA2(u64 a, u64 b, u64 c){
    u64 d; asm("fma.rn.f32x2 %0, %1, %2, %3;" : "=l"(d) : "l"(a), "l"(b), "l"(c)); return d;
}
__device__ __forceinline__ u64 MUL2(u64 a, u64 b){
    u64 d; asm("mul.rn.f32x2 %0, %1, %2;" : "=l"(d) : "l"(a), "l"(b)); return d;
}
__device__ __forceinline__ u64 ADD2(u64 a, u64 b){
    u64 d; asm("add.rn.f32x2 %0, %1, %2;" : "=l"(d) : "l"(a), "l"(b)); return d;
}
__device__ __forceinline__ u64 PK2(float x){
    u64 d; asm("mov.b64 %0, {%1, %1};" : "=l"(d) : "f"(x)); return d;
}
__device__ __forceinline__ float HADD2(u64 d){
    float a, b; asm("mov.b64 {%0, %1}, %2;" : "=f"(a), "=f"(b) : "l"(d)); return a + b;
}

// ---------------- job descriptor for batched GEMM ----------------
struct GJob {
    const float* A; const float* B; float* C; const float* bias;
    int lda, ldb, ldc, N, K, mode; float scale; int round_out;
};

// ---------------- tf32 GEMM (mma.sync + ldmatrix): C = A * B^T, z-batched ----------------
// mode: 0 plain(+bias), 1 tanh, 2 scale*sigmoid(x+bias), 3 per-col stage1
template<int NT>
__global__ void __launch_bounds__(256,2) gemm_mma(GJob j0, GJob j1, GJob j2, GJob j3)
{
    extern __shared__ float sm[];
    const int AS  = 128*32;
    const int STG = (128+NT)*32;
    const int NTN = (NT==128) ? 8 : 4;
    const int NLD = NTN/2;

    GJob jb = j0;
    if (blockIdx.z == 1) jb = j1;
    else if (blockIdx.z == 2) jb = j2;
    else if (blockIdx.z == 3) jb = j3;

    int tid = threadIdx.x, wid = tid >> 5, lane = tid & 31;
    int bm0 = blockIdx.x * 128, bn0 = blockIdx.y * NT;
    int grp = lane >> 2, thr = lane & 3;
    int wm = (wid & 3) * 32;
    int wn = (NT==128) ? (wid >> 2) * 64 : (wid >> 2) * 32;
    int NC = jb.K >> 5;

    float acc[2][NTN][4];
    #pragma unroll
    for (int i=0;i<2;i++)
      #pragma unroll
      for (int j=0;j<NTN;j++)
        #pragma unroll
        for (int l=0;l<4;l++) acc[i][j][l]=0.f;

    uint32_t smb = (uint32_t)__cvta_generic_to_shared(sm);

    uint32_t aoff[2][4], boff[NLD][4];
    #pragma unroll
    for (int mt=0;mt<2;mt++)
      #pragma unroll
      for (int kk=0;kk<4;kk++){
        int row = wm + mt*16 + (lane & 15);
        int col = kk*8 + (lane >> 4) * 4;
        aoff[mt][kk] = 4u * (uint32_t)swz(row, col);
      }
    #pragma unroll
    for (int np=0;np<NLD;np++)
      #pragma unroll
      for (int kk=0;kk<4;kk++){
        int row = wn + np*16 + (lane & 7) + ((lane >> 4) & 1) * 8;
        int col = kk*8 + ((lane >> 3) & 1) * 4;
        boff[np][kk] = 4u * (uint32_t)(AS + swz(row, col));
      }

    auto load_stage = [&](int stg, int c){
        const float* Ag = jb.A + (size_t)bm0 * jb.lda + c*32;
        #pragma unroll
        for (int i=0;i<4;i++){
            int idx = tid + 256*i; int r = idx>>3, j = idx&7;
            unsigned dst = smb + 4u*(uint32_t)(stg*STG + swz(r, j*4));
            const float* src = Ag + (size_t)r*jb.lda + j*4;
            asm volatile("cp.async.cg.shared.global [%0], [%1], 16;"::"r"(dst),"l"(src));
        }
        const float* Bg = jb.B + (size_t)bn0 * jb.ldb + c*32;
        #pragma unroll
        for (int i=0;i<NT/32;i++){
            int idx = tid + 256*i; int r = idx>>3, j = idx&7;
            unsigned dst = smb + 4u*(uint32_t)(stg*STG + AS + swz(r, j*4));
            const float* src = Bg + (size_t)r*jb.ldb + j*4;
            asm volatile("cp.async.cg.shared.global [%0], [%1], 16;"::"r"(dst),"l"(src));
        }
    };

    load_stage(0, 0);
    asm volatile("cp.async.commit_group;");
    if (NC > 1) load_stage(1, 1);
    asm volatile("cp.async.commit_group;");

    for (int c = 0; c < NC; c++){
        asm volatile("cp.async.wait_group 1;");
        __syncthreads();
        uint32_t sb = smb + 4u*(uint32_t)((c % 3) * STG);
        #pragma unroll
        for (int kk=0; kk<4; kk++){
            uint32_t af[2][4];
            ldsm4(af[0], sb + aoff[0][kk]);
            ldsm4(af[1], sb + aoff[1][kk]);
            uint32_t bf[NLD][4];
            #pragma unroll
            for (int np=0;np<NLD;np++) ldsm4(bf[np], sb + boff[np][kk]);
            #pragma unroll
            for (int mt=0;mt<2;mt++)
                #pragma unroll
                for (int nt=0;nt<NTN;nt++)
                    mma8(acc[mt][nt], af[mt], &bf[nt>>1][(nt&1)*2]);
        }
        if (c + 2 < NC) load_stage((c+2) % 3, c+2);
        asm volatile("cp.async.commit_group;");
    }

    #pragma unroll
    for (int mt=0;mt<2;mt++){
        #pragma unroll
        for (int nt=0;nt<NTN;nt++){
            #pragma unroll
            for (int half=0; half<2; half++){
                int row = bm0 + wm + mt*16 + grp + half*8;
                int col = bn0 + wn + nt*8 + thr*2;
                float v0 = acc[mt][nt][half*2+0];
                float v1 = acc[mt][nt][half*2+1];
                if (jb.bias){ v0 += jb.bias[col]; v1 += jb.bias[col+1]; }
                if (jb.mode==1){ v0 = tanhf(v0); v1 = tanhf(v1); }
                else if (jb.mode==2){ v0 = jb.scale*sigm_(v0); v1 = jb.scale*sigm_(v1); }
                else if (jb.mode==3){
                    v0 = (col   < 64) ? tanhf(v0) : (col   < 192 ? v0 : sigm_(v0));
                    v1 = (col+1 < 64) ? tanhf(v1) : (col+1 < 192 ? v1 : sigm_(v1));
                }
                if (jb.round_out){ v0 = to_tf32(v0); v1 = to_tf32(v1); }
                float* cp = jb.C + (size_t)row*jb.ldc + col;
                cp[0] = v0; cp[1] = v1;
            }
        }
    }
}

// ---------------- fused elementwise prep: weights + token-shift mix ----------------
__device__ __forceinline__ void do_tr(const float* src, float* dst, int rows, int cols, int li){
    int r = li / cols, c = li - r * cols;
    dst[(size_t)c * rows + r] = to_tf32(src[li]);
}
__global__ __launch_bounds__(256) void elem_prep(
    const float* __restrict__ Wr, const float* __restrict__ Wk,
    const float* __restrict__ Wv, const float* __restrict__ Wo,
    const float* __restrict__ w1, const float* __restrict__ a1,
    const float* __restrict__ v1, const float* __restrict__ g1,
    const float* __restrict__ w2, const float* __restrict__ a2,
    const float* __restrict__ v2, const float* __restrict__ g2,
    const float* __restrict__ x_w, const float* __restrict__ x_a,
    const float* __restrict__ x_v, const float* __restrict__ x_g,
    const float* __restrict__ x,
    const float* __restrict__ mr, const float* __restrict__ mk, const float* __restrict__ mv,
    float* __restrict__ Sg)
{
    if (blockIdx.x >= 20096){
        // ---- token-shift mix ----
        int row = blockIdx.x - 20096;
        int t = row & (TT-1);
        int c4 = threadIdx.x;
        const float4* xv4 = (const float4*)x;
        float4 xc = xv4[(size_t)row*256 + c4];
        float4 xp = make_float4(0.f,0.f,0.f,0.f);
        if (t > 0) xp = xv4[(size_t)(row-1)*256 + c4];
        float4 dx = make_float4(xp.x-xc.x, xp.y-xc.y, xp.z-xc.z, xp.w-xc.w);
        size_t o = (size_t)row*256 + c4;
        float4 m;
        #define MIXOUT(dst, mp) \
            m = ((const float4*)mp)[c4]; \
            ((float4*)(Sg+dst))[o] = make_float4(to_tf32(xc.x+dx.x*m.x), to_tf32(xc.y+dx.y*m.y), \
                                                 to_tf32(xc.z+dx.z*m.z), to_tf32(xc.w+dx.w*m.w));
        MIXOUT(OXR, mr) MIXOUT(OXK, mk) MIXOUT(OXV, mv)
        #undef MIXOUT
        float4* xcp = (float4*)(Sg + OXC + (size_t)row*2048);
        xcp[c4]       = make_float4(to_tf32(xc.x), to_tf32(xc.y), to_tf32(xc.z), to_tf32(xc.w));
        xcp[256 + c4] = make_float4(to_tf32(dx.x), to_tf32(dx.y), to_tf32(dx.z), to_tf32(dx.w));
        return;
    }
    int idx = blockIdx.x * 256 + threadIdx.x;
    if (idx < 4194304){
        int m = idx >> 20;
        int i = idx & 1048575;
        const float* src = (m == 0) ? Wr : (m == 1) ? Wk : (m == 2) ? Wv : Wo;
        float* dst = Sg + ((m == 0) ? OWRr : (m == 1) ? OWKr : (m == 2) ? OWVr : OWOr);
        dst[i] = to_tf32(src[i]);
        return;
    }
    idx -= 4194304;
    if (idx < 655360){
        int n = idx >> 11;
        int k = idx & 2047;
        int kk = k & 1023;
        float val = 0.f;
        if (n < 64){
            float w = w1[kk*64 + n];
            val = (k < 1024) ? w : x_w[kk]*w;
        } else if (n < 128){
            float w = a1[kk*64 + (n-64)];
            val = (k < 1024) ? w : x_a[kk]*w;
        } else if (n < 160){
            float w = v1[kk*32 + (n-128)];
            val = (k < 1024) ? w : x_v[kk]*w;
        } else if (n >= 192){
            float w = g1[kk*128 + (n-192)];
            val = (k < 1024) ? w : x_g[kk]*w;
        }
        Sg[OBU + idx] = to_tf32(val);
        return;
    }
    int j = idx - 655360;
    if (j >= 294912) return;
    if      (j < 65536 )  do_tr(w2, Sg+OW2T, 64, 1024,  j);
    else if (j < 131072)  do_tr(a2, Sg+OA2T, 64, 1024,  j-65536);
    else if (j < 163840)  do_tr(v2, Sg+OV2T, 32, 1024,  j-131072);
    else                  do_tr(g2, Sg+OG2T, 128, 1024, j-163840);
}

// ---------------- H = act(Hlo + Hhi), per-col activation, tf32 round ----------------
__global__ __launch_bounds__(256) void hsum_act(
    const float* __restrict__ Hlo, const float* __restrict__ Hhi, float* __restrict__ H)
{
    int i = blockIdx.x*256 + threadIdx.x;       // quad index over 4096x320
    if (i >= 4096*80) return;
    int row = i / 80, q = i - row*80;
    int col = q*4;
    size_t off = (size_t)row*320 + col;
    float4 a = *(const float4*)&Hlo[off];
    float4 b = *(const float4*)&Hhi[off];
    float v[4] = {a.x+b.x, a.y+b.y, a.z+b.z, a.w+b.w};
    #pragma unroll
    for (int j=0;j<4;j++){
        int c = col + j;
        float xx = v[j];
        xx = (c < 64) ? tanhf(xx) : (c < 192 ? xx : sigm_(xx));
        v[j] = to_tf32(xx);
    }
    *(float4*)&H[off] = make_float4(v[0], v[1], v[2], v[3]);
}

// ---------------- scan-operand prep ----------------
__global__ __launch_bounds__(256) void prep_kernel(
    const float* __restrict__ K, const float* __restrict__ A, const float* __restrict__ V,
    const float* __restrict__ WL, const float* __restrict__ VMIX, const float* __restrict__ vfirst,
    const float* __restrict__ k_k, const float* __restrict__ k_a,
    float* __restrict__ EW, float* __restrict__ BBo, float* __restrict__ AAo,
    float* __restrict__ K2o, float* __restrict__ Vo)
{
    int gw = (blockIdx.x*256 + threadIdx.x) >> 5;
    int lane = threadIdx.x & 31;
    int h = gw & 15, t = (gw >> 4) & 1023, b = gw >> 14;
    int c = h*64 + lane*2;
    size_t btc = ((size_t)(b*TT + t))*CC + c;
    float2 k  = *(const float2*)&K[btc];
    float2 kw = *(const float2*)&k_k[c];
    float2 ka = *(const float2*)&k_a[c];
    float2 a  = *(const float2*)&A[btc];
    float kk0 = k.x*kw.x, kk1 = k.y*kw.y;
    float ss = kk0*kk0 + kk1*kk1;
    #pragma unroll
    for (int off=16; off>0; off>>=1) ss += __shfl_xor_sync(0xffffffffu, ss, off);
    float inv = 1.f / fmaxf(sqrtf(ss), 1e-12f);
    kk0 *= inv; kk1 *= inv;
    float2 wl = *(const float2*)&WL[btc];
    float2 v  = *(const float2*)&V[btc];
    float2 vf = *(const float2*)&vfirst[btc];
    float2 vm = *(const float2*)&VMIX[btc];
    v.x = v.x + (vf.x - v.x)*vm.x;
    v.y = v.y + (vf.y - v.y)*vm.y;
    float k20 = k.x*(1.f + (a.x-1.f)*ka.x);
    float k21 = k.y*(1.f + (a.y-1.f)*ka.y);
    size_t bhtd = ((size_t)((b*HH + h)*TT + t))*64 + lane*2;
    *(float2*)&EW[bhtd]  = make_float2(expf(wl.x), expf(wl.y));
    *(float2*)&BBo[bhtd] = make_float2(kk0*a.x, kk1*a.y);
    *(float2*)&AAo[bhtd] = make_float2(-kk0, -kk1);
    *(float2*)&K2o[bhtd] = make_float2(k20, k21);
    *(float2*)&Vo[bhtd]  = v;
}

// ---------------- sequential RWKV7 scan (f32x2, deferred o-reduction) ----------------
__device__ __forceinline__ float red8(float v){
    v += __shfl_xor_sync(0xffffffffu, v, 1);
    v += __shfl_xor_sync(0xffffffffu, v, 2);
    v += __shfl_xor_sync(0xffffffffu, v, 4);
    return v;
}

__global__ __launch_bounds__(256) void scan_kernel(
    const float* __restrict__ EW, const float* __restrict__ BBp, const float* __restrict__ AAp,
    const float* __restrict__ K2p, const float* __restrict__ RB, const float* __restrict__ Vp,
    float* __restrict__ O4)
{
    __shared__ float sm[16*6*64];   // 16 stages x 6 arrays x 64 = 24KB
    int bh = blockIdx.x >> 1;
    int b = bh >> 4, h = bh & 15;
    int rowBase = (blockIdx.x & 1) * 32;
    int tid = threadIdx.x;
    int row = rowBase + (tid >> 3);
    int col0 = (tid & 7) * 8;
    size_t base = (size_t)bh * TT * 64;
    size_t base4 = (size_t)bh * TT * 256;

    int arr = tid >> 4, seg = tid & 15;
    const float* mysrc = nullptr; int mystride = 64;
    if (tid < 96){
        switch (arr){
            case 0: mysrc = EW  + base; break;
            case 1: mysrc = BBp + base; break;
            case 2: mysrc = AAp + base; break;
            case 3: mysrc = K2p + base; break;
            case 4: mysrc = RB + (size_t)b*TT*CC + h*64; mystride = CC; break;
            case 5: mysrc = Vp  + base; break;
        }
    }
    uint32_t smb = (uint32_t)__cvta_generic_to_shared(sm);

    auto pf4 = [&](int batch){
        if (tid < 96){
            #pragma unroll
            for (int u=0; u<4; u++){
                int t = batch*4 + u;
                const float* g = mysrc + (size_t)t*mystride + seg*4;
                unsigned sa = smb + 4u*(uint32_t)(((t&15)*384) + arr*64 + seg*4);
                asm volatile("cp.async.ca.shared.global [%0], [%1], 16;"::"r"(sa),"l"(g));
            }
        }
        asm volatile("cp.async.commit_group;");
    };

    pf4(0); pf4(1); pf4(2);

    u64 S2[4];
    #pragma unroll
    for (int i=0;i<4;i++) S2[i] = 0ull;

    for (int i=0; i<256; i++){
        asm volatile("cp.async.wait_group 2;");
        __syncthreads();
        if (i+3 < 256) pf4(i+3);
        else asm volatile("cp.async.commit_group;");
        int tb = i*4;

        #pragma unroll
        for (int u=0; u<4; u++){
            const float* st = &sm[((tb+u) & 15) * 384];
            u64 ew2[4], bb2[4], aa2[4], kk2[4], rr2[4];
            #define LD2(dst, off) { \
                ulonglong2 q0 = *(const ulonglong2*)&st[(off)+col0]; \
                ulonglong2 q1 = *(const ulonglong2*)&st[(off)+col0+4]; \
                dst[0]=q0.x; dst[1]=q0.y; dst[2]=q1.x; dst[3]=q1.y; }
            LD2(ew2,   0) LD2(bb2,  64) LD2(aa2, 128) LD2(kk2, 192) LD2(rr2, 256)
            #undef LD2
            float vv = st[320 + row];

            u64 d0 = MUL2(S2[0], ew2[0]);
            u64 d1 = MUL2(S2[1], ew2[1]);
            u64 d2 = MUL2(S2[2], ew2[2]);
            u64 d3 = MUL2(S2[3], ew2[3]);

            u64 q0 = MUL2(S2[0], aa2[0]);
            u64 q1 = MUL2(S2[1], aa2[1]);
            q0 = FMA2(S2[2], aa2[2], q0);
            q1 = FMA2(S2[3], aa2[3], q1);
            float sab = red8(HADD2(ADD2(q0, q1)));

            u64 sab2 = PK2(sab), vv2 = PK2(vv);
            S2[0] = FMA2(kk2[0], vv2, FMA2(bb2[0], sab2, d0));
            S2[1] = FMA2(kk2[1], vv2, FMA2(bb2[1], sab2, d1));
            S2[2] = FMA2(kk2[2], vv2, FMA2(bb2[2], sab2, d2));
            S2[3] = FMA2(kk2[3], vv2, FMA2(bb2[3], sab2, d3));

            // deferred output reduction: 1 shfl, write 4 partials per row
            u64 o0 = MUL2(S2[0], rr2[0]);
            u64 o1 = MUL2(S2[1], rr2[1]);
            o0 = FMA2(S2[2], rr2[2], o0);
            o1 = FMA2(S2[3], rr2[3], o1);
            float po = HADD2(ADD2(o0, o1));
            po += __shfl_xor_sync(0xffffffffu, po, 1);
            if ((tid & 1) == 0)
                O4[base4 + (size_t)(tb+u)*256 + (size_t)row*4 + ((tid&7)>>1)] = po;
        }
    }
}

// ---------------- post: sum partials + groupnorm + bonus + gate ----------------
__global__ __launch_bounds__(256) void post_kernel(
    const float* __restrict__ O4, const float* __restrict__ RB, const float* __restrict__ K2p,
    const float* __restrict__ Vp, const float* __restrict__ G,
    const float* __restrict__ r_k, const float* __restrict__ gn_w, const float* __restrict__ gn_b,
    float* __restrict__ Z)
{
    int gw = (blockIdx.x*256 + threadIdx.x) >> 5;
    int lane = threadIdx.x & 31;
    int h = gw & 15, t = (gw >> 4) & 1023, b = gw >> 14;
    size_t bhtd = ((size_t)((b*HH + h)*TT + t))*64 + lane*2;
    int c = h*64 + lane*2;
    size_t btc = ((size_t)(b*TT + t))*CC + c;

    size_t b4 = ((size_t)(b*HH + h))*TT*256 + (size_t)t*256 + (size_t)lane*8;
    float4 pa = *(const float4*)&O4[b4];
    float4 pb = *(const float4*)&O4[b4 + 4];
    float2 o = make_float2(pa.x+pa.y+pa.z+pa.w, pb.x+pb.y+pb.z+pb.w);

    float sm = o.x + o.y;
    #pragma unroll
    for (int off=16; off>0; off>>=1) sm += __shfl_xor_sync(0xffffffffu, sm, off);
    float mean = sm * (1.f/64.f);
    float dx = o.x - mean, dy = o.y - mean;
    float vs = dx*dx + dy*dy;
    #pragma unroll
    for (int off=16; off>0; off>>=1) vs += __shfl_xor_sync(0xffffffffu, vs, off);
    float inv = rsqrtf(vs*(1.f/64.f) + GN_EPS);

    float2 r  = *(const float2*)&RB[btc];
    float2 k2 = *(const float2*)&K2p[bhtd];
    float2 v  = *(const float2*)&Vp[bhtd];
    float2 rk = *(const float2*)&r_k[c];
    float bs = r.x*k2.x*rk.x + r.y*k2.y*rk.y;
    #pragma unroll
    for (int off=16; off>0; off>>=1) bs += __shfl_xor_sync(0xffffffffu, bs, off);

    float2 g  = *(const float2*)&G[btc];
    float2 w  = *(const float2*)&gn_w[c];
    float2 bb = *(const float2*)&gn_b[c];
    float z0 = ((dx*inv)*w.x + bb.x + bs*v.x) * g.x;
    float z1 = ((dy*inv)*w.y + bb.y + bs*v.y) * g.y;
    *(float2*)&Z[btc] = make_float2(to_tf32(z0), to_tf32(z1));
}

// ---------------- driver ----------------
static inline GJob mkjob(const float* A, int lda, const float* B, int ldb, float* C, int ldc,
                         int N, int K, const float* bias, int mode, float scale, int ro){
    GJob j; j.A=A; j.B=B; j.C=C; j.bias=bias; j.lda=lda; j.ldb=ldb; j.ldc=ldc;
    j.N=N; j.K=K; j.mode=mode; j.scale=scale; j.round_out=ro; return j;
}

extern "C" void kernel_launch(void* const* d_in, const int* in_sizes, int n_in,
                              void* d_out, int out_size) {
    const float* x   = (const float*)d_in[0];
    const float* vfi = (const float*)d_in[1];
    const float* x_r = (const float*)d_in[2];
    const float* x_w = (const float*)d_in[3];
    const float* x_k = (const float*)d_in[4];
    const float* x_v = (const float*)d_in[5];
    const float* x_a = (const float*)d_in[6];
    const float* x_g = (const float*)d_in[7];
    const float* Wr  = (const float*)d_in[8];
    const float* Wk  = (const float*)d_in[9];
    const float* Wv  = (const float*)d_in[10];
    const float* Wo  = (const float*)d_in[11];
    const float* w0  = (const float*)d_in[12];
    const float* w1  = (const float*)d_in[13];
    const float* w2  = (const float*)d_in[14];
    const float* a0  = (const float*)d_in[15];
    const float* a1  = (const float*)d_in[16];
    const float* a2  = (const float*)d_in[17];
    const float* v0  = (const float*)d_in[18];
    const float* v1  = (const float*)d_in[19];
    const float* v2  = (const float*)d_in[20];
    const float* g1  = (const float*)d_in[21];
    const float* g2  = (const float*)d_in[22];
    const float* k_k = (const float*)d_in[23];
    const float* k_a = (const float*)d_in[24];
    const float* r_k = (const float*)d_in[25];
    const float* gnw = (const float*)d_in[26];
    const float* gnb = (const float*)d_in[27];
    float* out = (float*)d_out;

    float* S;
    cudaGetSymbolAddress((void**)&S, gScratch);

    const int SM128 = 3*(128+128)*32*4;   // 98304
    const int SM64  = 3*(128+64)*32*4;    // 73728
    cudaFuncSetAttribute(gemm_mma<128>, cudaFuncAttributeMaxDynamicSharedMemorySize, SM128);
    cudaFuncSetAttribute(gemm_mma<64>,  cudaFuncAttributeMaxDynamicSharedMemorySize, SM64);

    const int M = BB*TT;
    float* H = S + OHST;   // 4096 x 320

    // 0: fused elementwise prep (weights + mixes)
    elem_prep<<<24192, 256>>>(Wr, Wk, Wv, Wo, w1, a1, v1, g1, w2, a2, v2, g2,
                              x_w, x_a, x_v, x_g, x, x_r, x_k, x_v, S);
    // 1: stage-1 split-K halves: Hlo = x@BUlo^T, Hhi = xx@BUhi^T
    {
        GJob jlo = mkjob(S+OXC,      2048, S+OBU,      2048, S+OHLO, 320, 320, 1024, nullptr, 0, 1.f, 0);
        GJob jhi = mkjob(S+OXC+1024, 2048, S+OBU+1024, 2048, S+OHHI, 320, 320, 1024, nullptr, 0, 1.f, 0);
        gemm_mma<64><<<dim3(M/128,5,2), 256, SM64>>>(jlo, jhi, jlo, jlo);
    }
    // 2: H = act(Hlo + Hhi)
    hsum_act<<<1280, 256>>>(S+OHLO, S+OHHI, H);
    // 3: stage-2 low-rank outputs, z-batched (WL, a, vmix, g)  <-- profiled (idx 3)
    {
        GJob jw = mkjob(H+0,   320, S+OW2T, 64,  S+OWL,  1024, 1024, 64,  w0, 2, LOG_DECAY, 0);
        GJob ja = mkjob(H+64,  320, S+OA2T, 64,  S+OAB,  1024, 1024, 64,  a0, 2, 1.f, 0);
        GJob jv = mkjob(H+128, 320, S+OV2T, 32,  S+OVMX, 1024, 1024, 32,  v0, 2, 1.f, 0);
        GJob jg = mkjob(H+192, 320, S+OG2T, 128, S+OGB,  1024, 1024, 128, nullptr, 0, 1.f, 0);
        gemm_mma<128><<<dim3(M/128,8,4), 256, SM128>>>(jw, ja, jv, jg);
    }
    // 4: R/K/V projections, z-batched
    {
        GJob jr = mkjob(S+OXR, 1024, S+OWRr, 1024, S+ORB, 1024, 1024, 1024, nullptr, 0, 1.f, 0);
        GJob jk = mkjob(S+OXK, 1024, S+OWKr, 1024, S+OKB, 1024, 1024, 1024, nullptr, 0, 1.f, 0);
        GJob jv = mkjob(S+OXV, 1024, S+OWVr, 1024, S+OVB, 1024, 1024, 1024, nullptr, 0, 1.f, 0);
        gemm_mma<128><<<dim3(M/128,8,3), 256, SM128>>>(jr, jk, jv, jr);
    }
    // 5: scan operand prep
    prep_kernel<<<(BB*TT*HH*32)/256, 256>>>(S+OKB, S+OAB, S+OVB, S+OWL, S+OVMX, vfi,
                                            k_k, k_a,
                                            S+OEW, S+OBBA, S+OAAA, S+OKK2, S+OVVA);
    // 6: sequential scan (r read directly from ORB; partials to O4)
    scan_kernel<<<BB*HH*2, 256>>>(S+OEW, S+OBBA, S+OAAA, S+OKK2, S+ORB, S+OVVA, S+OO4);
    // 7: sum partials + groupnorm + bonus + gate
    post_kernel<<<(BB*TT*HH*32)/256, 256>>>(S+OO4, S+ORB, S+OKK2, S+OVVA, S+OGB,
                                            r_k, gnw, gnb, S+OZB);
    // 8: out = Z @ Wo^T
    {
        GJob jo = mkjob(S+OZB, 1024, S+OWOr, 1024, out, 1024, 1024, 1024, nullptr, 0, 1.f, 0);
        gemm_mma<128><<<dim3(M/128,8,1), 256, SM128>>>(jo, jo, jo, jo);
    }
    // v_first passthrough
    if (out_size >= 2*NE){
        cudaMemcpyAsync(out + NE, vfi, (size_t)NE*sizeof(float), cudaMemcpyDeviceToDevice);
    }
}

// round 9
// speedup vs baseline: 2.2076x; 1.0989x over previous
#include <cuda_runtime.h>
#include <math.h>
#include <stdint.h>

#define BB 4
#define TT 1024
#define CC 1024
#define HH 16
#define DD 64
#define NE 4194304     // B*T*C
#define LOG_DECAY (-0.6065306597126334f)
#define GN_EPS 64e-5f

typedef unsigned long long u64;

// ---------------- static scratch ----------------
__device__ float gScratch[104857600];

#define OO4  ((size_t)0)               // scan partials: 64bh x 1024t x 256 = 4*NE (slots 0-3)
#define OXR  ((size_t)0*NE)            // mix outputs (dead before scan)
#define OXK  ((size_t)2*NE)
#define OXV  ((size_t)3*NE)
#define OXC  ((size_t)4*NE)            // [x | xx] 4096 x 2048 (slots 4-5)
#define ORB  ((size_t)6*NE)
#define OKB  ((size_t)7*NE)
#define OVB  ((size_t)8*NE)
#define OAB  ((size_t)9*NE)
#define OGB  ((size_t)10*NE)
#define OWL  ((size_t)11*NE)
#define OVMX ((size_t)12*NE)
#define OHST ((size_t)13*NE)           // stage-1 H: 4096 x 320
#define OHLO ((size_t)14*NE)           // stage-1 half products
#define OHHI ((size_t)15*NE)
#define OEW  ((size_t)16*NE)
#define OBBA ((size_t)17*NE)
#define OAAA ((size_t)18*NE)
#define OKK2 ((size_t)19*NE)
#define OVVA ((size_t)20*NE)
#define OZB  ((size_t)21*NE)
#define OW2T ((size_t)22*NE)
#define OA2T (OW2T + 65536)
#define OV2T (OA2T + 65536)
#define OG2T (OV2T + 32768)
#define OWRr (OG2T + 131072)
#define OWKr (OWRr + 1048576)
#define OWVr (OWKr + 1048576)
#define OWOr (OWVr + 1048576)
#define OBU  (OWOr + 1048576)          // stacked stage-1 weights: 320 x 2048

__device__ __forceinline__ float to_tf32(float x){
    uint32_t u; asm("cvt.rna.tf32.f32 %0, %1;" : "=r"(u) : "f"(x));
    return __uint_as_float(u);
}
__device__ __forceinline__ float sigm_(float x){ return 1.f/(1.f+expf(-x)); }

__device__ __forceinline__ void mma8(float* d, const uint32_t* a, const uint32_t* b){
    asm volatile("mma.sync.aligned.m16n8k8.row.col.f32.tf32.tf32.f32 "
        "{%0,%1,%2,%3}, {%4,%5,%6,%7}, {%8,%9}, {%0,%1,%2,%3};"
        : "+f"(d[0]), "+f"(d[1]), "+f"(d[2]), "+f"(d[3])
        : "r"(a[0]), "r"(a[1]), "r"(a[2]), "r"(a[3]), "r"(b[0]), "r"(b[1]));
}
__device__ __forceinline__ void ldsm4(uint32_t* r, uint32_t a){
    asm volatile("ldmatrix.sync.aligned.m8n8.x4.shared.b16 {%0,%1,%2,%3}, [%4];"
        : "=r"(r[0]),"=r"(r[1]),"=r"(r[2]),"=r"(r[3]) : "r"(a));
}
__device__ __forceinline__ int swz(int r, int c){
    return r*32 + (int)((((((unsigned)c>>2) ^ ((unsigned)r & 7u)) << 2)) | ((unsigned)c & 3u));
}

// f32x2 packed math helpers
__device__ __forceinline__ u64 FMA2(u64 a, u64 b, u64 c){
    u64 d; asm("fma.rn.f32x2 %0, %1, %2, %3;" : "=l"(d) : "l"(a), "l"(b), "l"(c)); return d;
}
__device__ __forceinline__ u64 MUL2(u64 a, u64 b){
    u64 d; asm("mul.rn.f32x2 %0, %1, %2;" : "=l"(d) : "l"(a), "l"(b)); return d;
}
__device__ __forceinline__ u64 ADD2(u64 a, u64 b){
    u64 d; asm("add.rn.f32x2 %0, %1, %2;" : "=l"(d) : "l"(a), "l"(b)); return d;
}
__device__ __forceinline__ u64 PK2(float x){
    u64 d; asm("mov.b64 %0, {%1, %1};" : "=l"(d) : "f"(x)); return d;
}
__device__ __forceinline__ float HADD2(u64 d){
    float a, b; asm("mov.b64 {%0, %1}, %2;" : "=f"(a), "=f"(b) : "l"(d)); return a + b;
}

// ---------------- job descriptor for batched GEMM ----------------
struct GJob {
    const float* A; const float* B; float* C; const float* bias;
    int lda, ldb, ldc, N, K, mode; float scale; int round_out; int nrep;
};

// ---------------- tf32 GEMM (mma.sync + ldmatrix): C = A * B^T, z-batched, n-rep ----------------
// mode: 0 plain(+bias), 1 tanh, 2 scale*sigmoid(x+bias), 3 per-col stage1
template<int NT>
__global__ void __launch_bounds__(256,2) gemm_mma(GJob j0, GJob j1, GJob j2, GJob j3)
{
    extern __shared__ float sm[];
    const int AS  = 128*32;
    const int STG = (128+NT)*32;
    const int NTN = (NT==128) ? 8 : 4;
    const int NLD = NTN/2;

    GJob jb = j0;
    if (blockIdx.z == 1) jb = j1;
    else if (blockIdx.z == 2) jb = j2;
    else if (blockIdx.z == 3) jb = j3;

    int tid = threadIdx.x, wid = tid >> 5, lane = tid & 31;
    int bm0 = blockIdx.x * 128;
    int grp = lane >> 2, thr = lane & 3;
    int wm = (wid & 3) * 32;
    int wn = (NT==128) ? (wid >> 2) * 64 : (wid >> 2) * 32;
    int NC = jb.K >> 5;

    uint32_t smb = (uint32_t)__cvta_generic_to_shared(sm);

    uint32_t aoff[2][4], boff[NLD][4];
    #pragma unroll
    for (int mt=0;mt<2;mt++)
      #pragma unroll
      for (int kk=0;kk<4;kk++){
        int row = wm + mt*16 + (lane & 15);
        int col = kk*8 + (lane >> 4) * 4;
        aoff[mt][kk] = 4u * (uint32_t)swz(row, col);
      }
    #pragma unroll
    for (int np=0;np<NLD;np++)
      #pragma unroll
      for (int kk=0;kk<4;kk++){
        int row = wn + np*16 + (lane & 7) + ((lane >> 4) & 1) * 8;
        int col = kk*8 + ((lane >> 3) & 1) * 4;
        boff[np][kk] = 4u * (uint32_t)(AS + swz(row, col));
      }

    int bn0 = 0;
    auto load_stage = [&](int stg, int c){
        const float* Ag = jb.A + (size_t)bm0 * jb.lda + c*32;
        #pragma unroll
        for (int i=0;i<4;i++){
            int idx = tid + 256*i; int r = idx>>3, j = idx&7;
            unsigned dst = smb + 4u*(uint32_t)(stg*STG + swz(r, j*4));
            const float* src = Ag + (size_t)r*jb.lda + j*4;
            asm volatile("cp.async.cg.shared.global [%0], [%1], 16;"::"r"(dst),"l"(src));
        }
        const float* Bg = jb.B + (size_t)bn0 * jb.ldb + c*32;
        #pragma unroll
        for (int i=0;i<NT/32;i++){
            int idx = tid + 256*i; int r = idx>>3, j = idx&7;
            unsigned dst = smb + 4u*(uint32_t)(stg*STG + AS + swz(r, j*4));
            const float* src = Bg + (size_t)r*jb.ldb + j*4;
            asm volatile("cp.async.cg.shared.global [%0], [%1], 16;"::"r"(dst),"l"(src));
        }
    };

    for (int rep = 0; rep < jb.nrep; rep++){
        bn0 = (blockIdx.y * jb.nrep + rep) * NT;
        if (rep > 0) __syncthreads();   // protect smem reuse across reps

        float acc[2][NTN][4];
        #pragma unroll
        for (int i=0;i<2;i++)
          #pragma unroll
          for (int j=0;j<NTN;j++)
            #pragma unroll
            for (int l=0;l<4;l++) acc[i][j][l]=0.f;

        load_stage(0, 0);
        asm volatile("cp.async.commit_group;");
        if (NC > 1) load_stage(1, 1);
        asm volatile("cp.async.commit_group;");

        for (int c = 0; c < NC; c++){
            asm volatile("cp.async.wait_group 1;");
            __syncthreads();
            uint32_t sb = smb + 4u*(uint32_t)((c % 3) * STG);
            #pragma unroll
            for (int kk=0; kk<4; kk++){
                uint32_t af[2][4];
                ldsm4(af[0], sb + aoff[0][kk]);
                ldsm4(af[1], sb + aoff[1][kk]);
                uint32_t bf[NLD][4];
                #pragma unroll
                for (int np=0;np<NLD;np++) ldsm4(bf[np], sb + boff[np][kk]);
                #pragma unroll
                for (int mt=0;mt<2;mt++)
                    #pragma unroll
                    for (int nt=0;nt<NTN;nt++)
                        mma8(acc[mt][nt], af[mt], &bf[nt>>1][(nt&1)*2]);
            }
            if (c + 2 < NC) load_stage((c+2) % 3, c+2);
            asm volatile("cp.async.commit_group;");
        }

        #pragma unroll
        for (int mt=0;mt<2;mt++){
            #pragma unroll
            for (int nt=0;nt<NTN;nt++){
                #pragma unroll
                for (int half=0; half<2; half++){
                    int row = bm0 + wm + mt*16 + grp + half*8;
                    int col = bn0 + wn + nt*8 + thr*2;
                    float v0 = acc[mt][nt][half*2+0];
                    float v1 = acc[mt][nt][half*2+1];
                    if (jb.bias){ v0 += jb.bias[col]; v1 += jb.bias[col+1]; }
                    if (jb.mode==1){ v0 = tanhf(v0); v1 = tanhf(v1); }
                    else if (jb.mode==2){ v0 = jb.scale*sigm_(v0); v1 = jb.scale*sigm_(v1); }
                    else if (jb.mode==3){
                        v0 = (col   < 64) ? tanhf(v0) : (col   < 192 ? v0 : sigm_(v0));
                        v1 = (col+1 < 64) ? tanhf(v1) : (col+1 < 192 ? v1 : sigm_(v1));
                    }
                    if (jb.round_out){ v0 = to_tf32(v0); v1 = to_tf32(v1); }
                    float* cp = jb.C + (size_t)row*jb.ldc + col;
                    cp[0] = v0; cp[1] = v1;
                }
            }
        }
    }
}

// ---------------- fused elementwise prep: weights + token-shift mix ----------------
__device__ __forceinline__ void do_tr(const float* src, float* dst, int rows, int cols, int li){
    int r = li / cols, c = li - r * cols;
    dst[(size_t)c * rows + r] = to_tf32(src[li]);
}
__global__ __launch_bounds__(256) void elem_prep(
    const float* __restrict__ Wr, const float* __restrict__ Wk,
    const float* __restrict__ Wv, const float* __restrict__ Wo,
    const float* __restrict__ w1, const float* __restrict__ a1,
    const float* __restrict__ v1, const float* __restrict__ g1,
    const float* __restrict__ w2, const float* __restrict__ a2,
    const float* __restrict__ v2, const float* __restrict__ g2,
    const float* __restrict__ x_w, const float* __restrict__ x_a,
    const float* __restrict__ x_v, const float* __restrict__ x_g,
    const float* __restrict__ x,
    const float* __restrict__ mr, const float* __restrict__ mk, const float* __restrict__ mv,
    float* __restrict__ Sg)
{
    if (blockIdx.x >= 20096){
        int row = blockIdx.x - 20096;
        int t = row & (TT-1);
        int c4 = threadIdx.x;
        const float4* xv4 = (const float4*)x;
        float4 xc = xv4[(size_t)row*256 + c4];
        float4 xp = make_float4(0.f,0.f,0.f,0.f);
        if (t > 0) xp = xv4[(size_t)(row-1)*256 + c4];
        float4 dx = make_float4(xp.x-xc.x, xp.y-xc.y, xp.z-xc.z, xp.w-xc.w);
        size_t o = (size_t)row*256 + c4;
        float4 m;
        #define MIXOUT(dst, mp) \
            m = ((const float4*)mp)[c4]; \
            ((float4*)(Sg+dst))[o] = make_float4(to_tf32(xc.x+dx.x*m.x), to_tf32(xc.y+dx.y*m.y), \
                                                 to_tf32(xc.z+dx.z*m.z), to_tf32(xc.w+dx.w*m.w));
        MIXOUT(OXR, mr) MIXOUT(OXK, mk) MIXOUT(OXV, mv)
        #undef MIXOUT
        float4* xcp = (float4*)(Sg + OXC + (size_t)row*2048);
        xcp[c4]       = make_float4(to_tf32(xc.x), to_tf32(xc.y), to_tf32(xc.z), to_tf32(xc.w));
        xcp[256 + c4] = make_float4(to_tf32(dx.x), to_tf32(dx.y), to_tf32(dx.z), to_tf32(dx.w));
        return;
    }
    int idx = blockIdx.x * 256 + threadIdx.x;
    if (idx < 4194304){
        int m = idx >> 20;
        int i = idx & 1048575;
        const float* src = (m == 0) ? Wr : (m == 1) ? Wk : (m == 2) ? Wv : Wo;
        float* dst = Sg + ((m == 0) ? OWRr : (m == 1) ? OWKr : (m == 2) ? OWVr : OWOr);
        dst[i] = to_tf32(src[i]);
        return;
    }
    idx -= 4194304;
    if (idx < 655360){
        int n = idx >> 11;
        int k = idx & 2047;
        int kk = k & 1023;
        float val = 0.f;
        if (n < 64){
            float w = w1[kk*64 + n];
            val = (k < 1024) ? w : x_w[kk]*w;
        } else if (n < 128){
            float w = a1[kk*64 + (n-64)];
            val = (k < 1024) ? w : x_a[kk]*w;
        } else if (n < 160){
            float w = v1[kk*32 + (n-128)];
            val = (k < 1024) ? w : x_v[kk]*w;
        } else if (n >= 192){
            float w = g1[kk*128 + (n-192)];
            val = (k < 1024) ? w : x_g[kk]*w;
        }
        Sg[OBU + idx] = to_tf32(val);
        return;
    }
    int j = idx - 655360;
    if (j >= 294912) return;
    if      (j < 65536 )  do_tr(w2, Sg+OW2T, 64, 1024,  j);
    else if (j < 131072)  do_tr(a2, Sg+OA2T, 64, 1024,  j-65536);
    else if (j < 163840)  do_tr(v2, Sg+OV2T, 32, 1024,  j-131072);
    else                  do_tr(g2, Sg+OG2T, 128, 1024, j-163840);
}

// ---------------- H = act(Hlo + Hhi) ----------------
__global__ __launch_bounds__(256) void hsum_act(
    const float* __restrict__ Hlo, const float* __restrict__ Hhi, float* __restrict__ H)
{
    int i = blockIdx.x*256 + threadIdx.x;
    if (i >= 4096*80) return;
    int row = i / 80, q = i - row*80;
    int col = q*4;
    size_t off = (size_t)row*320 + col;
    float4 a = *(const float4*)&Hlo[off];
    float4 b = *(const float4*)&Hhi[off];
    float v[4] = {a.x+b.x, a.y+b.y, a.z+b.z, a.w+b.w};
    #pragma unroll
    for (int j=0;j<4;j++){
        int c = col + j;
        float xx = v[j];
        xx = (c < 64) ? tanhf(xx) : (c < 192 ? xx : sigm_(xx));
        v[j] = to_tf32(xx);
    }
    *(float4*)&H[off] = make_float4(v[0], v[1], v[2], v[3]);
}

// ---------------- scan-operand prep ----------------
__global__ __launch_bounds__(256) void prep_kernel(
    const float* __restrict__ K, const float* __restrict__ A, const float* __restrict__ V,
    const float* __restrict__ WL, const float* __restrict__ VMIX, const float* __restrict__ vfirst,
    const float* __restrict__ k_k, const float* __restrict__ k_a,
    float* __restrict__ EW, float* __restrict__ BBo, float* __restrict__ AAo,
    float* __restrict__ K2o, float* __restrict__ Vo)
{
    int gw = (blockIdx.x*256 + threadIdx.x) >> 5;
    int lane = threadIdx.x & 31;
    int h = gw & 15, t = (gw >> 4) & 1023, b = gw >> 14;
    int c = h*64 + lane*2;
    size_t btc = ((size_t)(b*TT + t))*CC + c;
    float2 k  = *(const float2*)&K[btc];
    float2 kw = *(const float2*)&k_k[c];
    float2 ka = *(const float2*)&k_a[c];
    float2 a  = *(const float2*)&A[btc];
    float kk0 = k.x*kw.x, kk1 = k.y*kw.y;
    float ss = kk0*kk0 + kk1*kk1;
    #pragma unroll
    for (int off=16; off>0; off>>=1) ss += __shfl_xor_sync(0xffffffffu, ss, off);
    float inv = 1.f / fmaxf(sqrtf(ss), 1e-12f);
    kk0 *= inv; kk1 *= inv;
    float2 wl = *(const float2*)&WL[btc];
    float2 v  = *(const float2*)&V[btc];
    float2 vf = *(const float2*)&vfirst[btc];
    float2 vm = *(const float2*)&VMIX[btc];
    v.x = v.x + (vf.x - v.x)*vm.x;
    v.y = v.y + (vf.y - v.y)*vm.y;
    float k20 = k.x*(1.f + (a.x-1.f)*ka.x);
    float k21 = k.y*(1.f + (a.y-1.f)*ka.y);
    size_t bhtd = ((size_t)((b*HH + h)*TT + t))*64 + lane*2;
    *(float2*)&EW[bhtd]  = make_float2(expf(wl.x), expf(wl.y));
    *(float2*)&BBo[bhtd] = make_float2(kk0*a.x, kk1*a.y);
    *(float2*)&AAo[bhtd] = make_float2(-kk0, -kk1);
    *(float2*)&K2o[bhtd] = make_float2(k20, k21);
    *(float2*)&Vo[bhtd]  = v;
}

// ---------------- sequential RWKV7 scan v2: 64 thr/CTA, 4 rows/thread ----------------
__global__ void __launch_bounds__(64) scan_kernel(
    const float* __restrict__ EW, const float* __restrict__ BBp, const float* __restrict__ AAp,
    const float* __restrict__ K2p, const float* __restrict__ RB, const float* __restrict__ Vp,
    float* __restrict__ O4)
{
    __shared__ float sm[16*6*64];   // 16 stages x 384 floats = 24KB
    int bh = blockIdx.x >> 1;
    int b = bh >> 4, h = bh & 15;
    int rowBase = (blockIdx.x & 1) * 32;
    int tid = threadIdx.x;          // 0..63
    int cg = tid & 7;               // column group (8 cols)
    int rg = tid >> 3;              // row subgroup (0..7)
    int col0 = cg * 8;
    size_t base = (size_t)bh * TT * 64;
    size_t base4 = (size_t)bh * TT * 256;

    // prefetch task assignment: task id -> (arr, seg). 96 tasks, thread does tid and tid+64(if tid<32)
    const float* src1; int str1 = 64;
    {
        int arr = tid >> 4;  // 0..3
        src1 = (arr==0) ? EW+base : (arr==1) ? BBp+base : (arr==2) ? AAp+base : K2p+base;
    }
    const float* src2 = nullptr; int str2 = 64;
    if (tid < 32){
        int arr = 4 + (tid >> 4);   // 4 or 5
        if (arr == 4){ src2 = RB + (size_t)b*TT*CC + h*64; str2 = CC; }
        else         { src2 = Vp + base; str2 = 64; }
    }
    int seg = tid & 15;
    int arr1 = tid >> 4;
    int arr2 = 4 + (tid >> 4);
    uint32_t smb = (uint32_t)__cvta_generic_to_shared(sm);

    auto pf4 = [&](int batch){
        #pragma unroll
        for (int u=0; u<4; u++){
            int t = batch*4 + u;
            {
                const float* g = src1 + (size_t)t*str1 + seg*4;
                unsigned sa = smb + 4u*(uint32_t)(((t&15)*384) + arr1*64 + seg*4);
                asm volatile("cp.async.ca.shared.global [%0], [%1], 16;"::"r"(sa),"l"(g));
            }
            if (tid < 32){
                const float* g = src2 + (size_t)t*str2 + seg*4;
                unsigned sa = smb + 4u*(uint32_t)(((t&15)*384) + arr2*64 + seg*4);
                asm volatile("cp.async.ca.shared.global [%0], [%1], 16;"::"r"(sa),"l"(g));
            }
        }
        asm volatile("cp.async.commit_group;");
    };

    pf4(0); pf4(1); pf4(2);

    u64 S2[4][4];    // [row j][col u64]
    #pragma unroll
    for (int j=0;j<4;j++)
        #pragma unroll
        for (int i=0;i<4;i++) S2[j][i] = 0ull;

    for (int i=0; i<256; i++){
        asm volatile("cp.async.wait_group 2;");
        __syncthreads();
        if (i+3 < 256) pf4(i+3);
        else asm volatile("cp.async.commit_group;");
        int tb = i*4;

        #pragma unroll
        for (int u=0; u<4; u++){
            const float* st = &sm[((tb+u) & 15) * 384];
            u64 ew2[4], bb2[4], aa2[4], kk2[4], rr2[4];
            #define LD2(dst, off) { \
                ulonglong2 q0 = *(const ulonglong2*)&st[(off)+col0]; \
                ulonglong2 q1 = *(const ulonglong2*)&st[(off)+col0+4]; \
                dst[0]=q0.x; dst[1]=q0.y; dst[2]=q1.x; dst[3]=q1.y; }
            LD2(ew2,   0) LD2(bb2,  64) LD2(aa2, 128) LD2(kk2, 192) LD2(rr2, 256)
            #undef LD2
            float vv[4];
            #pragma unroll
            for (int j=0;j<4;j++) vv[j] = st[320 + rowBase + rg + 8*j];

            // sab partials for the 4 rows (parallel chains)
            float sab[4];
            #pragma unroll
            for (int j=0;j<4;j++){
                u64 q0 = MUL2(S2[j][0], aa2[0]);
                u64 q1 = MUL2(S2[j][1], aa2[1]);
                q0 = FMA2(S2[j][2], aa2[2], q0);
                q1 = FMA2(S2[j][3], aa2[3], q1);
                sab[j] = HADD2(ADD2(q0, q1));
            }
            // reduce across the 8 column-threads (lanes with same rg are contiguous: cg = low 3 bits)
            #pragma unroll
            for (int j=0;j<4;j++){
                sab[j] += __shfl_xor_sync(0xffffffffu, sab[j], 1);
                sab[j] += __shfl_xor_sync(0xffffffffu, sab[j], 2);
                sab[j] += __shfl_xor_sync(0xffffffffu, sab[j], 4);
            }

            float po[4];
            #pragma unroll
            for (int j=0;j<4;j++){
                u64 sab2 = PK2(sab[j]), vv2 = PK2(vv[j]);
                S2[j][0] = FMA2(kk2[0], vv2, FMA2(bb2[0], sab2, MUL2(S2[j][0], ew2[0])));
                S2[j][1] = FMA2(kk2[1], vv2, FMA2(bb2[1], sab2, MUL2(S2[j][1], ew2[1])));
                S2[j][2] = FMA2(kk2[2], vv2, FMA2(bb2[2], sab2, MUL2(S2[j][2], ew2[2])));
                S2[j][3] = FMA2(kk2[3], vv2, FMA2(bb2[3], sab2, MUL2(S2[j][3], ew2[3])));
                u64 o0 = MUL2(S2[j][0], rr2[0]);
                u64 o1 = MUL2(S2[j][1], rr2[1]);
                o0 = FMA2(S2[j][2], rr2[2], o0);
                o1 = FMA2(S2[j][3], rr2[3], o1);
                po[j] = HADD2(ADD2(o0, o1));
                po[j] += __shfl_xor_sync(0xffffffffu, po[j], 1);
            }
            if ((tid & 1) == 0){
                size_t ob = base4 + (size_t)(tb+u)*256;
                int p = cg >> 1;
                #pragma unroll
                for (int j=0;j<4;j++)
                    O4[ob + (size_t)(rowBase + rg + 8*j)*4 + p] = po[j];
            }
        }
    }
}

// ---------------- post: sum partials + groupnorm + bonus + gate ----------------
__global__ __launch_bounds__(256) void post_kernel(
    const float* __restrict__ O4, const float* __restrict__ RB, const float* __restrict__ K2p,
    const float* __restrict__ Vp, const float* __restrict__ G,
    const float* __restrict__ r_k, const float* __restrict__ gn_w, const float* __restrict__ gn_b,
    float* __restrict__ Z)
{
    int gw = (blockIdx.x*256 + threadIdx.x) >> 5;
    int lane = threadIdx.x & 31;
    int h = gw & 15, t = (gw >> 4) & 1023, b = gw >> 14;
    size_t bhtd = ((size_t)((b*HH + h)*TT + t))*64 + lane*2;
    int c = h*64 + lane*2;
    size_t btc = ((size_t)(b*TT + t))*CC + c;

    size_t b4 = ((size_t)(b*HH + h))*TT*256 + (size_t)t*256 + (size_t)lane*8;
    float4 pa = *(const float4*)&O4[b4];
    float4 pb = *(const float4*)&O4[b4 + 4];
    float2 o = make_float2(pa.x+pa.y+pa.z+pa.w, pb.x+pb.y+pb.z+pb.w);

    float sm = o.x + o.y;
    #pragma unroll
    for (int off=16; off>0; off>>=1) sm += __shfl_xor_sync(0xffffffffu, sm, off);
    float mean = sm * (1.f/64.f);
    float dx = o.x - mean, dy = o.y - mean;
    float vs = dx*dx + dy*dy;
    #pragma unroll
    for (int off=16; off>0; off>>=1) vs += __shfl_xor_sync(0xffffffffu, vs, off);
    float inv = rsqrtf(vs*(1.f/64.f) + GN_EPS);

    float2 r  = *(const float2*)&RB[btc];
    float2 k2 = *(const float2*)&K2p[bhtd];
    float2 v  = *(const float2*)&Vp[bhtd];
    float2 rk = *(const float2*)&r_k[c];
    float bs = r.x*k2.x*rk.x + r.y*k2.y*rk.y;
    #pragma unroll
    for (int off=16; off>0; off>>=1) bs += __shfl_xor_sync(0xffffffffu, bs, off);

    float2 g  = *(const float2*)&G[btc];
    float2 w  = *(const float2*)&gn_w[c];
    float2 bb = *(const float2*)&gn_b[c];
    float z0 = ((dx*inv)*w.x + bb.x + bs*v.x) * g.x;
    float z1 = ((dy*inv)*w.y + bb.y + bs*v.y) * g.y;
    *(float2*)&Z[btc] = make_float2(to_tf32(z0), to_tf32(z1));
}

// ---------------- driver ----------------
static inline GJob mkjob(const float* A, int lda, const float* B, int ldb, float* C, int ldc,
                         int N, int K, const float* bias, int mode, float scale, int ro, int nrep=1){
    GJob j; j.A=A; j.B=B; j.C=C; j.bias=bias; j.lda=lda; j.ldb=ldb; j.ldc=ldc;
    j.N=N; j.K=K; j.mode=mode; j.scale=scale; j.round_out=ro; j.nrep=nrep; return j;
}

extern "C" void kernel_launch(void* const* d_in, const int* in_sizes, int n_in,
                              void* d_out, int out_size) {
    const float* x   = (const float*)d_in[0];
    const float* vfi = (const float*)d_in[1];
    const float* x_r = (const float*)d_in[2];
    const float* x_w = (const float*)d_in[3];
    const float* x_k = (const float*)d_in[4];
    const float* x_v = (const float*)d_in[5];
    const float* x_a = (const float*)d_in[6];
    const float* x_g = (const float*)d_in[7];
    const float* Wr  = (const float*)d_in[8];
    const float* Wk  = (const float*)d_in[9];
    const float* Wv  = (const float*)d_in[10];
    const float* Wo  = (const float*)d_in[11];
    const float* w0  = (const float*)d_in[12];
    const float* w1  = (const float*)d_in[13];
    const float* w2  = (const float*)d_in[14];
    const float* a0  = (const float*)d_in[15];
    const float* a1  = (const float*)d_in[16];
    const float* a2  = (const float*)d_in[17];
    const float* v0  = (const float*)d_in[18];
    const float* v1  = (const float*)d_in[19];
    const float* v2  = (const float*)d_in[20];
    const float* g1  = (const float*)d_in[21];
    const float* g2  = (const float*)d_in[22];
    const float* k_k = (const float*)d_in[23];
    const float* k_a = (const float*)d_in[24];
    const float* r_k = (const float*)d_in[25];
    const float* gnw = (const float*)d_in[26];
    const float* gnb = (const float*)d_in[27];
    float* out = (float*)d_out;

    float* S;
    cudaGetSymbolAddress((void**)&S, gScratch);

    const int SM128 = 3*(128+128)*32*4;   // 98304
    const int SM64  = 3*(128+64)*32*4;    // 73728
    cudaFuncSetAttribute(gemm_mma<128>, cudaFuncAttributeMaxDynamicSharedMemorySize, SM128);
    cudaFuncSetAttribute(gemm_mma<64>,  cudaFuncAttributeMaxDynamicSharedMemorySize, SM64);

    const int M = BB*TT;
    float* H = S + OHST;

    // 0: fused elementwise prep (weights + mixes)
    elem_prep<<<24192, 256>>>(Wr, Wk, Wv, Wo, w1, a1, v1, g1, w2, a2, v2, g2,
                              x_w, x_a, x_v, x_g, x, x_r, x_k, x_v, S);
    // 1: stage-1 split-K halves
    {
        GJob jlo = mkjob(S+OXC,      2048, S+OBU,      2048, S+OHLO, 320, 320, 1024, nullptr, 0, 1.f, 0);
        GJob jhi = mkjob(S+OXC+1024, 2048, S+OBU+1024, 2048, S+OHHI, 320, 320, 1024, nullptr, 0, 1.f, 0);
        gemm_mma<64><<<dim3(M/128,5,2), 256, SM64>>>(jlo, jhi, jlo, jlo);
    }
    // 2: H = act(Hlo + Hhi)
    hsum_act<<<1280, 256>>>(S+OHLO, S+OHHI, H);
    // 3: stage-2 low-rank outputs, z-batched + n-rep=4 (grid 256)  <-- profiled (idx 3)
    {
        GJob jw = mkjob(H+0,   320, S+OW2T, 64,  S+OWL,  1024, 1024, 64,  w0, 2, LOG_DECAY, 0, 4);
        GJob ja = mkjob(H+64,  320, S+OA2T, 64,  S+OAB,  1024, 1024, 64,  a0, 2, 1.f, 0, 4);
        GJob jv = mkjob(H+128, 320, S+OV2T, 32,  S+OVMX, 1024, 1024, 32,  v0, 2, 1.f, 0, 4);
        GJob jg = mkjob(H+192, 320, S+OG2T, 128, S+OGB,  1024, 1024, 128, nullptr, 0, 1.f, 0, 4);
        gemm_mma<128><<<dim3(M/128,2,4), 256, SM128>>>(jw, ja, jv, jg);
    }
    // 4: R/K/V projections, z-batched
    {
        GJob jr = mkjob(S+OXR, 1024, S+OWRr, 1024, S+ORB, 1024, 1024, 1024, nullptr, 0, 1.f, 0);
        GJob jk = mkjob(S+OXK, 1024, S+OWKr, 1024, S+OKB, 1024, 1024, 1024, nullptr, 0, 1.f, 0);
        GJob jv = mkjob(S+OXV, 1024, S+OWVr, 1024, S+OVB, 1024, 1024, 1024, nullptr, 0, 1.f, 0);
        gemm_mma<128><<<dim3(M/128,8,3), 256, SM128>>>(jr, jk, jv, jr);
    }
    // 5: scan operand prep
    prep_kernel<<<(BB*TT*HH*32)/256, 256>>>(S+OKB, S+OAB, S+OVB, S+OWL, S+OVMX, vfi,
                                            k_k, k_a,
                                            S+OEW, S+OBBA, S+OAAA, S+OKK2, S+OVVA);
    // 6: sequential scan v2 (64 threads, 4 rows/thread)
    scan_kernel<<<BB*HH*2, 64>>>(S+OEW, S+OBBA, S+OAAA, S+OKK2, S+ORB, S+OVVA, S+OO4);
    // 7: sum partials + groupnorm + bonus + gate
    post_kernel<<<(BB*TT*HH*32)/256, 256>>>(S+OO4, S+ORB, S+OKK2, S+OVVA, S+OGB,
                                            r_k, gnw, gnb, S+OZB);
    // 8: out = Z @ Wo^T
    {
        GJob jo = mkjob(S+OZB, 1024, S+OWOr, 1024, out, 1024, 1024, 1024, nullptr, 0, 1.f, 0);
        gemm_mma<128><<<dim3(M/128,8,1), 256, SM128>>>(jo, jo, jo, jo);
    }
    // v_first passthrough
    if (out_size >= 2*NE){
        cudaMemcpyAsync(out + NE, vfi, (size_t)NE*sizeof(float), cudaMemcpyDeviceToDevice);
    }
}

// round 10
// speedup vs baseline: 2.3369x; 1.0586x over previous
#include <cuda_runtime.h>
#include <math.h>
#include <stdint.h>

#define BB 4
#define TT 1024
#define CC 1024
#define HH 16
#define DD 64
#define NE 4194304     // B*T*C
#define LOG_DECAY (-0.6065306597126334f)
#define GN_EPS 64e-5f

typedef unsigned long long u64;

// ---------------- static scratch ----------------
__device__ float gScratch[104857600];

#define OO4  ((size_t)0)               // scan partials (slots 0-3)
#define OXR  ((size_t)0*NE)
#define OXK  ((size_t)2*NE)
#define OXV  ((size_t)3*NE)
#define OXC  ((size_t)4*NE)            // [x | xx] (slots 4-5)
#define ORB  ((size_t)6*NE)
#define OKB  ((size_t)7*NE)
#define OVB  ((size_t)8*NE)
#define OAB  ((size_t)9*NE)
#define OGB  ((size_t)10*NE)
#define OWL  ((size_t)11*NE)
#define OVMX ((size_t)12*NE)
#define OHST ((size_t)13*NE)
#define OHLO ((size_t)14*NE)
#define OHHI ((size_t)15*NE)
#define OEW  ((size_t)16*NE)
#define OBBA ((size_t)17*NE)
#define OAAA ((size_t)18*NE)
#define OKK2 ((size_t)19*NE)
#define OVVA ((size_t)20*NE)
#define OZB  ((size_t)21*NE)
#define OW2T ((size_t)22*NE)
#define OA2T (OW2T + 65536)
#define OV2T (OA2T + 65536)
#define OG2T (OV2T + 32768)
#define OWRr (OG2T + 131072)
#define OWKr (OWRr + 1048576)
#define OWVr (OWKr + 1048576)
#define OWOr (OWVr + 1048576)
#define OBU  (OWOr + 1048576)

__device__ __forceinline__ float to_tf32(float x){
    uint32_t u; asm("cvt.rna.tf32.f32 %0, %1;" : "=r"(u) : "f"(x));
    return __uint_as_float(u);
}
__device__ __forceinline__ float sigm_(float x){ return 1.f/(1.f+expf(-x)); }

__device__ __forceinline__ void mma8(float* d, const uint32_t* a, const uint32_t* b){
    asm volatile("mma.sync.aligned.m16n8k8.row.col.f32.tf32.tf32.f32 "
        "{%0,%1,%2,%3}, {%4,%5,%6,%7}, {%8,%9}, {%0,%1,%2,%3};"
        : "+f"(d[0]), "+f"(d[1]), "+f"(d[2]), "+f"(d[3])
        : "r"(a[0]), "r"(a[1]), "r"(a[2]), "r"(a[3]), "r"(b[0]), "r"(b[1]));
}
__device__ __forceinline__ void ldsm4(uint32_t* r, uint32_t a){
    asm volatile("ldmatrix.sync.aligned.m8n8.x4.shared.b16 {%0,%1,%2,%3}, [%4];"
        : "=r"(r[0]),"=r"(r[1]),"=r"(r[2]),"=r"(r[3]) : "r"(a));
}
__device__ __forceinline__ int swz(int r, int c){
    return r*32 + (int)((((((unsigned)c>>2) ^ ((unsigned)r & 7u)) << 2)) | ((unsigned)c & 3u));
}

// f32x2 packed math helpers
__device__ __forceinline__ u64 FMA2(u64 a, u64 b, u64 c){
    u64 d; asm("fma.rn.f32x2 %0, %1, %2, %3;" : "=l"(d) : "l"(a), "l"(b), "l"(c)); return d;
}
__device__ __forceinline__ u64 MUL2(u64 a, u64 b){
    u64 d; asm("mul.rn.f32x2 %0, %1, %2;" : "=l"(d) : "l"(a), "l"(b)); return d;
}
__device__ __forceinline__ u64 ADD2(u64 a, u64 b){
    u64 d; asm("add.rn.f32x2 %0, %1, %2;" : "=l"(d) : "l"(a), "l"(b)); return d;
}
__device__ __forceinline__ u64 PK2(float x){
    u64 d; asm("mov.b64 %0, {%1, %1};" : "=l"(d) : "f"(x)); return d;
}
__device__ __forceinline__ float HADD2(u64 d){
    float a, b; asm("mov.b64 {%0, %1}, %2;" : "=f"(a), "=f"(b) : "l"(d)); return a + b;
}

// ---------------- job descriptor for batched GEMM ----------------
struct GJob {
    const float* A; const float* B; float* C; const float* bias;
    int lda, ldb, ldc, N, K, mode; float scale; int round_out; int nrep;
};

// ---------------- tf32 GEMM: C = A * B^T, z-batched, flattened pipelined n-rep ----------------
template<int NT>
__global__ void __launch_bounds__(256,2) gemm_mma(GJob j0, GJob j1, GJob j2, GJob j3)
{
    extern __shared__ float sm[];
    const int AS  = 128*32;
    const int STG = (128+NT)*32;
    const int NTN = (NT==128) ? 8 : 4;
    const int NLD = NTN/2;

    GJob jb = j0;
    if (blockIdx.z == 1) jb = j1;
    else if (blockIdx.z == 2) jb = j2;
    else if (blockIdx.z == 3) jb = j3;

    int tid = threadIdx.x, wid = tid >> 5, lane = tid & 31;
    int bm0 = blockIdx.x * 128;
    int grp = lane >> 2, thr = lane & 3;
    int wm = (wid & 3) * 32;
    int wn = (NT==128) ? (wid >> 2) * 64 : (wid >> 2) * 32;
    int NC = jb.K >> 5;
    int total = jb.nrep * NC;

    uint32_t smb = (uint32_t)__cvta_generic_to_shared(sm);

    uint32_t aoff[2][4], boff[NLD][4];
    #pragma unroll
    for (int mt=0;mt<2;mt++)
      #pragma unroll
      for (int kk=0;kk<4;kk++){
        int row = wm + mt*16 + (lane & 15);
        int col = kk*8 + (lane >> 4) * 4;
        aoff[mt][kk] = 4u * (uint32_t)swz(row, col);
      }
    #pragma unroll
    for (int np=0;np<NLD;np++)
      #pragma unroll
      for (int kk=0;kk<4;kk++){
        int row = wn + np*16 + (lane & 7) + ((lane >> 4) & 1) * 8;
        int col = kk*8 + ((lane >> 3) & 1) * 4;
        boff[np][kk] = 4u * (uint32_t)(AS + swz(row, col));
      }

    auto load_stage = [&](int stg, int tc){
        int rep = tc / NC;
        int c = tc - rep*NC;
        int bn = (blockIdx.y * jb.nrep + rep) * NT;
        const float* Ag = jb.A + (size_t)bm0 * jb.lda + c*32;
        #pragma unroll
        for (int i=0;i<4;i++){
            int idx = tid + 256*i; int r = idx>>3, j = idx&7;
            unsigned dst = smb + 4u*(uint32_t)(stg*STG + swz(r, j*4));
            const float* src = Ag + (size_t)r*jb.lda + j*4;
            asm volatile("cp.async.cg.shared.global [%0], [%1], 16;"::"r"(dst),"l"(src));
        }
        const float* Bg = jb.B + (size_t)bn * jb.ldb + c*32;
        #pragma unroll
        for (int i=0;i<NT/32;i++){
            int idx = tid + 256*i; int r = idx>>3, j = idx&7;
            unsigned dst = smb + 4u*(uint32_t)(stg*STG + AS + swz(r, j*4));
            const float* src = Bg + (size_t)r*jb.ldb + j*4;
            asm volatile("cp.async.cg.shared.global [%0], [%1], 16;"::"r"(dst),"l"(src));
        }
    };

    float acc[2][NTN][4];
    #pragma unroll
    for (int i=0;i<2;i++)
      #pragma unroll
      for (int j=0;j<NTN;j++)
        #pragma unroll
        for (int l=0;l<4;l++) acc[i][j][l]=0.f;

    load_stage(0, 0);
    asm volatile("cp.async.commit_group;");
    if (total > 1) load_stage(1, 1);
    asm volatile("cp.async.commit_group;");

    int cc = 0;   // chunk within rep
    for (int tc = 0; tc < total; tc++){
        asm volatile("cp.async.wait_group 1;");
        __syncthreads();
        uint32_t sb = smb + 4u*(uint32_t)((tc % 3) * STG);
        #pragma unroll
        for (int kk=0; kk<4; kk++){
            uint32_t af[2][4];
            ldsm4(af[0], sb + aoff[0][kk]);
            ldsm4(af[1], sb + aoff[1][kk]);
            uint32_t bf[NLD][4];
            #pragma unroll
            for (int np=0;np<NLD;np++) ldsm4(bf[np], sb + boff[np][kk]);
            #pragma unroll
            for (int mt=0;mt<2;mt++)
                #pragma unroll
                for (int nt=0;nt<NTN;nt++)
                    mma8(acc[mt][nt], af[mt], &bf[nt>>1][(nt&1)*2]);
        }
        if (tc + 2 < total) load_stage((tc+2) % 3, tc+2);
        asm volatile("cp.async.commit_group;");

        if (++cc == NC){
            cc = 0;
            int rep = tc / NC;
            int bn0 = (blockIdx.y * jb.nrep + rep) * NT;
            #pragma unroll
            for (int mt=0;mt<2;mt++){
                #pragma unroll
                for (int nt=0;nt<NTN;nt++){
                    #pragma unroll
                    for (int half=0; half<2; half++){
                        int row = bm0 + wm + mt*16 + grp + half*8;
                        int col = bn0 + wn + nt*8 + thr*2;
                        float v0 = acc[mt][nt][half*2+0];
                        float v1 = acc[mt][nt][half*2+1];
                        if (jb.bias){ v0 += jb.bias[col]; v1 += jb.bias[col+1]; }
                        if (jb.mode==1){ v0 = tanhf(v0); v1 = tanhf(v1); }
                        else if (jb.mode==2){ v0 = jb.scale*sigm_(v0); v1 = jb.scale*sigm_(v1); }
                        else if (jb.mode==3){
                            v0 = (col   < 64) ? tanhf(v0) : (col   < 192 ? v0 : sigm_(v0));
                            v1 = (col+1 < 64) ? tanhf(v1) : (col+1 < 192 ? v1 : sigm_(v1));
                        }
                        if (jb.round_out){ v0 = to_tf32(v0); v1 = to_tf32(v1); }
                        float* cp = jb.C + (size_t)row*jb.ldc + col;
                        cp[0] = v0; cp[1] = v1;
                        acc[mt][nt][half*2+0] = 0.f;
                        acc[mt][nt][half*2+1] = 0.f;
                    }
                }
            }
        }
    }
}

// ---------------- fused elementwise prep: weights + token-shift mix ----------------
__device__ __forceinline__ void do_tr(const float* src, float* dst, int rows, int cols, int li){
    int r = li / cols, c = li - r * cols;
    dst[(size_t)c * rows + r] = to_tf32(src[li]);
}
__global__ __launch_bounds__(256) void elem_prep(
    const float* __restrict__ Wr, const float* __restrict__ Wk,
    const float* __restrict__ Wv, const float* __restrict__ Wo,
    const float* __restrict__ w1, const float* __restrict__ a1,
    const float* __restrict__ v1, const float* __restrict__ g1,
    const float* __restrict__ w2, const float* __restrict__ a2,
    const float* __restrict__ v2, const float* __restrict__ g2,
    const float* __restrict__ x_w, const float* __restrict__ x_a,
    const float* __restrict__ x_v, const float* __restrict__ x_g,
    const float* __restrict__ x,
    const float* __restrict__ mr, const float* __restrict__ mk, const float* __restrict__ mv,
    float* __restrict__ Sg)
{
    if (blockIdx.x >= 20096){
        int row = blockIdx.x - 20096;
        int t = row & (TT-1);
        int c4 = threadIdx.x;
        const float4* xv4 = (const float4*)x;
        float4 xc = xv4[(size_t)row*256 + c4];
        float4 xp = make_float4(0.f,0.f,0.f,0.f);
        if (t > 0) xp = xv4[(size_t)(row-1)*256 + c4];
        float4 dx = make_float4(xp.x-xc.x, xp.y-xc.y, xp.z-xc.z, xp.w-xc.w);
        size_t o = (size_t)row*256 + c4;
        float4 m;
        #define MIXOUT(dst, mp) \
            m = ((const float4*)mp)[c4]; \
            ((float4*)(Sg+dst))[o] = make_float4(to_tf32(xc.x+dx.x*m.x), to_tf32(xc.y+dx.y*m.y), \
                                                 to_tf32(xc.z+dx.z*m.z), to_tf32(xc.w+dx.w*m.w));
        MIXOUT(OXR, mr) MIXOUT(OXK, mk) MIXOUT(OXV, mv)
        #undef MIXOUT
        float4* xcp = (float4*)(Sg + OXC + (size_t)row*2048);
        xcp[c4]       = make_float4(to_tf32(xc.x), to_tf32(xc.y), to_tf32(xc.z), to_tf32(xc.w));
        xcp[256 + c4] = make_float4(to_tf32(dx.x), to_tf32(dx.y), to_tf32(dx.z), to_tf32(dx.w));
        return;
    }
    int idx = blockIdx.x * 256 + threadIdx.x;
    if (idx < 4194304){
        int m = idx >> 20;
        int i = idx & 1048575;
        const float* src = (m == 0) ? Wr : (m == 1) ? Wk : (m == 2) ? Wv : Wo;
        float* dst = Sg + ((m == 0) ? OWRr : (m == 1) ? OWKr : (m == 2) ? OWVr : OWOr);
        dst[i] = to_tf32(src[i]);
        return;
    }
    idx -= 4194304;
    if (idx < 655360){
        int n = idx >> 11;
        int k = idx & 2047;
        int kk = k & 1023;
        float val = 0.f;
        if (n < 64){
            float w = w1[kk*64 + n];
            val = (k < 1024) ? w : x_w[kk]*w;
        } else if (n < 128){
            float w = a1[kk*64 + (n-64)];
            val = (k < 1024) ? w : x_a[kk]*w;
        } else if (n < 160){
            float w = v1[kk*32 + (n-128)];
            val = (k < 1024) ? w : x_v[kk]*w;
        } else if (n >= 192){
            float w = g1[kk*128 + (n-192)];
            val = (k < 1024) ? w : x_g[kk]*w;
        }
        Sg[OBU + idx] = to_tf32(val);
        return;
    }
    int j = idx - 655360;
    if (j >= 294912) return;
    if      (j < 65536 )  do_tr(w2, Sg+OW2T, 64, 1024,  j);
    else if (j < 131072)  do_tr(a2, Sg+OA2T, 64, 1024,  j-65536);
    else if (j < 163840)  do_tr(v2, Sg+OV2T, 32, 1024,  j-131072);
    else                  do_tr(g2, Sg+OG2T, 128, 1024, j-163840);
}

// ---------------- H = act(Hlo + Hhi) ----------------
__global__ __launch_bounds__(256) void hsum_act(
    const float* __restrict__ Hlo, const float* __restrict__ Hhi, float* __restrict__ H)
{
    int i = blockIdx.x*256 + threadIdx.x;
    if (i >= 4096*80) return;
    int row = i / 80, q = i - row*80;
    int col = q*4;
    size_t off = (size_t)row*320 + col;
    float4 a = *(const float4*)&Hlo[off];
    float4 b = *(const float4*)&Hhi[off];
    float v[4] = {a.x+b.x, a.y+b.y, a.z+b.z, a.w+b.w};
    #pragma unroll
    for (int j=0;j<4;j++){
        int c = col + j;
        float xx = v[j];
        xx = (c < 64) ? tanhf(xx) : (c < 192 ? xx : sigm_(xx));
        v[j] = to_tf32(xx);
    }
    *(float4*)&H[off] = make_float4(v[0], v[1], v[2], v[3]);
}

// ---------------- scan-operand prep ----------------
__global__ __launch_bounds__(256) void prep_kernel(
    const float* __restrict__ K, const float* __restrict__ A, const float* __restrict__ V,
    const float* __restrict__ WL, const float* __restrict__ VMIX, const float* __restrict__ vfirst,
    const float* __restrict__ k_k, const float* __restrict__ k_a,
    float* __restrict__ EW, float* __restrict__ BBo, float* __restrict__ AAo,
    float* __restrict__ K2o, float* __restrict__ Vo)
{
    int gw = (blockIdx.x*256 + threadIdx.x) >> 5;
    int lane = threadIdx.x & 31;
    int h = gw & 15, t = (gw >> 4) & 1023, b = gw >> 14;
    int c = h*64 + lane*2;
    size_t btc = ((size_t)(b*TT + t))*CC + c;
    float2 k  = *(const float2*)&K[btc];
    float2 kw = *(const float2*)&k_k[c];
    float2 ka = *(const float2*)&k_a[c];
    float2 a  = *(const float2*)&A[btc];
    float kk0 = k.x*kw.x, kk1 = k.y*kw.y;
    float ss = kk0*kk0 + kk1*kk1;
    #pragma unroll
    for (int off=16; off>0; off>>=1) ss += __shfl_xor_sync(0xffffffffu, ss, off);
    float inv = 1.f / fmaxf(sqrtf(ss), 1e-12f);
    kk0 *= inv; kk1 *= inv;
    float2 wl = *(const float2*)&WL[btc];
    float2 v  = *(const float2*)&V[btc];
    float2 vf = *(const float2*)&vfirst[btc];
    float2 vm = *(const float2*)&VMIX[btc];
    v.x = v.x + (vf.x - v.x)*vm.x;
    v.y = v.y + (vf.y - v.y)*vm.y;
    float k20 = k.x*(1.f + (a.x-1.f)*ka.x);
    float k21 = k.y*(1.f + (a.y-1.f)*ka.y);
    size_t bhtd = ((size_t)((b*HH + h)*TT + t))*64 + lane*2;
    *(float2*)&EW[bhtd]  = make_float2(expf(wl.x), expf(wl.y));
    *(float2*)&BBo[bhtd] = make_float2(kk0*a.x, kk1*a.y);
    *(float2*)&AAo[bhtd] = make_float2(-kk0, -kk1);
    *(float2*)&K2o[bhtd] = make_float2(k20, k21);
    *(float2*)&Vo[bhtd]  = v;
}

// ---------------- scan v3: 128 thr/CTA (4 warps), 4 rows x 4 cols per thread ----------------
__global__ void __launch_bounds__(128) scan_kernel(
    const float* __restrict__ EW, const float* __restrict__ BBp, const float* __restrict__ AAp,
    const float* __restrict__ K2p, const float* __restrict__ RB, const float* __restrict__ Vp,
    float* __restrict__ O4)
{
    __shared__ float sm[16*6*64];   // 16 stages x 384 floats = 24KB
    int bh = blockIdx.x >> 1;
    int b = bh >> 4, h = bh & 15;
    int rowBase = (blockIdx.x & 1) * 32;
    int tid = threadIdx.x;          // 0..127
    int cg = tid & 15;              // column group (4 cols)
    int rg = tid >> 4;              // row subgroup (0..7)
    int col0 = cg * 4;
    size_t base = (size_t)bh * TT * 64;
    size_t base4 = (size_t)bh * TT * 256;

    // prefetch: 96 tasks (6 arrays x 16 segs of 16B)
    const float* mysrc = nullptr; int mystride = 64;
    int arr = tid >> 4, seg = tid & 15;
    if (tid < 96){
        switch (arr){
            case 0: mysrc = EW  + base; break;
            case 1: mysrc = BBp + base; break;
            case 2: mysrc = AAp + base; break;
            case 3: mysrc = K2p + base; break;
            case 4: mysrc = RB + (size_t)b*TT*CC + h*64; mystride = CC; break;
            case 5: mysrc = Vp  + base; break;
        }
    }
    uint32_t smb = (uint32_t)__cvta_generic_to_shared(sm);

    auto pf4 = [&](int batch){
        if (tid < 96){
            #pragma unroll
            for (int u=0; u<4; u++){
                int t = batch*4 + u;
                const float* g = mysrc + (size_t)t*mystride + seg*4;
                unsigned sa = smb + 4u*(uint32_t)(((t&15)*384) + arr*64 + seg*4);
                asm volatile("cp.async.ca.shared.global [%0], [%1], 16;"::"r"(sa),"l"(g));
            }
        }
        asm volatile("cp.async.commit_group;");
    };

    pf4(0); pf4(1); pf4(2);

    u64 S2[4][2];    // [row j][col u64 pair]
    #pragma unroll
    for (int j=0;j<4;j++){ S2[j][0]=0ull; S2[j][1]=0ull; }

    for (int i=0; i<256; i++){
        asm volatile("cp.async.wait_group 2;");
        __syncthreads();
        if (i+3 < 256) pf4(i+3);
        else asm volatile("cp.async.commit_group;");
        int tb = i*4;

        #pragma unroll
        for (int u=0; u<4; u++){
            const float* st = &sm[((tb+u) & 15) * 384];
            u64 ew2[2], bb2[2], aa2[2], kk2[2], rr2[2];
            #define LD2(dst, off) { \
                ulonglong2 q = *(const ulonglong2*)&st[(off)+col0]; \
                dst[0]=q.x; dst[1]=q.y; }
            LD2(ew2,   0) LD2(bb2,  64) LD2(aa2, 128) LD2(kk2, 192) LD2(rr2, 256)
            #undef LD2
            float vv[4];
            #pragma unroll
            for (int j=0;j<4;j++) vv[j] = st[320 + rowBase + rg + 8*j];

            // sab partials (4 parallel row chains)
            float sab[4];
            #pragma unroll
            for (int j=0;j<4;j++){
                u64 q = MUL2(S2[j][0], aa2[0]);
                q = FMA2(S2[j][1], aa2[1], q);
                sab[j] = HADD2(q);
            }
            // reduce over 16 column-threads (cg = low 4 bits of lane)
            #pragma unroll
            for (int j=0;j<4;j++){
                sab[j] += __shfl_xor_sync(0xffffffffu, sab[j], 1);
                sab[j] += __shfl_xor_sync(0xffffffffu, sab[j], 2);
                sab[j] += __shfl_xor_sync(0xffffffffu, sab[j], 4);
                sab[j] += __shfl_xor_sync(0xffffffffu, sab[j], 8);
            }

            float po[4];
            #pragma unroll
            for (int j=0;j<4;j++){
                u64 sab2 = PK2(sab[j]), vv2 = PK2(vv[j]);
                S2[j][0] = FMA2(kk2[0], vv2, FMA2(bb2[0], sab2, MUL2(S2[j][0], ew2[0])));
                S2[j][1] = FMA2(kk2[1], vv2, FMA2(bb2[1], sab2, MUL2(S2[j][1], ew2[1])));
                u64 o = MUL2(S2[j][0], rr2[0]);
                o = FMA2(S2[j][1], rr2[1], o);
                po[j] = HADD2(o);
                po[j] += __shfl_xor_sync(0xffffffffu, po[j], 1);
                po[j] += __shfl_xor_sync(0xffffffffu, po[j], 2);
            }
            if ((tid & 3) == 0){
                size_t ob = base4 + (size_t)(tb+u)*256;
                int p = cg >> 2;   // 0..3
                #pragma unroll
                for (int j=0;j<4;j++)
                    O4[ob + (size_t)(rowBase + rg + 8*j)*4 + p] = po[j];
            }
        }
    }
}

// ---------------- post: sum partials + groupnorm + bonus + gate ----------------
__global__ __launch_bounds__(256) void post_kernel(
    const float* __restrict__ O4, const float* __restrict__ RB, const float* __restrict__ K2p,
    const float* __restrict__ Vp, const float* __restrict__ G,
    const float* __restrict__ r_k, const float* __restrict__ gn_w, const float* __restrict__ gn_b,
    float* __restrict__ Z)
{
    int gw = (blockIdx.x*256 + threadIdx.x) >> 5;
    int lane = threadIdx.x & 31;
    int h = gw & 15, t = (gw >> 4) & 1023, b = gw >> 14;
    size_t bhtd = ((size_t)((b*HH + h)*TT + t))*64 + lane*2;
    int c = h*64 + lane*2;
    size_t btc = ((size_t)(b*TT + t))*CC + c;

    size_t b4 = ((size_t)(b*HH + h))*TT*256 + (size_t)t*256 + (size_t)lane*8;
    float4 pa = *(const float4*)&O4[b4];
    float4 pb = *(const float4*)&O4[b4 + 4];
    float2 o = make_float2(pa.x+pa.y+pa.z+pa.w, pb.x+pb.y+pb.z+pb.w);

    float sm = o.x + o.y;
    #pragma unroll
    for (int off=16; off>0; off>>=1) sm += __shfl_xor_sync(0xffffffffu, sm, off);
    float mean = sm * (1.f/64.f);
    float dx = o.x - mean, dy = o.y - mean;
    float vs = dx*dx + dy*dy;
    #pragma unroll
    for (int off=16; off>0; off>>=1) vs += __shfl_xor_sync(0xffffffffu, vs, off);
    float inv = rsqrtf(vs*(1.f/64.f) + GN_EPS);

    float2 r  = *(const float2*)&RB[btc];
    float2 k2 = *(const float2*)&K2p[bhtd];
    float2 v  = *(const float2*)&Vp[bhtd];
    float2 rk = *(const float2*)&r_k[c];
    float bs = r.x*k2.x*rk.x + r.y*k2.y*rk.y;
    #pragma unroll
    for (int off=16; off>0; off>>=1) bs += __shfl_xor_sync(0xffffffffu, bs, off);

    float2 g  = *(const float2*)&G[btc];
    float2 w  = *(const float2*)&gn_w[c];
    float2 bb = *(const float2*)&gn_b[c];
    float z0 = ((dx*inv)*w.x + bb.x + bs*v.x) * g.x;
    float z1 = ((dy*inv)*w.y + bb.y + bs*v.y) * g.y;
    *(float2*)&Z[btc] = make_float2(to_tf32(z0), to_tf32(z1));
}

// ---------------- driver ----------------
static inline GJob mkjob(const float* A, int lda, const float* B, int ldb, float* C, int ldc,
                         int N, int K, const float* bias, int mode, float scale, int ro, int nrep=1){
    GJob j; j.A=A; j.B=B; j.C=C; j.bias=bias; j.lda=lda; j.ldb=ldb; j.ldc=ldc;
    j.N=N; j.K=K; j.mode=mode; j.scale=scale; j.round_out=ro; j.nrep=nrep; return j;
}

extern "C" void kernel_launch(void* const* d_in, const int* in_sizes, int n_in,
                              void* d_out, int out_size) {
    const float* x   = (const float*)d_in[0];
    const float* vfi = (const float*)d_in[1];
    const float* x_r = (const float*)d_in[2];
    const float* x_w = (const float*)d_in[3];
    const float* x_k = (const float*)d_in[4];
    const float* x_v = (const float*)d_in[5];
    const float* x_a = (const float*)d_in[6];
    const float* x_g = (const float*)d_in[7];
    const float* Wr  = (const float*)d_in[8];
    const float* Wk  = (const float*)d_in[9];
    const float* Wv  = (const float*)d_in[10];
    const float* Wo  = (const float*)d_in[11];
    const float* w0  = (const float*)d_in[12];
    const float* w1  = (const float*)d_in[13];
    const float* w2  = (const float*)d_in[14];
    const float* a0  = (const float*)d_in[15];
    const float* a1  = (const float*)d_in[16];
    const float* a2  = (const float*)d_in[17];
    const float* v0  = (const float*)d_in[18];
    const float* v1  = (const float*)d_in[19];
    const float* v2  = (const float*)d_in[20];
    const float* g1  = (const float*)d_in[21];
    const float* g2  = (const float*)d_in[22];
    const float* k_k = (const float*)d_in[23];
    const float* k_a = (const float*)d_in[24];
    const float* r_k = (const float*)d_in[25];
    const float* gnw = (const float*)d_in[26];
    const float* gnb = (const float*)d_in[27];
    float* out = (float*)d_out;

    float* S;
    cudaGetSymbolAddress((void**)&S, gScratch);

    const int SM128 = 3*(128+128)*32*4;   // 98304
    const int SM64  = 3*(128+64)*32*4;    // 73728
    cudaFuncSetAttribute(gemm_mma<128>, cudaFuncAttributeMaxDynamicSharedMemorySize, SM128);
    cudaFuncSetAttribute(gemm_mma<64>,  cudaFuncAttributeMaxDynamicSharedMemorySize, SM64);

    const int M = BB*TT;
    float* H = S + OHST;

    // 0: fused elementwise prep
    elem_prep<<<24192, 256>>>(Wr, Wk, Wv, Wo, w1, a1, v1, g1, w2, a2, v2, g2,
                              x_w, x_a, x_v, x_g, x, x_r, x_k, x_v, S);
    // 1: stage-1 split-K halves
    {
        GJob jlo = mkjob(S+OXC,      2048, S+OBU,      2048, S+OHLO, 320, 320, 1024, nullptr, 0, 1.f, 0);
        GJob jhi = mkjob(S+OXC+1024, 2048, S+OBU+1024, 2048, S+OHHI, 320, 320, 1024, nullptr, 0, 1.f, 0);
        gemm_mma<64><<<dim3(M/128,5,2), 256, SM64>>>(jlo, jhi, jlo, jlo);
    }
    // 2: H = act(Hlo + Hhi)
    hsum_act<<<1280, 256>>>(S+OHLO, S+OHHI, H);
    // 3: stage-2 low-rank outputs, z-batched, pipelined n-rep=4  <-- profiled (idx 3)
    {
        GJob jw = mkjob(H+0,   320, S+OW2T, 64,  S+OWL,  1024, 1024, 64,  w0, 2, LOG_DECAY, 0, 4);
        GJob ja = mkjob(H+64,  320, S+OA2T, 64,  S+OAB,  1024, 1024, 64,  a0, 2, 1.f, 0, 4);
        GJob jv = mkjob(H+128, 320, S+OV2T, 32,  S+OVMX, 1024, 1024, 32,  v0, 2, 1.f, 0, 4);
        GJob jg = mkjob(H+192, 320, S+OG2T, 128, S+OGB,  1024, 1024, 128, nullptr, 0, 1.f, 0, 4);
        gemm_mma<128><<<dim3(M/128,2,4), 256, SM128>>>(jw, ja, jv, jg);
    }
    // 4: R/K/V projections, z-batched
    {
        GJob jr = mkjob(S+OXR, 1024, S+OWRr, 1024, S+ORB, 1024, 1024, 1024, nullptr, 0, 1.f, 0);
        GJob jk = mkjob(S+OXK, 1024, S+OWKr, 1024, S+OKB, 1024, 1024, 1024, nullptr, 0, 1.f, 0);
        GJob jv = mkjob(S+OXV, 1024, S+OWVr, 1024, S+OVB, 1024, 1024, 1024, nullptr, 0, 1.f, 0);
        gemm_mma<128><<<dim3(M/128,8,3), 256, SM128>>>(jr, jk, jv, jr);
    }
    // 5: scan operand prep
    prep_kernel<<<(BB*TT*HH*32)/256, 256>>>(S+OKB, S+OAB, S+OVB, S+OWL, S+OVMX, vfi,
                                            k_k, k_a,
                                            S+OEW, S+OBBA, S+OAAA, S+OKK2, S+OVVA);
    // 6: sequential scan v3 (128 threads, 4 rows x 4 cols per thread)
    scan_kernel<<<BB*HH*2, 128>>>(S+OEW, S+OBBA, S+OAAA, S+OKK2, S+ORB, S+OVVA, S+OO4);
    // 7: sum partials + groupnorm + bonus + gate
    post_kernel<<<(BB*TT*HH*32)/256, 256>>>(S+OO4, S+ORB, S+OKK2, S+OVVA, S+OGB,
                                            r_k, gnw, gnb, S+OZB);
    // 8: out = Z @ Wo^T
    {
        GJob jo = mkjob(S+OZB, 1024, S+OWOr, 1024, out, 1024, 1024, 1024, nullptr, 0, 1.f, 0);
        gemm_mma<128><<<dim3(M/128,8,1), 256, SM128>>>(jo, jo, jo, jo);
    }
    // v_first passthrough
    if (out_size >= 2*NE){
        cudaMemcpyAsync(out + NE, vfi, (size_t)NE*sizeof(float), cudaMemcpyDeviceToDevice);
    }
}

// round 11
// speedup vs baseline: 2.4096x; 1.0311x over previous
#include <cuda_runtime.h>
#include <math.h>
#include <stdint.h>

#define BB 4
#define TT 1024
#define CC 1024
#define HH 16
#define DD 64
#define NE 4194304     // B*T*C
#define LOG_DECAY (-0.6065306597126334f)
#define GN_EPS 64e-5f

typedef unsigned long long u64;

// ---------------- static scratch ----------------
__device__ float gScratch[104857600];

#define OO4  ((size_t)0)               // scan partials (slots 0-3)
#define OXR  ((size_t)0*NE)
#define OXK  ((size_t)2*NE)
#define OXV  ((size_t)3*NE)
#define OXC  ((size_t)4*NE)            // [x | xx] (slots 4-5)
#define ORB  ((size_t)6*NE)
#define OKB  ((size_t)7*NE)
#define OVB  ((size_t)8*NE)
#define OAB  ((size_t)9*NE)
#define OGB  ((size_t)10*NE)
#define OWL  ((size_t)11*NE)
#define OVMX ((size_t)12*NE)
#define OHST ((size_t)13*NE)
#define OHLO ((size_t)14*NE)           // dead after hsum_act -> reused as MA
#define OHHI ((size_t)15*NE)           // dead after hsum_act -> reused as BG
#define OMA  OHLO
#define OBG  OHHI
#define OEW  ((size_t)16*NE)
#define OBBA ((size_t)17*NE)
#define OAAA ((size_t)18*NE)
#define OKK2 ((size_t)19*NE)
#define OVVA ((size_t)20*NE)
#define OZB  ((size_t)21*NE)
#define OW2T ((size_t)22*NE)
#define OA2T (OW2T + 65536)
#define OV2T (OA2T + 65536)
#define OG2T (OV2T + 32768)
#define OWRr (OG2T + 131072)
#define OWKr (OWRr + 1048576)
#define OWVr (OWKr + 1048576)
#define OWOr (OWVr + 1048576)
#define OBU  (OWOr + 1048576)

__device__ __forceinline__ float to_tf32(float x){
    uint32_t u; asm("cvt.rna.tf32.f32 %0, %1;" : "=r"(u) : "f"(x));
    return __uint_as_float(u);
}
__device__ __forceinline__ float sigm_(float x){ return 1.f/(1.f+expf(-x)); }

__device__ __forceinline__ void mma8(float* d, const uint32_t* a, const uint32_t* b){
    asm volatile("mma.sync.aligned.m16n8k8.row.col.f32.tf32.tf32.f32 "
        "{%0,%1,%2,%3}, {%4,%5,%6,%7}, {%8,%9}, {%0,%1,%2,%3};"
        : "+f"(d[0]), "+f"(d[1]), "+f"(d[2]), "+f"(d[3])
        : "r"(a[0]), "r"(a[1]), "r"(a[2]), "r"(a[3]), "r"(b[0]), "r"(b[1]));
}
__device__ __forceinline__ void ldsm4(uint32_t* r, uint32_t a){
    asm volatile("ldmatrix.sync.aligned.m8n8.x4.shared.b16 {%0,%1,%2,%3}, [%4];"
        : "=r"(r[0]),"=r"(r[1]),"=r"(r[2]),"=r"(r[3]) : "r"(a));
}
__device__ __forceinline__ int swz(int r, int c){
    return r*32 + (int)((((((unsigned)c>>2) ^ ((unsigned)r & 7u)) << 2)) | ((unsigned)c & 3u));
}

// f32x2 packed math helpers
__device__ __forceinline__ u64 FMA2(u64 a, u64 b, u64 c){
    u64 d; asm("fma.rn.f32x2 %0, %1, %2, %3;" : "=l"(d) : "l"(a), "l"(b), "l"(c)); return d;
}
__device__ __forceinline__ u64 MUL2(u64 a, u64 b){
    u64 d; asm("mul.rn.f32x2 %0, %1, %2;" : "=l"(d) : "l"(a), "l"(b)); return d;
}
__device__ __forceinline__ u64 PK2(float x){
    u64 d; asm("mov.b64 %0, {%1, %1};" : "=l"(d) : "f"(x)); return d;
}
__device__ __forceinline__ float HADD2(u64 d){
    float a, b; asm("mov.b64 {%0, %1}, %2;" : "=f"(a), "=f"(b) : "l"(d)); return a + b;
}

// ---------------- job descriptor for batched GEMM ----------------
struct GJob {
    const float* A; const float* B; float* C; const float* bias;
    int lda, ldb, ldc, N, K, mode; float scale; int round_out; int nrep;
};

// ---------------- tf32 GEMM: C = A * B^T, z-batched, flattened pipelined n-rep ----------------
template<int NT>
__global__ void __launch_bounds__(256,2) gemm_mma(GJob j0, GJob j1, GJob j2, GJob j3)
{
    extern __shared__ float sm[];
    const int AS  = 128*32;
    const int STG = (128+NT)*32;
    const int NTN = (NT==128) ? 8 : 4;
    const int NLD = NTN/2;

    GJob jb = j0;
    if (blockIdx.z == 1) jb = j1;
    else if (blockIdx.z == 2) jb = j2;
    else if (blockIdx.z == 3) jb = j3;

    int tid = threadIdx.x, wid = tid >> 5, lane = tid & 31;
    int bm0 = blockIdx.x * 128;
    int grp = lane >> 2, thr = lane & 3;
    int wm = (wid & 3) * 32;
    int wn = (NT==128) ? (wid >> 2) * 64 : (wid >> 2) * 32;
    int NC = jb.K >> 5;
    int total = jb.nrep * NC;

    uint32_t smb = (uint32_t)__cvta_generic_to_shared(sm);

    uint32_t aoff[2][4], boff[NLD][4];
    #pragma unroll
    for (int mt=0;mt<2;mt++)
      #pragma unroll
      for (int kk=0;kk<4;kk++){
        int row = wm + mt*16 + (lane & 15);
        int col = kk*8 + (lane >> 4) * 4;
        aoff[mt][kk] = 4u * (uint32_t)swz(row, col);
      }
    #pragma unroll
    for (int np=0;np<NLD;np++)
      #pragma unroll
      for (int kk=0;kk<4;kk++){
        int row = wn + np*16 + (lane & 7) + ((lane >> 4) & 1) * 8;
        int col = kk*8 + ((lane >> 3) & 1) * 4;
        boff[np][kk] = 4u * (uint32_t)(AS + swz(row, col));
      }

    auto load_stage = [&](int stg, int tc){
        int rep = tc / NC;
        int c = tc - rep*NC;
        int bn = (blockIdx.y * jb.nrep + rep) * NT;
        const float* Ag = jb.A + (size_t)bm0 * jb.lda + c*32;
        #pragma unroll
        for (int i=0;i<4;i++){
            int idx = tid + 256*i; int r = idx>>3, j = idx&7;
            unsigned dst = smb + 4u*(uint32_t)(stg*STG + swz(r, j*4));
            const float* src = Ag + (size_t)r*jb.lda + j*4;
            asm volatile("cp.async.cg.shared.global [%0], [%1], 16;"::"r"(dst),"l"(src));
        }
        const float* Bg = jb.B + (size_t)bn * jb.ldb + c*32;
        #pragma unroll
        for (int i=0;i<NT/32;i++){
            int idx = tid + 256*i; int r = idx>>3, j = idx&7;
            unsigned dst = smb + 4u*(uint32_t)(stg*STG + AS + swz(r, j*4));
            const float* src = Bg + (size_t)r*jb.ldb + j*4;
            asm volatile("cp.async.cg.shared.global [%0], [%1], 16;"::"r"(dst),"l"(src));
        }
    };

    float acc[2][NTN][4];
    #pragma unroll
    for (int i=0;i<2;i++)
      #pragma unroll
      for (int j=0;j<NTN;j++)
        #pragma unroll
        for (int l=0;l<4;l++) acc[i][j][l]=0.f;

    load_stage(0, 0);
    asm volatile("cp.async.commit_group;");
    if (total > 1) load_stage(1, 1);
    asm volatile("cp.async.commit_group;");

    int cc = 0;
    for (int tc = 0; tc < total; tc++){
        asm volatile("cp.async.wait_group 1;");
        __syncthreads();
        uint32_t sb = smb + 4u*(uint32_t)((tc % 3) * STG);
        #pragma unroll
        for (int kk=0; kk<4; kk++){
            uint32_t af[2][4];
            ldsm4(af[0], sb + aoff[0][kk]);
            ldsm4(af[1], sb + aoff[1][kk]);
            uint32_t bf[NLD][4];
            #pragma unroll
            for (int np=0;np<NLD;np++) ldsm4(bf[np], sb + boff[np][kk]);
            #pragma unroll
            for (int mt=0;mt<2;mt++)
                #pragma unroll
                for (int nt=0;nt<NTN;nt++)
                    mma8(acc[mt][nt], af[mt], &bf[nt>>1][(nt&1)*2]);
        }
        if (tc + 2 < total) load_stage((tc+2) % 3, tc+2);
        asm volatile("cp.async.commit_group;");

        if (++cc == NC){
            cc = 0;
            int rep = tc / NC;
            int bn0 = (blockIdx.y * jb.nrep + rep) * NT;
            #pragma unroll
            for (int mt=0;mt<2;mt++){
                #pragma unroll
                for (int nt=0;nt<NTN;nt++){
                    #pragma unroll
                    for (int half=0; half<2; half++){
                        int row = bm0 + wm + mt*16 + grp + half*8;
                        int col = bn0 + wn + nt*8 + thr*2;
                        float v0 = acc[mt][nt][half*2+0];
                        float v1 = acc[mt][nt][half*2+1];
                        if (jb.bias){ v0 += jb.bias[col]; v1 += jb.bias[col+1]; }
                        if (jb.mode==1){ v0 = tanhf(v0); v1 = tanhf(v1); }
                        else if (jb.mode==2){ v0 = jb.scale*sigm_(v0); v1 = jb.scale*sigm_(v1); }
                        else if (jb.mode==3){
                            v0 = (col   < 64) ? tanhf(v0) : (col   < 192 ? v0 : sigm_(v0));
                            v1 = (col+1 < 64) ? tanhf(v1) : (col+1 < 192 ? v1 : sigm_(v1));
                        }
                        if (jb.round_out){ v0 = to_tf32(v0); v1 = to_tf32(v1); }
                        float* cp = jb.C + (size_t)row*jb.ldc + col;
                        cp[0] = v0; cp[1] = v1;
                        acc[mt][nt][half*2+0] = 0.f;
                        acc[mt][nt][half*2+1] = 0.f;
                    }
                }
            }
        }
    }
}

// ---------------- fused elementwise prep: weights + token-shift mix ----------------
__device__ __forceinline__ void do_tr(const float* src, float* dst, int rows, int cols, int li){
    int r = li / cols, c = li - r * cols;
    dst[(size_t)c * rows + r] = to_tf32(src[li]);
}
__global__ __launch_bounds__(256) void elem_prep(
    const float* __restrict__ Wr, const float* __restrict__ Wk,
    const float* __restrict__ Wv, const float* __restrict__ Wo,
    const float* __restrict__ w1, const float* __restrict__ a1,
    const float* __restrict__ v1, const float* __restrict__ g1,
    const float* __restrict__ w2, const float* __restrict__ a2,
    const float* __restrict__ v2, const float* __restrict__ g2,
    const float* __restrict__ x_w, const float* __restrict__ x_a,
    const float* __restrict__ x_v, const float* __restrict__ x_g,
    const float* __restrict__ x,
    const float* __restrict__ mr, const float* __restrict__ mk, const float* __restrict__ mv,
    float* __restrict__ Sg)
{
    if (blockIdx.x >= 20096){
        int row = blockIdx.x - 20096;
        int t = row & (TT-1);
        int c4 = threadIdx.x;
        const float4* xv4 = (const float4*)x;
        float4 xc = xv4[(size_t)row*256 + c4];
        float4 xp = make_float4(0.f,0.f,0.f,0.f);
        if (t > 0) xp = xv4[(size_t)(row-1)*256 + c4];
        float4 dx = make_float4(xp.x-xc.x, xp.y-xc.y, xp.z-xc.z, xp.w-xc.w);
        size_t o = (size_t)row*256 + c4;
        float4 m;
        #define MIXOUT(dst, mp) \
            m = ((const float4*)mp)[c4]; \
            ((float4*)(Sg+dst))[o] = make_float4(to_tf32(xc.x+dx.x*m.x), to_tf32(xc.y+dx.y*m.y), \
                                                 to_tf32(xc.z+dx.z*m.z), to_tf32(xc.w+dx.w*m.w));
        MIXOUT(OXR, mr) MIXOUT(OXK, mk) MIXOUT(OXV, mv)
        #undef MIXOUT
        float4* xcp = (float4*)(Sg + OXC + (size_t)row*2048);
        xcp[c4]       = make_float4(to_tf32(xc.x), to_tf32(xc.y), to_tf32(xc.z), to_tf32(xc.w));
        xcp[256 + c4] = make_float4(to_tf32(dx.x), to_tf32(dx.y), to_tf32(dx.z), to_tf32(dx.w));
        return;
    }
    int idx = blockIdx.x * 256 + threadIdx.x;
    if (idx < 4194304){
        int m = idx >> 20;
        int i = idx & 1048575;
        const float* src = (m == 0) ? Wr : (m == 1) ? Wk : (m == 2) ? Wv : Wo;
        float* dst = Sg + ((m == 0) ? OWRr : (m == 1) ? OWKr : (m == 2) ? OWVr : OWOr);
        dst[i] = to_tf32(src[i]);
        return;
    }
    idx -= 4194304;
    if (idx < 655360){
        int n = idx >> 11;
        int k = idx & 2047;
        int kk = k & 1023;
        float val = 0.f;
        if (n < 64){
            float w = w1[kk*64 + n];
            val = (k < 1024) ? w : x_w[kk]*w;
        } else if (n < 128){
            float w = a1[kk*64 + (n-64)];
            val = (k < 1024) ? w : x_a[kk]*w;
        } else if (n < 160){
            float w = v1[kk*32 + (n-128)];
            val = (k < 1024) ? w : x_v[kk]*w;
        } else if (n >= 192){
            float w = g1[kk*128 + (n-192)];
            val = (k < 1024) ? w : x_g[kk]*w;
        }
        Sg[OBU + idx] = to_tf32(val);
        return;
    }
    int j = idx - 655360;
    if (j >= 294912) return;
    if      (j < 65536 )  do_tr(w2, Sg+OW2T, 64, 1024,  j);
    else if (j < 131072)  do_tr(a2, Sg+OA2T, 64, 1024,  j-65536);
    else if (j < 163840)  do_tr(v2, Sg+OV2T, 32, 1024,  j-131072);
    else                  do_tr(g2, Sg+OG2T, 128, 1024, j-163840);
}

// ---------------- H = act(Hlo + Hhi) ----------------
__global__ __launch_bounds__(256) void hsum_act(
    const float* __restrict__ Hlo, const float* __restrict__ Hhi, float* __restrict__ H)
{
    int i = blockIdx.x*256 + threadIdx.x;
    if (i >= 4096*80) return;
    int row = i / 80, q = i - row*80;
    int col = q*4;
    size_t off = (size_t)row*320 + col;
    float4 a = *(const float4*)&Hlo[off];
    float4 b = *(const float4*)&Hhi[off];
    float v[4] = {a.x+b.x, a.y+b.y, a.z+b.z, a.w+b.w};
    #pragma unroll
    for (int j=0;j<4;j++){
        int c = col + j;
        float xx = v[j];
        xx = (c < 64) ? tanhf(xx) : (c < 192 ? xx : sigm_(xx));
        v[j] = to_tf32(xx);
    }
    *(float4*)&H[off] = make_float4(v[0], v[1], v[2], v[3]);
}

// ---------------- scan-operand prep ----------------
__global__ __launch_bounds__(256) void prep_kernel(
    const float* __restrict__ K, const float* __restrict__ A, const float* __restrict__ V,
    const float* __restrict__ WL, const float* __restrict__ VMIX, const float* __restrict__ vfirst,
    const float* __restrict__ k_k, const float* __restrict__ k_a,
    float* __restrict__ EW, float* __restrict__ BBo, float* __restrict__ AAo,
    float* __restrict__ K2o, float* __restrict__ Vo)
{
    int gw = (blockIdx.x*256 + threadIdx.x) >> 5;
    int lane = threadIdx.x & 31;
    int h = gw & 15, t = (gw >> 4) & 1023, b = gw >> 14;
    int c = h*64 + lane*2;
    size_t btc = ((size_t)(b*TT + t))*CC + c;
    float2 k  = *(const float2*)&K[btc];
    float2 kw = *(const float2*)&k_k[c];
    float2 ka = *(const float2*)&k_a[c];
    float2 a  = *(const float2*)&A[btc];
    float kk0 = k.x*kw.x, kk1 = k.y*kw.y;
    float ss = kk0*kk0 + kk1*kk1;
    #pragma unroll
    for (int off=16; off>0; off>>=1) ss += __shfl_xor_sync(0xffffffffu, ss, off);
    float inv = 1.f / fmaxf(sqrtf(ss), 1e-12f);
    kk0 *= inv; kk1 *= inv;
    float2 wl = *(const float2*)&WL[btc];
    float2 v  = *(const float2*)&V[btc];
    float2 vf = *(const float2*)&vfirst[btc];
    float2 vm = *(const float2*)&VMIX[btc];
    v.x = v.x + (vf.x - v.x)*vm.x;
    v.y = v.y + (vf.y - v.y)*vm.y;
    float k20 = k.x*(1.f + (a.x-1.f)*ka.x);
    float k21 = k.y*(1.f + (a.y-1.f)*ka.y);
    size_t bhtd = ((size_t)((b*HH + h)*TT + t))*64 + lane*2;
    *(float2*)&EW[bhtd]  = make_float2(expf(wl.x), expf(wl.y));
    *(float2*)&BBo[bhtd] = make_float2(kk0*a.x, kk1*a.y);
    *(float2*)&AAo[bhtd] = make_float2(-kk0, -kk1);
    *(float2*)&K2o[bhtd] = make_float2(k20, k21);
    *(float2*)&Vo[bhtd]  = v;
}

// ---------------- prep2: look-ahead vectors/scalars ----------------
// MA_t = EW_t ∘ AA_{t+1};  BG[bh][t] = {dot(BB_t, AA_{t+1}), dot(K2_t, AA_{t+1})}
__global__ __launch_bounds__(256) void prep2_kernel(
    const float* __restrict__ EW, const float* __restrict__ BBo, const float* __restrict__ AAo,
    const float* __restrict__ K2o, float* __restrict__ MA, float* __restrict__ BG)
{
    int gw = (blockIdx.x*256 + threadIdx.x) >> 5;
    int lane = threadIdx.x & 31;
    int h = gw & 15, t = (gw >> 4) & 1023, b = gw >> 14;
    size_t bhtd = ((size_t)((b*HH + h)*TT + t))*64 + lane*2;
    float2 aan = make_float2(0.f, 0.f);
    if (t < TT-1) aan = *(const float2*)&AAo[bhtd + 64];
    float2 ew = *(const float2*)&EW[bhtd];
    float2 bb = *(const float2*)&BBo[bhtd];
    float2 k2 = *(const float2*)&K2o[bhtd];
    *(float2*)&MA[bhtd] = make_float2(ew.x*aan.x, ew.y*aan.y);
    float bsum = bb.x*aan.x + bb.y*aan.y;
    float gsum = k2.x*aan.x + k2.y*aan.y;
    #pragma unroll
    for (int off=16; off>0; off>>=1){
        bsum += __shfl_xor_sync(0xffffffffu, bsum, off);
        gsum += __shfl_xor_sync(0xffffffffu, gsum, off);
    }
    if (lane == 0)
        *(float2*)&BG[((size_t)(b*HH + h)*TT + t)*2] = make_float2(bsum, gsum);
}

// ---------------- scan v4: look-ahead recurrence, 128 thr, 4 rows x 4 cols ----------------
__global__ void __launch_bounds__(128) scan_kernel(
    const float* __restrict__ EW, const float* __restrict__ BBp, const float* __restrict__ MAp,
    const float* __restrict__ K2p, const float* __restrict__ RB, const float* __restrict__ Vp,
    const float* __restrict__ BG, float* __restrict__ O4)
{
    __shared__ float sm[16*6*64];   // 16 stages x 384 floats
    __shared__ float bg_sm[32];     // 16 stages x {beta, gamma}
    int bh = blockIdx.x >> 1;
    int b = bh >> 4, h = bh & 15;
    int rowBase = (blockIdx.x & 1) * 32;
    int tid = threadIdx.x;
    int cg = tid & 15;
    int rg = tid >> 4;
    int col0 = cg * 4;
    size_t base = (size_t)bh * TT * 64;
    size_t base4 = (size_t)bh * TT * 256;
    const float* BGp = BG + (size_t)bh * TT * 2;

    const float* mysrc = nullptr; int mystride = 64;
    int arr = tid >> 4, seg = tid & 15;
    if (tid < 96){
        switch (arr){
            case 0: mysrc = EW  + base; break;
            case 1: mysrc = BBp + base; break;
            case 2: mysrc = MAp + base; break;
            case 3: mysrc = K2p + base; break;
            case 4: mysrc = RB + (size_t)b*TT*CC + h*64; mystride = CC; break;
            case 5: mysrc = Vp  + base; break;
        }
    }
    uint32_t smb = (uint32_t)__cvta_generic_to_shared(sm);
    uint32_t smbg = (uint32_t)__cvta_generic_to_shared(bg_sm);

    auto pf4 = [&](int batch){
        if (tid < 96){
            #pragma unroll
            for (int u=0; u<4; u++){
                int t = batch*4 + u;
                const float* g = mysrc + (size_t)t*mystride + seg*4;
                unsigned sa = smb + 4u*(uint32_t)(((t&15)*384) + arr*64 + seg*4);
                asm volatile("cp.async.ca.shared.global [%0], [%1], 16;"::"r"(sa),"l"(g));
            }
        } else if (tid < 98){
            const float* g = BGp + (size_t)batch*8 + (tid-96)*4;
            unsigned sa = smbg + 4u*(uint32_t)((((batch*4)&15)*2) + (tid-96)*4);
            asm volatile("cp.async.ca.shared.global [%0], [%1], 16;"::"r"(sa),"l"(g));
        }
        asm volatile("cp.async.commit_group;");
    };

    pf4(0); pf4(1); pf4(2);

    u64 S2[4][2];
    float sab[4];
    #pragma unroll
    for (int j=0;j<4;j++){ S2[j][0]=0ull; S2[j][1]=0ull; sab[j]=0.f; }

    for (int i=0; i<256; i++){
        asm volatile("cp.async.wait_group 2;");
        __syncthreads();
        if (i+3 < 256) pf4(i+3);
        else asm volatile("cp.async.commit_group;");
        int tb = i*4;

        #pragma unroll
        for (int u=0; u<4; u++){
            const float* st = &sm[((tb+u) & 15) * 384];
            u64 ew2[2], bb2[2], ma2[2], kk2[2], rr2[2];
            #define LD2(dst, off) { \
                ulonglong2 q = *(const ulonglong2*)&st[(off)+col0]; \
                dst[0]=q.x; dst[1]=q.y; }
            LD2(ew2,   0) LD2(bb2,  64) LD2(ma2, 128) LD2(kk2, 192) LD2(rr2, 256)
            #undef LD2
            float vv[4];
            #pragma unroll
            for (int j=0;j<4;j++) vv[j] = st[320 + rowBase + rg + 8*j];
            float2 bg = *(const float2*)&bg_sm[((tb+u)&15)*2];

            // D partials from OLD state (off-chain; shfls overlap the S update below)
            float Dp[4];
            #pragma unroll
            for (int j=0;j<4;j++)
                Dp[j] = HADD2(FMA2(S2[j][1], ma2[1], MUL2(S2[j][0], ma2[0])));
            #pragma unroll
            for (int j=0;j<4;j++){
                Dp[j] += __shfl_xor_sync(0xffffffffu, Dp[j], 1);
                Dp[j] += __shfl_xor_sync(0xffffffffu, Dp[j], 2);
                Dp[j] += __shfl_xor_sync(0xffffffffu, Dp[j], 4);
                Dp[j] += __shfl_xor_sync(0xffffffffu, Dp[j], 8);
            }

            // state update + deferred output partials
            float po[4];
            #pragma unroll
            for (int j=0;j<4;j++){
                u64 sab2 = PK2(sab[j]), vv2 = PK2(vv[j]);
                S2[j][0] = FMA2(kk2[0], vv2, FMA2(bb2[0], sab2, MUL2(S2[j][0], ew2[0])));
                S2[j][1] = FMA2(kk2[1], vv2, FMA2(bb2[1], sab2, MUL2(S2[j][1], ew2[1])));
                po[j] = HADD2(FMA2(S2[j][1], rr2[1], MUL2(S2[j][0], rr2[0])));
                po[j] += __shfl_xor_sync(0xffffffffu, po[j], 1);
                po[j] += __shfl_xor_sync(0xffffffffu, po[j], 2);
            }
            // next sab via look-ahead recurrence (short chain)
            #pragma unroll
            for (int j=0;j<4;j++)
                sab[j] = Dp[j] + sab[j]*bg.x + vv[j]*bg.y;

            if ((tid & 3) == 0){
                size_t ob = base4 + (size_t)(tb+u)*256;
                int p = cg >> 2;
                #pragma unroll
                for (int j=0;j<4;j++)
                    O4[ob + (size_t)(rowBase + rg + 8*j)*4 + p] = po[j];
            }
        }
    }
}

// ---------------- post: sum partials + groupnorm + bonus + gate ----------------
__global__ __launch_bounds__(256) void post_kernel(
    const float* __restrict__ O4, const float* __restrict__ RB, const float* __restrict__ K2p,
    const float* __restrict__ Vp, const float* __restrict__ G,
    const float* __restrict__ r_k, const float* __restrict__ gn_w, const float* __restrict__ gn_b,
    float* __restrict__ Z)
{
    int gw = (blockIdx.x*256 + threadIdx.x) >> 5;
    int lane = threadIdx.x & 31;
    int h = gw & 15, t = (gw >> 4) & 1023, b = gw >> 14;
    size_t bhtd = ((size_t)((b*HH + h)*TT + t))*64 + lane*2;
    int c = h*64 + lane*2;
    size_t btc = ((size_t)(b*TT + t))*CC + c;

    size_t b4 = ((size_t)(b*HH + h))*TT*256 + (size_t)t*256 + (size_t)lane*8;
    float4 pa = *(const float4*)&O4[b4];
    float4 pb = *(const float4*)&O4[b4 + 4];
    float2 o = make_float2(pa.x+pa.y+pa.z+pa.w, pb.x+pb.y+pb.z+pb.w);

    float sm = o.x + o.y;
    #pragma unroll
    for (int off=16; off>0; off>>=1) sm += __shfl_xor_sync(0xffffffffu, sm, off);
    float mean = sm * (1.f/64.f);
    float dx = o.x - mean, dy = o.y - mean;
    float vs = dx*dx + dy*dy;
    #pragma unroll
    for (int off=16; off>0; off>>=1) vs += __shfl_xor_sync(0xffffffffu, vs, off);
    float inv = rsqrtf(vs*(1.f/64.f) + GN_EPS);

    float2 r  = *(const float2*)&RB[btc];
    float2 k2 = *(const float2*)&K2p[bhtd];
    float2 v  = *(const float2*)&Vp[bhtd];
    float2 rk = *(const float2*)&r_k[c];
    float bs = r.x*k2.x*rk.x + r.y*k2.y*rk.y;
    #pragma unroll
    for (int off=16; off>0; off>>=1) bs += __shfl_xor_sync(0xffffffffu, bs, off);

    float2 g  = *(const float2*)&G[btc];
    float2 w  = *(const float2*)&gn_w[c];
    float2 bb = *(const float2*)&gn_b[c];
    float z0 = ((dx*inv)*w.x + bb.x + bs*v.x) * g.x;
    float z1 = ((dy*inv)*w.y + bb.y + bs*v.y) * g.y;
    *(float2*)&Z[btc] = make_float2(to_tf32(z0), to_tf32(z1));
}

// ---------------- driver ----------------
static inline GJob mkjob(const float* A, int lda, const float* B, int ldb, float* C, int ldc,
                         int N, int K, const float* bias, int mode, float scale, int ro, int nrep=1){
    GJob j; j.A=A; j.B=B; j.C=C; j.bias=bias; j.lda=lda; j.ldb=ldb; j.ldc=ldc;
    j.N=N; j.K=K; j.mode=mode; j.scale=scale; j.round_out=ro; j.nrep=nrep; return j;
}

extern "C" void kernel_launch(void* const* d_in, const int* in_sizes, int n_in,
                              void* d_out, int out_size) {
    const float* x   = (const float*)d_in[0];
    const float* vfi = (const float*)d_in[1];
    const float* x_r = (const float*)d_in[2];
    const float* x_w = (const float*)d_in[3];
    const float* x_k = (const float*)d_in[4];
    const float* x_v = (const float*)d_in[5];
    const float* x_a = (const float*)d_in[6];
    const float* x_g = (const float*)d_in[7];
    const float* Wr  = (const float*)d_in[8];
    const float* Wk  = (const float*)d_in[9];
    const float* Wv  = (const float*)d_in[10];
    const float* Wo  = (const float*)d_in[11];
    const float* w0  = (const float*)d_in[12];
    const float* w1  = (const float*)d_in[13];
    const float* w2  = (const float*)d_in[14];
    const float* a0  = (const float*)d_in[15];
    const float* a1  = (const float*)d_in[16];
    const float* a2  = (const float*)d_in[17];
    const float* v0  = (const float*)d_in[18];
    const float* v1  = (const float*)d_in[19];
    const float* v2  = (const float*)d_in[20];
    const float* g1  = (const float*)d_in[21];
    const float* g2  = (const float*)d_in[22];
    const float* k_k = (const float*)d_in[23];
    const float* k_a = (const float*)d_in[24];
    const float* r_k = (const float*)d_in[25];
    const float* gnw = (const float*)d_in[26];
    const float* gnb = (const float*)d_in[27];
    float* out = (float*)d_out;

    float* S;
    cudaGetSymbolAddress((void**)&S, gScratch);

    const int SM128 = 3*(128+128)*32*4;   // 98304
    const int SM64  = 3*(128+64)*32*4;    // 73728
    cudaFuncSetAttribute(gemm_mma<128>, cudaFuncAttributeMaxDynamicSharedMemorySize, SM128);
    cudaFuncSetAttribute(gemm_mma<64>,  cudaFuncAttributeMaxDynamicSharedMemorySize, SM64);

    const int M = BB*TT;
    float* H = S + OHST;

    // 0: fused elementwise prep
    elem_prep<<<24192, 256>>>(Wr, Wk, Wv, Wo, w1, a1, v1, g1, w2, a2, v2, g2,
                              x_w, x_a, x_v, x_g, x, x_r, x_k, x_v, S);
    // 1: stage-1 split-K halves
    {
        GJob jlo = mkjob(S+OXC,      2048, S+OBU,      2048, S+OHLO, 320, 320, 1024, nullptr, 0, 1.f, 0);
        GJob jhi = mkjob(S+OXC+1024, 2048, S+OBU+1024, 2048, S+OHHI, 320, 320, 1024, nullptr, 0, 1.f, 0);
        gemm_mma<64><<<dim3(M/128,5,2), 256, SM64>>>(jlo, jhi, jlo, jlo);
    }
    // 2: H = act(Hlo + Hhi)
    hsum_act<<<1280, 256>>>(S+OHLO, S+OHHI, H);
    // 3: stage-2 low-rank outputs, z-batched, pipelined n-rep=4  <-- profiled (idx 3)
    {
        GJob jw = mkjob(H+0,   320, S+OW2T, 64,  S+OWL,  1024, 1024, 64,  w0, 2, LOG_DECAY, 0, 4);
        GJob ja = mkjob(H+64,  320, S+OA2T, 64,  S+OAB,  1024, 1024, 64,  a0, 2, 1.f, 0, 4);
        GJob jv = mkjob(H+128, 320, S+OV2T, 32,  S+OVMX, 1024, 1024, 32,  v0, 2, 1.f, 0, 4);
        GJob jg = mkjob(H+192, 320, S+OG2T, 128, S+OGB,  1024, 1024, 128, nullptr, 0, 1.f, 0, 4);
        gemm_mma<128><<<dim3(M/128,2,4), 256, SM128>>>(jw, ja, jv, jg);
    }
    // 4: R/K/V projections, z-batched
    {
        GJob jr = mkjob(S+OXR, 1024, S+OWRr, 1024, S+ORB, 1024, 1024, 1024, nullptr, 0, 1.f, 0);
        GJob jk = mkjob(S+OXK, 1024, S+OWKr, 1024, S+OKB, 1024, 1024, 1024, nullptr, 0, 1.f, 0);
        GJob jv = mkjob(S+OXV, 1024, S+OWVr, 1024, S+OVB, 1024, 1024, 1024, nullptr, 0, 1.f, 0);
        gemm_mma<128><<<dim3(M/128,8,3), 256, SM128>>>(jr, jk, jv, jr);
    }
    // 5: scan operand prep
    prep_kernel<<<(BB*TT*HH*32)/256, 256>>>(S+OKB, S+OAB, S+OVB, S+OWL, S+OVMX, vfi,
                                            k_k, k_a,
                                            S+OEW, S+OBBA, S+OAAA, S+OKK2, S+OVVA);
    // 6: look-ahead vectors/scalars
    prep2_kernel<<<(BB*TT*HH*32)/256, 256>>>(S+OEW, S+OBBA, S+OAAA, S+OKK2, S+OMA, S+OBG);
    // 7: sequential scan v4
    scan_kernel<<<BB*HH*2, 128>>>(S+OEW, S+OBBA, S+OMA, S+OKK2, S+ORB, S+OVVA, S+OBG, S+OO4);
    // 8: sum partials + groupnorm + bonus + gate
    post_kernel<<<(BB*TT*HH*32)/256, 256>>>(S+OO4, S+ORB, S+OKK2, S+OVVA, S+OGB,
                                            r_k, gnw, gnb, S+OZB);
    // 9: out = Z @ Wo^T
    {
        GJob jo = mkjob(S+OZB, 1024, S+OWOr, 1024, out, 1024, 1024, 1024, nullptr, 0, 1.f, 0);
        gemm_mma<128><<<dim3(M/128,8,1), 256, SM128>>>(jo, jo, jo, jo);
    }
    // v_first passthrough
    if (out_size >= 2*NE){
        cudaMemcpyAsync(out + NE, vfi, (size_t)NE*sizeof(float), cudaMemcpyDeviceToDevice);
    }
}

// round 12
// speedup vs baseline: 2.5781x; 1.0699x over previous
#include <cuda_runtime.h>
#include <math.h>
#include <stdint.h>

#define BB 4
#define TT 1024
#define CC 1024
#define HH 16
#define DD 64
#define NE 4194304     // B*T*C
#define LOG_DECAY (-0.6065306597126334f)
#define GN_EPS 64e-5f

typedef unsigned long long u64;

// ---------------- static scratch ----------------
__device__ float gScratch[104857600];

#define OO4  ((size_t)0)               // scan partials (slots 0-3)
#define OXR  ((size_t)0*NE)
#define OXK  ((size_t)2*NE)
#define OXV  ((size_t)3*NE)
#define OXC  ((size_t)4*NE)            // [x | xx] (slots 4-5)
#define ORB  ((size_t)6*NE)
#define OKB  ((size_t)7*NE)
#define OVB  ((size_t)8*NE)
#define OAB  ((size_t)9*NE)
#define OGB  ((size_t)10*NE)
#define OWL  ((size_t)11*NE)
#define OVMX ((size_t)12*NE)
#define OHST ((size_t)13*NE)
#define OHLO ((size_t)14*NE)           // dead after hsum_act -> reused as MA
#define OHHI ((size_t)15*NE)           // dead after hsum_act -> reused as BG
#define OMA  OHLO
#define OBG  OHHI
#define OEW  ((size_t)16*NE)
#define OBBA ((size_t)17*NE)
#define OKK2 ((size_t)19*NE)
#define OVVA ((size_t)20*NE)
#define OZB  ((size_t)21*NE)
#define OW2T ((size_t)22*NE)
#define OA2T (OW2T + 65536)
#define OV2T (OA2T + 65536)
#define OG2T (OV2T + 32768)
#define OWRr (OG2T + 131072)
#define OWKr (OWRr + 1048576)
#define OWVr (OWKr + 1048576)
#define OWOr (OWVr + 1048576)
#define OBU  (OWOr + 1048576)

__device__ __forceinline__ float to_tf32(float x){
    uint32_t u; asm("cvt.rna.tf32.f32 %0, %1;" : "=r"(u) : "f"(x));
    return __uint_as_float(u);
}
__device__ __forceinline__ float sigm_(float x){ return 1.f/(1.f+expf(-x)); }

__device__ __forceinline__ void mma8(float* d, const uint32_t* a, const uint32_t* b){
    asm volatile("mma.sync.aligned.m16n8k8.row.col.f32.tf32.tf32.f32 "
        "{%0,%1,%2,%3}, {%4,%5,%6,%7}, {%8,%9}, {%0,%1,%2,%3};"
        : "+f"(d[0]), "+f"(d[1]), "+f"(d[2]), "+f"(d[3])
        : "r"(a[0]), "r"(a[1]), "r"(a[2]), "r"(a[3]), "r"(b[0]), "r"(b[1]));
}
__device__ __forceinline__ void ldsm4(uint32_t* r, uint32_t a){
    asm volatile("ldmatrix.sync.aligned.m8n8.x4.shared.b16 {%0,%1,%2,%3}, [%4];"
        : "=r"(r[0]),"=r"(r[1]),"=r"(r[2]),"=r"(r[3]) : "r"(a));
}
__device__ __forceinline__ int swz(int r, int c){
    return r*32 + (int)((((((unsigned)c>>2) ^ ((unsigned)r & 7u)) << 2)) | ((unsigned)c & 3u));
}

// f32x2 packed math helpers
__device__ __forceinline__ u64 FMA2(u64 a, u64 b, u64 c){
    u64 d; asm("fma.rn.f32x2 %0, %1, %2, %3;" : "=l"(d) : "l"(a), "l"(b), "l"(c)); return d;
}
__device__ __forceinline__ u64 MUL2(u64 a, u64 b){
    u64 d; asm("mul.rn.f32x2 %0, %1, %2;" : "=l"(d) : "l"(a), "l"(b)); return d;
}
__device__ __forceinline__ u64 PK2(float x){
    u64 d; asm("mov.b64 %0, {%1, %1};" : "=l"(d) : "f"(x)); return d;
}
__device__ __forceinline__ float HADD2(u64 d){
    float a, b; asm("mov.b64 {%0, %1}, %2;" : "=f"(a), "=f"(b) : "l"(d)); return a + b;
}

// ---------------- job descriptor for batched GEMM ----------------
struct GJob {
    const float* A; const float* B; float* C; const float* bias;
    int lda, ldb, ldc, N, K, mode; float scale; int round_out; int nrep; int ny;
};
struct GPack { GJob j[8]; };

// ---------------- tf32 GEMM: C = A * B^T, z-batched pack, pipelined n-rep, ny early-exit ----
template<int NT>
__global__ void __launch_bounds__(256,2) gemm_mma(GPack p)
{
    extern __shared__ float sm[];
    const int AS  = 128*32;
    const int STG = (128+NT)*32;
    const int NTN = (NT==128) ? 8 : 4;
    const int NLD = NTN/2;

    GJob jb = p.j[blockIdx.z];
    if ((int)blockIdx.y >= jb.ny) return;

    int tid = threadIdx.x, wid = tid >> 5, lane = tid & 31;
    int bm0 = blockIdx.x * 128;
    int grp = lane >> 2, thr = lane & 3;
    int wm = (wid & 3) * 32;
    int wn = (NT==128) ? (wid >> 2) * 64 : (wid >> 2) * 32;
    int NC = jb.K >> 5;
    int total = jb.nrep * NC;

    uint32_t smb = (uint32_t)__cvta_generic_to_shared(sm);

    uint32_t aoff[2][4], boff[NLD][4];
    #pragma unroll
    for (int mt=0;mt<2;mt++)
      #pragma unroll
      for (int kk=0;kk<4;kk++){
        int row = wm + mt*16 + (lane & 15);
        int col = kk*8 + (lane >> 4) * 4;
        aoff[mt][kk] = 4u * (uint32_t)swz(row, col);
      }
    #pragma unroll
    for (int np=0;np<NLD;np++)
      #pragma unroll
      for (int kk=0;kk<4;kk++){
        int row = wn + np*16 + (lane & 7) + ((lane >> 4) & 1) * 8;
        int col = kk*8 + ((lane >> 3) & 1) * 4;
        boff[np][kk] = 4u * (uint32_t)(AS + swz(row, col));
      }

    auto load_stage = [&](int stg, int tc){
        int rep = tc / NC;
        int c = tc - rep*NC;
        int bn = (blockIdx.y * jb.nrep + rep) * NT;
        const float* Ag = jb.A + (size_t)bm0 * jb.lda + c*32;
        #pragma unroll
        for (int i=0;i<4;i++){
            int idx = tid + 256*i; int r = idx>>3, j = idx&7;
            unsigned dst = smb + 4u*(uint32_t)(stg*STG + swz(r, j*4));
            const float* src = Ag + (size_t)r*jb.lda + j*4;
            asm volatile("cp.async.cg.shared.global [%0], [%1], 16;"::"r"(dst),"l"(src));
        }
        const float* Bg = jb.B + (size_t)bn * jb.ldb + c*32;
        #pragma unroll
        for (int i=0;i<NT/32;i++){
            int idx = tid + 256*i; int r = idx>>3, j = idx&7;
            unsigned dst = smb + 4u*(uint32_t)(stg*STG + AS + swz(r, j*4));
            const float* src = Bg + (size_t)r*jb.ldb + j*4;
            asm volatile("cp.async.cg.shared.global [%0], [%1], 16;"::"r"(dst),"l"(src));
        }
    };

    float acc[2][NTN][4];
    #pragma unroll
    for (int i=0;i<2;i++)
      #pragma unroll
      for (int j=0;j<NTN;j++)
        #pragma unroll
        for (int l=0;l<4;l++) acc[i][j][l]=0.f;

    load_stage(0, 0);
    asm volatile("cp.async.commit_group;");
    if (total > 1) load_stage(1, 1);
    asm volatile("cp.async.commit_group;");

    int cc = 0;
    for (int tc = 0; tc < total; tc++){
        asm volatile("cp.async.wait_group 1;");
        __syncthreads();
        uint32_t sb = smb + 4u*(uint32_t)((tc % 3) * STG);
        #pragma unroll
        for (int kk=0; kk<4; kk++){
            uint32_t af[2][4];
            ldsm4(af[0], sb + aoff[0][kk]);
            ldsm4(af[1], sb + aoff[1][kk]);
            uint32_t bf[NLD][4];
            #pragma unroll
            for (int np=0;np<NLD;np++) ldsm4(bf[np], sb + boff[np][kk]);
            #pragma unroll
            for (int mt=0;mt<2;mt++)
                #pragma unroll
                for (int nt=0;nt<NTN;nt++)
                    mma8(acc[mt][nt], af[mt], &bf[nt>>1][(nt&1)*2]);
        }
        if (tc + 2 < total) load_stage((tc+2) % 3, tc+2);
        asm volatile("cp.async.commit_group;");

        if (++cc == NC){
            cc = 0;
            int rep = tc / NC;
            int bn0 = (blockIdx.y * jb.nrep + rep) * NT;
            #pragma unroll
            for (int mt=0;mt<2;mt++){
                #pragma unroll
                for (int nt=0;nt<NTN;nt++){
                    #pragma unroll
                    for (int half=0; half<2; half++){
                        int row = bm0 + wm + mt*16 + grp + half*8;
                        int col = bn0 + wn + nt*8 + thr*2;
                        float v0 = acc[mt][nt][half*2+0];
                        float v1 = acc[mt][nt][half*2+1];
                        if (jb.bias){ v0 += jb.bias[col]; v1 += jb.bias[col+1]; }
                        if (jb.mode==1){ v0 = tanhf(v0); v1 = tanhf(v1); }
                        else if (jb.mode==2){ v0 = jb.scale*sigm_(v0); v1 = jb.scale*sigm_(v1); }
                        else if (jb.mode==3){
                            v0 = (col   < 64) ? tanhf(v0) : (col   < 192 ? v0 : sigm_(v0));
                            v1 = (col+1 < 64) ? tanhf(v1) : (col+1 < 192 ? v1 : sigm_(v1));
                        }
                        if (jb.round_out){ v0 = to_tf32(v0); v1 = to_tf32(v1); }
                        float* cp = jb.C + (size_t)row*jb.ldc + col;
                        cp[0] = v0; cp[1] = v1;
                        acc[mt][nt][half*2+0] = 0.f;
                        acc[mt][nt][half*2+1] = 0.f;
                    }
                }
            }
        }
    }
}

// ---------------- fused elementwise prep: weights + token-shift mix ----------------
__device__ __forceinline__ void do_tr(const float* src, float* dst, int rows, int cols, int li){
    int r = li / cols, c = li - r * cols;
    dst[(size_t)c * rows + r] = to_tf32(src[li]);
}
__global__ __launch_bounds__(256) void elem_prep(
    const float* __restrict__ Wr, const float* __restrict__ Wk,
    const float* __restrict__ Wv, const float* __restrict__ Wo,
    const float* __restrict__ w1, const float* __restrict__ a1,
    const float* __restrict__ v1, const float* __restrict__ g1,
    const float* __restrict__ w2, const float* __restrict__ a2,
    const float* __restrict__ v2, const float* __restrict__ g2,
    const float* __restrict__ x_w, const float* __restrict__ x_a,
    const float* __restrict__ x_v, const float* __restrict__ x_g,
    const float* __restrict__ x,
    const float* __restrict__ mr, const float* __restrict__ mk, const float* __restrict__ mv,
    float* __restrict__ Sg)
{
    if (blockIdx.x >= 20096){
        int row = blockIdx.x - 20096;
        int t = row & (TT-1);
        int c4 = threadIdx.x;
        const float4* xv4 = (const float4*)x;
        float4 xc = xv4[(size_t)row*256 + c4];
        float4 xp = make_float4(0.f,0.f,0.f,0.f);
        if (t > 0) xp = xv4[(size_t)(row-1)*256 + c4];
        float4 dx = make_float4(xp.x-xc.x, xp.y-xc.y, xp.z-xc.z, xp.w-xc.w);
        size_t o = (size_t)row*256 + c4;
        float4 m;
        #define MIXOUT(dst, mp) \
            m = ((const float4*)mp)[c4]; \
            ((float4*)(Sg+dst))[o] = make_float4(to_tf32(xc.x+dx.x*m.x), to_tf32(xc.y+dx.y*m.y), \
                                                 to_tf32(xc.z+dx.z*m.z), to_tf32(xc.w+dx.w*m.w));
        MIXOUT(OXR, mr) MIXOUT(OXK, mk) MIXOUT(OXV, mv)
        #undef MIXOUT
        float4* xcp = (float4*)(Sg + OXC + (size_t)row*2048);
        xcp[c4]       = make_float4(to_tf32(xc.x), to_tf32(xc.y), to_tf32(xc.z), to_tf32(xc.w));
        xcp[256 + c4] = make_float4(to_tf32(dx.x), to_tf32(dx.y), to_tf32(dx.z), to_tf32(dx.w));
        return;
    }
    int idx = blockIdx.x * 256 + threadIdx.x;
    if (idx < 4194304){
        int m = idx >> 20;
        int i = idx & 1048575;
        const float* src = (m == 0) ? Wr : (m == 1) ? Wk : (m == 2) ? Wv : Wo;
        float* dst = Sg + ((m == 0) ? OWRr : (m == 1) ? OWKr : (m == 2) ? OWVr : OWOr);
        dst[i] = to_tf32(src[i]);
        return;
    }
    idx -= 4194304;
    if (idx < 655360){
        int n = idx >> 11;
        int k = idx & 2047;
        int kk = k & 1023;
        float val = 0.f;
        if (n < 64){
            float w = w1[kk*64 + n];
            val = (k < 1024) ? w : x_w[kk]*w;
        } else if (n < 128){
            float w = a1[kk*64 + (n-64)];
            val = (k < 1024) ? w : x_a[kk]*w;
        } else if (n < 160){
            float w = v1[kk*32 + (n-128)];
            val = (k < 1024) ? w : x_v[kk]*w;
        } else if (n >= 192){
            float w = g1[kk*128 + (n-192)];
            val = (k < 1024) ? w : x_g[kk]*w;
        }
        Sg[OBU + idx] = to_tf32(val);
        return;
    }
    int j = idx - 655360;
    if (j >= 294912) return;
    if      (j < 65536 )  do_tr(w2, Sg+OW2T, 64, 1024,  j);
    else if (j < 131072)  do_tr(a2, Sg+OA2T, 64, 1024,  j-65536);
    else if (j < 163840)  do_tr(v2, Sg+OV2T, 32, 1024,  j-131072);
    else                  do_tr(g2, Sg+OG2T, 128, 1024, j-163840);
}

// ---------------- H = act(Hlo + Hhi) ----------------
__global__ __launch_bounds__(256) void hsum_act(
    const float* __restrict__ Hlo, const float* __restrict__ Hhi, float* __restrict__ H)
{
    int i = blockIdx.x*256 + threadIdx.x;
    if (i >= 4096*80) return;
    int row = i / 80, q = i - row*80;
    int col = q*4;
    size_t off = (size_t)row*320 + col;
    float4 a = *(const float4*)&Hlo[off];
    float4 b = *(const float4*)&Hhi[off];
    float v[4] = {a.x+b.x, a.y+b.y, a.z+b.z, a.w+b.w};
    #pragma unroll
    for (int j=0;j<4;j++){
        int c = col + j;
        float xx = v[j];
        xx = (c < 64) ? tanhf(xx) : (c < 192 ? xx : sigm_(xx));
        v[j] = to_tf32(xx);
    }
    *(float4*)&H[off] = make_float4(v[0], v[1], v[2], v[3]);
}

// ---------------- scan-operand prep (with fused look-ahead MA/BG) ----------------
__global__ __launch_bounds__(256) void prep_kernel(
    const float* __restrict__ K, const float* __restrict__ A, const float* __restrict__ V,
    const float* __restrict__ WL, const float* __restrict__ VMIX, const float* __restrict__ vfirst,
    const float* __restrict__ k_k, const float* __restrict__ k_a,
    float* __restrict__ EW, float* __restrict__ BBo,
    float* __restrict__ K2o, float* __restrict__ Vo,
    float* __restrict__ MA, float* __restrict__ BG)
{
    int gw = (blockIdx.x*256 + threadIdx.x) >> 5;
    int lane = threadIdx.x & 31;
    int h = gw & 15, t = (gw >> 4) & 1023, b = gw >> 14;
    int c = h*64 + lane*2;
    size_t btc = ((size_t)(b*TT + t))*CC + c;
    float2 k  = *(const float2*)&K[btc];
    float2 kw = *(const float2*)&k_k[c];
    float2 ka = *(const float2*)&k_a[c];
    float2 a  = *(const float2*)&A[btc];
    float kk0 = k.x*kw.x, kk1 = k.y*kw.y;
    // next-token kk (for look-ahead)
    float2 kn = make_float2(0.f, 0.f);
    if (t < TT-1) kn = *(const float2*)&K[btc + CC];
    float kn0 = kn.x*kw.x, kn1 = kn.y*kw.y;
    float ss  = kk0*kk0 + kk1*kk1;
    float ssn = kn0*kn0 + kn1*kn1;
    #pragma unroll
    for (int off=16; off>0; off>>=1){
        ss  += __shfl_xor_sync(0xffffffffu, ss, off);
        ssn += __shfl_xor_sync(0xffffffffu, ssn, off);
    }
    float inv  = 1.f / fmaxf(sqrtf(ss), 1e-12f);
    float invn = 1.f / fmaxf(sqrtf(ssn), 1e-12f);
    kk0 *= inv; kk1 *= inv;
    float aan0 = -kn0*invn, aan1 = -kn1*invn;   // AA_{t+1}

    float2 wl = *(const float2*)&WL[btc];
    float2 v  = *(const float2*)&V[btc];
    float2 vf = *(const float2*)&vfirst[btc];
    float2 vm = *(const float2*)&VMIX[btc];
    v.x = v.x + (vf.x - v.x)*vm.x;
    v.y = v.y + (vf.y - v.y)*vm.y;
    float k20 = k.x*(1.f + (a.x-1.f)*ka.x);
    float k21 = k.y*(1.f + (a.y-1.f)*ka.y);
    float ew0 = expf(wl.x), ew1 = expf(wl.y);
    float bb0 = kk0*a.x, bb1 = kk1*a.y;

    float bsum = bb0*aan0 + bb1*aan1;
    float gsum = k20*aan0 + k21*aan1;
    #pragma unroll
    for (int off=16; off>0; off>>=1){
        bsum += __shfl_xor_sync(0xffffffffu, bsum, off);
        gsum += __shfl_xor_sync(0xffffffffu, gsum, off);
    }

    size_t bhtd = ((size_t)((b*HH + h)*TT + t))*64 + lane*2;
    *(float2*)&EW[bhtd]  = make_float2(ew0, ew1);
    *(float2*)&BBo[bhtd] = make_float2(bb0, bb1);
    *(float2*)&K2o[bhtd] = make_float2(k20, k21);
    *(float2*)&Vo[bhtd]  = v;
    *(float2*)&MA[bhtd]  = make_float2(ew0*aan0, ew1*aan1);
    if (lane == 0)
        *(float2*)&BG[((size_t)(b*HH + h)*TT + t)*2] = make_float2(bsum, gsum);
}

// ---------------- scan v4: look-ahead recurrence, 128 thr, 4 rows x 4 cols ----------------
__global__ void __launch_bounds__(128) scan_kernel(
    const float* __restrict__ EW, const float* __restrict__ BBp, const float* __restrict__ MAp,
    const float* __restrict__ K2p, const float* __restrict__ RB, const float* __restrict__ Vp,
    const float* __restrict__ BG, float* __restrict__ O4)
{
    __shared__ float sm[16*6*64];
    __shared__ float bg_sm[32];
    int bh = blockIdx.x >> 1;
    int b = bh >> 4, h = bh & 15;
    int rowBase = (blockIdx.x & 1) * 32;
    int tid = threadIdx.x;
    int cg = tid & 15;
    int rg = tid >> 4;
    int col0 = cg * 4;
    size_t base = (size_t)bh * TT * 64;
    size_t base4 = (size_t)bh * TT * 256;
    const float* BGp = BG + (size_t)bh * TT * 2;

    const float* mysrc = nullptr; int mystride = 64;
    int arr = tid >> 4, seg = tid & 15;
    if (tid < 96){
        switch (arr){
            case 0: mysrc = EW  + base; break;
            case 1: mysrc = BBp + base; break;
            case 2: mysrc = MAp + base; break;
            case 3: mysrc = K2p + base; break;
            case 4: mysrc = RB + (size_t)b*TT*CC + h*64; mystride = CC; break;
            case 5: mysrc = Vp  + base; break;
        }
    }
    uint32_t smb = (uint32_t)__cvta_generic_to_shared(sm);
    uint32_t smbg = (uint32_t)__cvta_generic_to_shared(bg_sm);

    auto pf4 = [&](int batch){
        if (tid < 96){
            #pragma unroll
            for (int u=0; u<4; u++){
                int t = batch*4 + u;
                const float* g = mysrc + (size_t)t*mystride + seg*4;
                unsigned sa = smb + 4u*(uint32_t)(((t&15)*384) + arr*64 + seg*4);
                asm volatile("cp.async.ca.shared.global [%0], [%1], 16;"::"r"(sa),"l"(g));
            }
        } else if (tid < 98){
            const float* g = BGp + (size_t)batch*8 + (tid-96)*4;
            unsigned sa = smbg + 4u*(uint32_t)((((batch*4)&15)*2) + (tid-96)*4);
            asm volatile("cp.async.ca.shared.global [%0], [%1], 16;"::"r"(sa),"l"(g));
        }
        asm volatile("cp.async.commit_group;");
    };

    pf4(0); pf4(1); pf4(2);

    u64 S2[4][2];
    float sab[4];
    #pragma unroll
    for (int j=0;j<4;j++){ S2[j][0]=0ull; S2[j][1]=0ull; sab[j]=0.f; }

    for (int i=0; i<256; i++){
        asm volatile("cp.async.wait_group 2;");
        __syncthreads();
        if (i+3 < 256) pf4(i+3);
        else asm volatile("cp.async.commit_group;");
        int tb = i*4;

        #pragma unroll
        for (int u=0; u<4; u++){
            const float* st = &sm[((tb+u) & 15) * 384];
            u64 ew2[2], bb2[2], ma2[2], kk2[2], rr2[2];
            #define LD2(dst, off) { \
                ulonglong2 q = *(const ulonglong2*)&st[(off)+col0]; \
                dst[0]=q.x; dst[1]=q.y; }
            LD2(ew2,   0) LD2(bb2,  64) LD2(ma2, 128) LD2(kk2, 192) LD2(rr2, 256)
            #undef LD2
            float vv[4];
            #pragma unroll
            for (int j=0;j<4;j++) vv[j] = st[320 + rowBase + rg + 8*j];
            float2 bg = *(const float2*)&bg_sm[((tb+u)&15)*2];

            float Dp[4];
            #pragma unroll
            for (int j=0;j<4;j++)
                Dp[j] = HADD2(FMA2(S2[j][1], ma2[1], MUL2(S2[j][0], ma2[0])));
            #pragma unroll
            for (int j=0;j<4;j++){
                Dp[j] += __shfl_xor_sync(0xffffffffu, Dp[j], 1);
                Dp[j] += __shfl_xor_sync(0xffffffffu, Dp[j], 2);
                Dp[j] += __shfl_xor_sync(0xffffffffu, Dp[j], 4);
                Dp[j] += __shfl_xor_sync(0xffffffffu, Dp[j], 8);
            }

            float po[4];
            #pragma unroll
            for (int j=0;j<4;j++){
                u64 sab2 = PK2(sab[j]), vv2 = PK2(vv[j]);
                S2[j][0] = FMA2(kk2[0], vv2, FMA2(bb2[0], sab2, MUL2(S2[j][0], ew2[0])));
                S2[j][1] = FMA2(kk2[1], vv2, FMA2(bb2[1], sab2, MUL2(S2[j][1], ew2[1])));
                po[j] = HADD2(FMA2(S2[j][1], rr2[1], MUL2(S2[j][0], rr2[0])));
                po[j] += __shfl_xor_sync(0xffffffffu, po[j], 1);
                po[j] += __shfl_xor_sync(0xffffffffu, po[j], 2);
            }
            #pragma unroll
            for (int j=0;j<4;j++)
                sab[j] = Dp[j] + sab[j]*bg.x + vv[j]*bg.y;

            if ((tid & 3) == 0){
                size_t ob = base4 + (size_t)(tb+u)*256;
                int p = cg >> 2;
                #pragma unroll
                for (int j=0;j<4;j++)
                    O4[ob + (size_t)(rowBase + rg + 8*j)*4 + p] = po[j];
            }
        }
    }
}

// ---------------- post: sum partials + groupnorm + bonus + gate ----------------
__global__ __launch_bounds__(256) void post_kernel(
    const float* __restrict__ O4, const float* __restrict__ RB, const float* __restrict__ K2p,
    const float* __restrict__ Vp, const float* __restrict__ G,
    const float* __restrict__ r_k, const float* __restrict__ gn_w, const float* __restrict__ gn_b,
    float* __restrict__ Z)
{
    int gw = (blockIdx.x*256 + threadIdx.x) >> 5;
    int lane = threadIdx.x & 31;
    int h = gw & 15, t = (gw >> 4) & 1023, b = gw >> 14;
    size_t bhtd = ((size_t)((b*HH + h)*TT + t))*64 + lane*2;
    int c = h*64 + lane*2;
    size_t btc = ((size_t)(b*TT + t))*CC + c;

    size_t b4 = ((size_t)(b*HH + h))*TT*256 + (size_t)t*256 + (size_t)lane*8;
    float4 pa = *(const float4*)&O4[b4];
    float4 pb = *(const float4*)&O4[b4 + 4];
    float2 o = make_float2(pa.x+pa.y+pa.z+pa.w, pb.x+pb.y+pb.z+pb.w);

    float sm = o.x + o.y;
    #pragma unroll
    for (int off=16; off>0; off>>=1) sm += __shfl_xor_sync(0xffffffffu, sm, off);
    float mean = sm * (1.f/64.f);
    float dx = o.x - mean, dy = o.y - mean;
    float vs = dx*dx + dy*dy;
    #pragma unroll
    for (int off=16; off>0; off>>=1) vs += __shfl_xor_sync(0xffffffffu, vs, off);
    float inv = rsqrtf(vs*(1.f/64.f) + GN_EPS);

    float2 r  = *(const float2*)&RB[btc];
    float2 k2 = *(const float2*)&K2p[bhtd];
    float2 v  = *(const float2*)&Vp[bhtd];
    float2 rk = *(const float2*)&r_k[c];
    float bs = r.x*k2.x*rk.x + r.y*k2.y*rk.y;
    #pragma unroll
    for (int off=16; off>0; off>>=1) bs += __shfl_xor_sync(0xffffffffu, bs, off);

    float2 g  = *(const float2*)&G[btc];
    float2 w  = *(const float2*)&gn_w[c];
    float2 bb = *(const float2*)&gn_b[c];
    float z0 = ((dx*inv)*w.x + bb.x + bs*v.x) * g.x;
    float z1 = ((dy*inv)*w.y + bb.y + bs*v.y) * g.y;
    *(float2*)&Z[btc] = make_float2(to_tf32(z0), to_tf32(z1));
}

// ---------------- driver ----------------
static inline GJob mkjob(const float* A, int lda, const float* B, int ldb, float* C, int ldc,
                         int N, int K, const float* bias, int mode, float scale, int ro,
                         int nrep, int ny){
    GJob j; j.A=A; j.B=B; j.C=C; j.bias=bias; j.lda=lda; j.ldb=ldb; j.ldc=ldc;
    j.N=N; j.K=K; j.mode=mode; j.scale=scale; j.round_out=ro; j.nrep=nrep; j.ny=ny; return j;
}

extern "C" void kernel_launch(void* const* d_in, const int* in_sizes, int n_in,
                              void* d_out, int out_size) {
    const float* x   = (const float*)d_in[0];
    const float* vfi = (const float*)d_in[1];
    const float* x_r = (const float*)d_in[2];
    const float* x_w = (const float*)d_in[3];
    const float* x_k = (const float*)d_in[4];
    const float* x_v = (const float*)d_in[5];
    const float* x_a = (const float*)d_in[6];
    const float* x_g = (const float*)d_in[7];
    const float* Wr  = (const float*)d_in[8];
    const float* Wk  = (const float*)d_in[9];
    const float* Wv  = (const float*)d_in[10];
    const float* Wo  = (const float*)d_in[11];
    const float* w0  = (const float*)d_in[12];
    const float* w1  = (const float*)d_in[13];
    const float* w2  = (const float*)d_in[14];
    const float* a0  = (const float*)d_in[15];
    const float* a1  = (const float*)d_in[16];
    const float* a2  = (const float*)d_in[17];
    const float* v0  = (const float*)d_in[18];
    const float* v1  = (const float*)d_in[19];
    const float* v2  = (const float*)d_in[20];
    const float* g1  = (const float*)d_in[21];
    const float* g2  = (const float*)d_in[22];
    const float* k_k = (const float*)d_in[23];
    const float* k_a = (const float*)d_in[24];
    const float* r_k = (const float*)d_in[25];
    const float* gnw = (const float*)d_in[26];
    const float* gnb = (const float*)d_in[27];
    float* out = (float*)d_out;

    float* S;
    cudaGetSymbolAddress((void**)&S, gScratch);

    const int SM128 = 3*(128+128)*32*4;   // 98304
    const int SM64  = 3*(128+64)*32*4;    // 73728
    cudaFuncSetAttribute(gemm_mma<128>, cudaFuncAttributeMaxDynamicSharedMemorySize, SM128);
    cudaFuncSetAttribute(gemm_mma<64>,  cudaFuncAttributeMaxDynamicSharedMemorySize, SM64);

    const int M = BB*TT;
    float* H = S + OHST;

    // 0: fused elementwise prep
    elem_prep<<<24192, 256>>>(Wr, Wk, Wv, Wo, w1, a1, v1, g1, w2, a2, v2, g2,
                              x_w, x_a, x_v, x_g, x, x_r, x_k, x_v, S);
    // 1: stage-1 split-K halves
    {
        GPack p{};
        p.j[0] = mkjob(S+OXC,      2048, S+OBU,      2048, S+OHLO, 320, 320, 1024, nullptr, 0, 1.f, 0, 1, 5);
        p.j[1] = mkjob(S+OXC+1024, 2048, S+OBU+1024, 2048, S+OHHI, 320, 320, 1024, nullptr, 0, 1.f, 0, 1, 5);
        gemm_mma<64><<<dim3(M/128,5,2), 256, SM64>>>(p);
    }
    // 2: H = act(Hlo + Hhi)
    hsum_act<<<1280, 256>>>(S+OHLO, S+OHHI, H);
    // 3: MERGED: R/K/V projections + stage-2 low-rank outputs (7 jobs)  <-- profiled (idx 3)
    {
        GPack p{};
        p.j[0] = mkjob(S+OXR, 1024, S+OWRr, 1024, S+ORB, 1024, 1024, 1024, nullptr, 0, 1.f, 0, 1, 8);
        p.j[1] = mkjob(S+OXK, 1024, S+OWKr, 1024, S+OKB, 1024, 1024, 1024, nullptr, 0, 1.f, 0, 1, 8);
        p.j[2] = mkjob(S+OXV, 1024, S+OWVr, 1024, S+OVB, 1024, 1024, 1024, nullptr, 0, 1.f, 0, 1, 8);
        p.j[3] = mkjob(H+0,   320, S+OW2T, 64,  S+OWL,  1024, 1024, 64,  w0, 2, LOG_DECAY, 0, 4, 2);
        p.j[4] = mkjob(H+64,  320, S+OA2T, 64,  S+OAB,  1024, 1024, 64,  a0, 2, 1.f, 0, 4, 2);
        p.j[5] = mkjob(H+128, 320, S+OV2T, 32,  S+OVMX, 1024, 1024, 32,  v0, 2, 1.f, 0, 4, 2);
        p.j[6] = mkjob(H+192, 320, S+OG2T, 128, S+OGB,  1024, 1024, 128, nullptr, 0, 1.f, 0, 4, 2);
        gemm_mma<128><<<dim3(M/128,8,7), 256, SM128>>>(p);
    }
    // 4: scan operand prep (fused look-ahead MA/BG)
    prep_kernel<<<(BB*TT*HH*32)/256, 256>>>(S+OKB, S+OAB, S+OVB, S+OWL, S+OVMX, vfi,
                                            k_k, k_a,
                                            S+OEW, S+OBBA, S+OKK2, S+OVVA, S+OMA, S+OBG);
    // 5: sequential scan v4
    scan_kernel<<<BB*HH*2, 128>>>(S+OEW, S+OBBA, S+OMA, S+OKK2, S+ORB, S+OVVA, S+OBG, S+OO4);
    // 6: sum partials + groupnorm + bonus + gate
    post_kernel<<<(BB*TT*HH*32)/256, 256>>>(S+OO4, S+ORB, S+OKK2, S+OVVA, S+OGB,
                                            r_k, gnw, gnb, S+OZB);
    // 7: out = Z @ Wo^T
    {
        GPack p{};
        p.j[0] = mkjob(S+OZB, 1024, S+OWOr, 1024, out, 1024, 1024, 1024, nullptr, 0, 1.f, 0, 1, 8);
        gemm_mma<128><<<dim3(M/128,8,1), 256, SM128>>>(p);
    }
    // v_first passthrough
    if (out_size >= 2*NE){
        cudaMemcpyAsync(out + NE, vfi, (size_t)NE*sizeof(float), cudaMemcpyDeviceToDevice);
    }
}

// round 13
// speedup vs baseline: 2.7043x; 1.0489x over previous
#include <cuda_runtime.h>
#include <math.h>
#include <stdint.h>

#define BB 4
#define TT 1024
#define CC 1024
#define HH 16
#define DD 64
#define NE 4194304     // B*T*C
#define LOG_DECAY (-0.6065306597126334f)
#define GN_EPS 64e-5f

typedef unsigned long long u64;

// ---------------- static scratch ----------------
__device__ float gScratch[104857600];

#define OO4  ((size_t)0)               // scan partials (slots 0-3)
#define OXR  ((size_t)0*NE)
#define OXK  ((size_t)2*NE)
#define OXV  ((size_t)3*NE)
#define OXC  ((size_t)4*NE)            // [x | xx] (slots 4-5)
#define ORB  ((size_t)6*NE)
#define OKB  ((size_t)7*NE)
#define OVB  ((size_t)8*NE)
#define OAB  ((size_t)9*NE)
#define OGB  ((size_t)10*NE)
#define OWL  ((size_t)11*NE)
#define OVMX ((size_t)12*NE)
#define OHST ((size_t)13*NE)
#define OHLO ((size_t)14*NE)           // dead after hsum_act -> reused as MA
#define OHHI ((size_t)15*NE)           // dead after hsum_act -> reused as BG
#define OMA  OHLO
#define OBG  OHHI
#define OEW  ((size_t)16*NE)
#define OBBA ((size_t)17*NE)
#define OKK2 ((size_t)19*NE)
#define OVVA ((size_t)20*NE)
#define OZB  ((size_t)21*NE)
#define OW2T ((size_t)22*NE)
#define OA2T (OW2T + 65536)
#define OV2T (OA2T + 65536)
#define OG2T (OV2T + 32768)
#define OWRr (OG2T + 131072)
#define OWKr (OWRr + 1048576)
#define OWVr (OWKr + 1048576)
#define OWOr (OWVr + 1048576)
#define OBU  (OWOr + 1048576)

__device__ __forceinline__ float to_tf32(float x){
    uint32_t u; asm("cvt.rna.tf32.f32 %0, %1;" : "=r"(u) : "f"(x));
    return __uint_as_float(u);
}
__device__ __forceinline__ float sigm_(float x){ return 1.f/(1.f+expf(-x)); }

__device__ __forceinline__ void mma8(float* d, const uint32_t* a, const uint32_t* b){
    asm volatile("mma.sync.aligned.m16n8k8.row.col.f32.tf32.tf32.f32 "
        "{%0,%1,%2,%3}, {%4,%5,%6,%7}, {%8,%9}, {%0,%1,%2,%3};"
        : "+f"(d[0]), "+f"(d[1]), "+f"(d[2]), "+f"(d[3])
        : "r"(a[0]), "r"(a[1]), "r"(a[2]), "r"(a[3]), "r"(b[0]), "r"(b[1]));
}
__device__ __forceinline__ void ldsm4(uint32_t* r, uint32_t a){
    asm volatile("ldmatrix.sync.aligned.m8n8.x4.shared.b16 {%0,%1,%2,%3}, [%4];"
        : "=r"(r[0]),"=r"(r[1]),"=r"(r[2]),"=r"(r[3]) : "r"(a));
}
__device__ __forceinline__ int swz(int r, int c){
    return r*32 + (int)((((((unsigned)c>>2) ^ ((unsigned)r & 7u)) << 2)) | ((unsigned)c & 3u));
}

// f32x2 packed math helpers
__device__ __forceinline__ u64 FMA2(u64 a, u64 b, u64 c){
    u64 d; asm("fma.rn.f32x2 %0, %1, %2, %3;" : "=l"(d) : "l"(a), "l"(b), "l"(c)); return d;
}
__device__ __forceinline__ u64 MUL2(u64 a, u64 b){
    u64 d; asm("mul.rn.f32x2 %0, %1, %2;" : "=l"(d) : "l"(a), "l"(b)); return d;
}
__device__ __forceinline__ u64 PK2(float x){
    u64 d; asm("mov.b64 %0, {%1, %1};" : "=l"(d) : "f"(x)); return d;
}
__device__ __forceinline__ float HADD2(u64 d){
    float a, b; asm("mov.b64 {%0, %1}, %2;" : "=f"(a), "=f"(b) : "l"(d)); return a + b;
}

// ---------------- job descriptor for batched GEMM ----------------
struct GJob {
    const float* A; const float* B; float* C; const float* bias;
    int lda, ldb, ldc, N, K, mode; float scale; int round_out; int nrep; int ny;
};
struct GPack { GJob j[8]; };

// ---------------- tf32 GEMM: C = A * B^T, z-batched pack, pipelined n-rep, ny early-exit ----
template<int NT>
__global__ void __launch_bounds__(256,2) gemm_mma(GPack p)
{
    extern __shared__ float sm[];
    const int AS  = 128*32;
    const int STG = (128+NT)*32;
    const int NTN = (NT==128) ? 8 : 4;
    const int NLD = NTN/2;

    GJob jb = p.j[blockIdx.z];
    if ((int)blockIdx.y >= jb.ny) return;

    int tid = threadIdx.x, wid = tid >> 5, lane = tid & 31;
    int bm0 = blockIdx.x * 128;
    int grp = lane >> 2, thr = lane & 3;
    int wm = (wid & 3) * 32;
    int wn = (NT==128) ? (wid >> 2) * 64 : (wid >> 2) * 32;
    int NC = jb.K >> 5;
    int total = jb.nrep * NC;
    int bnBase = blockIdx.y * jb.nrep;

    uint32_t smb = (uint32_t)__cvta_generic_to_shared(sm);

    uint32_t aoff[2][4], boff[NLD][4];
    #pragma unroll
    for (int mt=0;mt<2;mt++)
      #pragma unroll
      for (int kk=0;kk<4;kk++){
        int row = wm + mt*16 + (lane & 15);
        int col = kk*8 + (lane >> 4) * 4;
        aoff[mt][kk] = 4u * (uint32_t)swz(row, col);
      }
    #pragma unroll
    for (int np=0;np<NLD;np++)
      #pragma unroll
      for (int kk=0;kk<4;kk++){
        int row = wn + np*16 + (lane & 7) + ((lane >> 4) & 1) * 8;
        int col = kk*8 + ((lane >> 3) & 1) * 4;
        boff[np][kk] = 4u * (uint32_t)(AS + swz(row, col));
      }

    // per-thread base offsets for cp.async (hoisted)
    int ar = tid >> 3, aj = tid & 7;

    auto load_stage = [&](int stg, int rep, int c){
        const float* Ag = jb.A + (size_t)bm0 * jb.lda + c*32;
        #pragma unroll
        for (int i=0;i<4;i++){
            int r = ar + 32*i;
            unsigned dst = smb + 4u*(uint32_t)(stg*STG + swz(r, aj*4));
            const float* src = Ag + (size_t)r*jb.lda + aj*4;
            asm volatile("cp.async.cg.shared.global [%0], [%1], 16;"::"r"(dst),"l"(src));
        }
        int bn = (bnBase + rep) * NT;
        const float* Bg = jb.B + (size_t)bn * jb.ldb + c*32;
        #pragma unroll
        for (int i=0;i<NT/32;i++){
            int r = ar + 32*i;
            unsigned dst = smb + 4u*(uint32_t)(stg*STG + AS + swz(r, aj*4));
            const float* src = Bg + (size_t)r*jb.ldb + aj*4;
            asm volatile("cp.async.cg.shared.global [%0], [%1], 16;"::"r"(dst),"l"(src));
        }
    };

    float acc[2][NTN][4];
    #pragma unroll
    for (int i=0;i<2;i++)
      #pragma unroll
      for (int j=0;j<NTN;j++)
        #pragma unroll
        for (int l=0;l<4;l++) acc[i][j][l]=0.f;

    // prefetch position counters (no division)
    int pr = 0, pc = 0;
    load_stage(0, pr, pc);
    if (++pc == NC){ pc = 0; ++pr; }
    asm volatile("cp.async.commit_group;");
    if (total > 1){
        load_stage(1, pr, pc);
        if (++pc == NC){ pc = 0; ++pr; }
    }
    asm volatile("cp.async.commit_group;");

    int cstg = 0, pstg = 2;
    int cc = 0, erep = 0;
    for (int tc = 0; tc < total; tc++){
        asm volatile("cp.async.wait_group 1;");
        __syncthreads();
        uint32_t sb = smb + 4u*(uint32_t)(cstg * STG);
        #pragma unroll
        for (int kk=0; kk<4; kk++){
            uint32_t af[2][4];
            ldsm4(af[0], sb + aoff[0][kk]);
            ldsm4(af[1], sb + aoff[1][kk]);
            uint32_t bf[NLD][4];
            #pragma unroll
            for (int np=0;np<NLD;np++) ldsm4(bf[np], sb + boff[np][kk]);
            #pragma unroll
            for (int mt=0;mt<2;mt++)
                #pragma unroll
                for (int nt=0;nt<NTN;nt++)
                    mma8(acc[mt][nt], af[mt], &bf[nt>>1][(nt&1)*2]);
        }
        if (tc + 2 < total){
            load_stage(pstg, pr, pc);
            if (++pc == NC){ pc = 0; ++pr; }
        }
        asm volatile("cp.async.commit_group;");
        if (++cstg == 3) cstg = 0;
        if (++pstg == 3) pstg = 0;

        if (++cc == NC){
            cc = 0;
            int bn0 = (bnBase + erep) * NT;
            ++erep;
            #pragma unroll
            for (int mt=0;mt<2;mt++){
                #pragma unroll
                for (int nt=0;nt<NTN;nt++){
                    #pragma unroll
                    for (int half=0; half<2; half++){
                        int row = bm0 + wm + mt*16 + grp + half*8;
                        int col = bn0 + wn + nt*8 + thr*2;
                        float v0 = acc[mt][nt][half*2+0];
                        float v1 = acc[mt][nt][half*2+1];
                        if (jb.bias){ v0 += jb.bias[col]; v1 += jb.bias[col+1]; }
                        if (jb.mode==1){ v0 = tanhf(v0); v1 = tanhf(v1); }
                        else if (jb.mode==2){ v0 = jb.scale*sigm_(v0); v1 = jb.scale*sigm_(v1); }
                        else if (jb.mode==3){
                            v0 = (col   < 64) ? tanhf(v0) : (col   < 192 ? v0 : sigm_(v0));
                            v1 = (col+1 < 64) ? tanhf(v1) : (col+1 < 192 ? v1 : sigm_(v1));
                        }
                        if (jb.round_out){ v0 = to_tf32(v0); v1 = to_tf32(v1); }
                        float* cp = jb.C + (size_t)row*jb.ldc + col;
                        cp[0] = v0; cp[1] = v1;
                        acc[mt][nt][half*2+0] = 0.f;
                        acc[mt][nt][half*2+1] = 0.f;
                    }
                }
            }
        }
    }
}

// ---------------- fused elementwise prep: weights(vec4) + BU + transposes + mix ----------------
__device__ __forceinline__ void do_tr(const float* src, float* dst, int rows, int cols, int li){
    int r = li / cols, c = li - r * cols;
    dst[(size_t)c * rows + r] = to_tf32(src[li]);
}
__global__ __launch_bounds__(256) void elem_prep(
    const float* __restrict__ Wr, const float* __restrict__ Wk,
    const float* __restrict__ Wv, const float* __restrict__ Wo,
    const float* __restrict__ w1, const float* __restrict__ a1,
    const float* __restrict__ v1, const float* __restrict__ g1,
    const float* __restrict__ w2, const float* __restrict__ a2,
    const float* __restrict__ v2, const float* __restrict__ g2,
    const float* __restrict__ x_w, const float* __restrict__ x_a,
    const float* __restrict__ x_v, const float* __restrict__ x_g,
    const float* __restrict__ x,
    const float* __restrict__ mr, const float* __restrict__ mk, const float* __restrict__ mv,
    float* __restrict__ Sg)
{
    int bx = blockIdx.x;
    if (bx < 4096){
        // big-weight rounding, float4
        int idx = bx * 256 + threadIdx.x;       // 0..1048575 float4 slots
        int m = idx >> 18;
        int i = idx & 262143;
        const float* src = (m == 0) ? Wr : (m == 1) ? Wk : (m == 2) ? Wv : Wo;
        float* dst = Sg + ((m == 0) ? OWRr : (m == 1) ? OWKr : (m == 2) ? OWVr : OWOr);
        float4 v = ((const float4*)src)[i];
        ((float4*)dst)[i] = make_float4(to_tf32(v.x), to_tf32(v.y), to_tf32(v.z), to_tf32(v.w));
        return;
    }
    bx -= 4096;
    if (bx < 2560){
        int idx = bx * 256 + threadIdx.x;       // 0..655359
        int n = idx >> 11;
        int k = idx & 2047;
        int kk = k & 1023;
        float val = 0.f;
        if (n < 64){
            float w = w1[kk*64 + n];
            val = (k < 1024) ? w : x_w[kk]*w;
        } else if (n < 128){
            float w = a1[kk*64 + (n-64)];
            val = (k < 1024) ? w : x_a[kk]*w;
        } else if (n < 160){
            float w = v1[kk*32 + (n-128)];
            val = (k < 1024) ? w : x_v[kk]*w;
        } else if (n >= 192){
            float w = g1[kk*128 + (n-192)];
            val = (k < 1024) ? w : x_g[kk]*w;
        }
        Sg[OBU + idx] = to_tf32(val);
        return;
    }
    bx -= 2560;
    if (bx < 1152){
        int j = bx * 256 + threadIdx.x;
        if (j >= 294912) return;
        if      (j < 65536 )  do_tr(w2, Sg+OW2T, 64, 1024,  j);
        else if (j < 131072)  do_tr(a2, Sg+OA2T, 64, 1024,  j-65536);
        else if (j < 163840)  do_tr(v2, Sg+OV2T, 32, 1024,  j-131072);
        else                  do_tr(g2, Sg+OG2T, 128, 1024, j-163840);
        return;
    }
    bx -= 1152;
    {   // token-shift mix, one row per block
        int row = bx;
        int t = row & (TT-1);
        int c4 = threadIdx.x;
        const float4* xv4 = (const float4*)x;
        float4 xc = xv4[(size_t)row*256 + c4];
        float4 xp = make_float4(0.f,0.f,0.f,0.f);
        if (t > 0) xp = xv4[(size_t)(row-1)*256 + c4];
        float4 dx = make_float4(xp.x-xc.x, xp.y-xc.y, xp.z-xc.z, xp.w-xc.w);
        size_t o = (size_t)row*256 + c4;
        float4 m;
        #define MIXOUT(dst, mp) \
            m = ((const float4*)mp)[c4]; \
            ((float4*)(Sg+dst))[o] = make_float4(to_tf32(xc.x+dx.x*m.x), to_tf32(xc.y+dx.y*m.y), \
                                                 to_tf32(xc.z+dx.z*m.z), to_tf32(xc.w+dx.w*m.w));
        MIXOUT(OXR, mr) MIXOUT(OXK, mk) MIXOUT(OXV, mv)
        #undef MIXOUT
        float4* xcp = (float4*)(Sg + OXC + (size_t)row*2048);
        xcp[c4]       = make_float4(to_tf32(xc.x), to_tf32(xc.y), to_tf32(xc.z), to_tf32(xc.w));
        xcp[256 + c4] = make_float4(to_tf32(dx.x), to_tf32(dx.y), to_tf32(dx.z), to_tf32(dx.w));
    }
}

// ---------------- H = act(Hlo + Hhi) ----------------
__global__ __launch_bounds__(256) void hsum_act(
    const float* __restrict__ Hlo, const float* __restrict__ Hhi, float* __restrict__ H)
{
    int i = blockIdx.x*256 + threadIdx.x;
    if (i >= 4096*80) return;
    int row = i / 80, q = i - row*80;
    int col = q*4;
    size_t off = (size_t)row*320 + col;
    float4 a = *(const float4*)&Hlo[off];
    float4 b = *(const float4*)&Hhi[off];
    float v[4] = {a.x+b.x, a.y+b.y, a.z+b.z, a.w+b.w};
    #pragma unroll
    for (int j=0;j<4;j++){
        int c = col + j;
        float xx = v[j];
        xx = (c < 64) ? tanhf(xx) : (c < 192 ? xx : sigm_(xx));
        v[j] = to_tf32(xx);
    }
    *(float4*)&H[off] = make_float4(v[0], v[1], v[2], v[3]);
}

// ---------------- scan-operand prep (with fused look-ahead MA/BG) ----------------
__global__ __launch_bounds__(256) void prep_kernel(
    const float* __restrict__ K, const float* __restrict__ A, const float* __restrict__ V,
    const float* __restrict__ WL, const float* __restrict__ VMIX, const float* __restrict__ vfirst,
    const float* __restrict__ k_k, const float* __restrict__ k_a,
    float* __restrict__ EW, float* __restrict__ BBo,
    float* __restrict__ K2o, float* __restrict__ Vo,
    float* __restrict__ MA, float* __restrict__ BG)
{
    int gw = (blockIdx.x*256 + threadIdx.x) >> 5;
    int lane = threadIdx.x & 31;
    int h = gw & 15, t = (gw >> 4) & 1023, b = gw >> 14;
    int c = h*64 + lane*2;
    size_t btc = ((size_t)(b*TT + t))*CC + c;
    float2 k  = *(const float2*)&K[btc];
    float2 kw = *(const float2*)&k_k[c];
    float2 ka = *(const float2*)&k_a[c];
    float2 a  = *(const float2*)&A[btc];
    float kk0 = k.x*kw.x, kk1 = k.y*kw.y;
    float2 kn = make_float2(0.f, 0.f);
    if (t < TT-1) kn = *(const float2*)&K[btc + CC];
    float kn0 = kn.x*kw.x, kn1 = kn.y*kw.y;
    float ss  = kk0*kk0 + kk1*kk1;
    float ssn = kn0*kn0 + kn1*kn1;
    #pragma unroll
    for (int off=16; off>0; off>>=1){
        ss  += __shfl_xor_sync(0xffffffffu, ss, off);
        ssn += __shfl_xor_sync(0xffffffffu, ssn, off);
    }
    float inv  = 1.f / fmaxf(sqrtf(ss), 1e-12f);
    float invn = 1.f / fmaxf(sqrtf(ssn), 1e-12f);
    kk0 *= inv; kk1 *= inv;
    float aan0 = -kn0*invn, aan1 = -kn1*invn;

    float2 wl = *(const float2*)&WL[btc];
    float2 v  = *(const float2*)&V[btc];
    float2 vf = *(const float2*)&vfirst[btc];
    float2 vm = *(const float2*)&VMIX[btc];
    v.x = v.x + (vf.x - v.x)*vm.x;
    v.y = v.y + (vf.y - v.y)*vm.y;
    float k20 = k.x*(1.f + (a.x-1.f)*ka.x);
    float k21 = k.y*(1.f + (a.y-1.f)*ka.y);
    float ew0 = expf(wl.x), ew1 = expf(wl.y);
    float bb0 = kk0*a.x, bb1 = kk1*a.y;

    float bsum = bb0*aan0 + bb1*aan1;
    float gsum = k20*aan0 + k21*aan1;
    #pragma unroll
    for (int off=16; off>0; off>>=1){
        bsum += __shfl_xor_sync(0xffffffffu, bsum, off);
        gsum += __shfl_xor_sync(0xffffffffu, gsum, off);
    }

    size_t bhtd = ((size_t)((b*HH + h)*TT + t))*64 + lane*2;
    *(float2*)&EW[bhtd]  = make_float2(ew0, ew1);
    *(float2*)&BBo[bhtd] = make_float2(bb0, bb1);
    *(float2*)&K2o[bhtd] = make_float2(k20, k21);
    *(float2*)&Vo[bhtd]  = v;
    *(float2*)&MA[bhtd]  = make_float2(ew0*aan0, ew1*aan1);
    if (lane == 0)
        *(float2*)&BG[((size_t)(b*HH + h)*TT + t)*2] = make_float2(bsum, gsum);
}

// ---------------- scan v4: look-ahead recurrence, 128 thr, 4 rows x 4 cols ----------------
__global__ void __launch_bounds__(128) scan_kernel(
    const float* __restrict__ EW, const float* __restrict__ BBp, const float* __restrict__ MAp,
    const float* __restrict__ K2p, const float* __restrict__ RB, const float* __restrict__ Vp,
    const float* __restrict__ BG, float* __restrict__ O4)
{
    __shared__ float sm[16*6*64];
    __shared__ float bg_sm[32];
    int bh = blockIdx.x >> 1;
    int b = bh >> 4, h = bh & 15;
    int rowBase = (blockIdx.x & 1) * 32;
    int tid = threadIdx.x;
    int cg = tid & 15;
    int rg = tid >> 4;
    int col0 = cg * 4;
    size_t base = (size_t)bh * TT * 64;
    size_t base4 = (size_t)bh * TT * 256;
    const float* BGp = BG + (size_t)bh * TT * 2;

    const float* mysrc = nullptr; int mystride = 64;
    int arr = tid >> 4, seg = tid & 15;
    if (tid < 96){
        switch (arr){
            case 0: mysrc = EW  + base; break;
            case 1: mysrc = BBp + base; break;
            case 2: mysrc = MAp + base; break;
            case 3: mysrc = K2p + base; break;
            case 4: mysrc = RB + (size_t)b*TT*CC + h*64; mystride = CC; break;
            case 5: mysrc = Vp  + base; break;
        }
    }
    uint32_t smb = (uint32_t)__cvta_generic_to_shared(sm);
    uint32_t smbg = (uint32_t)__cvta_generic_to_shared(bg_sm);

    auto pf4 = [&](int batch){
        if (tid < 96){
            #pragma unroll
            for (int u=0; u<4; u++){
                int t = batch*4 + u;
                const float* g = mysrc + (size_t)t*mystride + seg*4;
                unsigned sa = smb + 4u*(uint32_t)(((t&15)*384) + arr*64 + seg*4);
                asm volatile("cp.async.ca.shared.global [%0], [%1], 16;"::"r"(sa),"l"(g));
            }
        } else if (tid < 98){
            const float* g = BGp + (size_t)batch*8 + (tid-96)*4;
            unsigned sa = smbg + 4u*(uint32_t)((((batch*4)&15)*2) + (tid-96)*4);
            asm volatile("cp.async.ca.shared.global [%0], [%1], 16;"::"r"(sa),"l"(g));
        }
        asm volatile("cp.async.commit_group;");
    };

    pf4(0); pf4(1); pf4(2);

    u64 S2[4][2];
    float sab[4];
    #pragma unroll
    for (int j=0;j<4;j++){ S2[j][0]=0ull; S2[j][1]=0ull; sab[j]=0.f; }

    for (int i=0; i<256; i++){
        asm volatile("cp.async.wait_group 2;");
        __syncthreads();
        if (i+3 < 256) pf4(i+3);
        else asm volatile("cp.async.commit_group;");
        int tb = i*4;

        #pragma unroll
        for (int u=0; u<4; u++){
            const float* st = &sm[((tb+u) & 15) * 384];
            u64 ew2[2], bb2[2], ma2[2], kk2[2], rr2[2];
            #define LD2(dst, off) { \
                ulonglong2 q = *(const ulonglong2*)&st[(off)+col0]; \
                dst[0]=q.x; dst[1]=q.y; }
            LD2(ew2,   0) LD2(bb2,  64) LD2(ma2, 128) LD2(kk2, 192) LD2(rr2, 256)
            #undef LD2
            float vv[4];
            #pragma unroll
            for (int j=0;j<4;j++) vv[j] = st[320 + rowBase + rg + 8*j];
            float2 bg = *(const float2*)&bg_sm[((tb+u)&15)*2];

            float Dp[4];
            #pragma unroll
            for (int j=0;j<4;j++)
                Dp[j] = HADD2(FMA2(S2[j][1], ma2[1], MUL2(S2[j][0], ma2[0])));
            #pragma unroll
            for (int j=0;j<4;j++){
                Dp[j] += __shfl_xor_sync(0xffffffffu, Dp[j], 1);
                Dp[j] += __shfl_xor_sync(0xffffffffu, Dp[j], 2);
                Dp[j] += __shfl_xor_sync(0xffffffffu, Dp[j], 4);
                Dp[j] += __shfl_xor_sync(0xffffffffu, Dp[j], 8);
            }

            float po[4];
            #pragma unroll
            for (int j=0;j<4;j++){
                u64 sab2 = PK2(sab[j]), vv2 = PK2(vv[j]);
                S2[j][0] = FMA2(kk2[0], vv2, FMA2(bb2[0], sab2, MUL2(S2[j][0], ew2[0])));
                S2[j][1] = FMA2(kk2[1], vv2, FMA2(bb2[1], sab2, MUL2(S2[j][1], ew2[1])));
                po[j] = HADD2(FMA2(S2[j][1], rr2[1], MUL2(S2[j][0], rr2[0])));
                po[j] += __shfl_xor_sync(0xffffffffu, po[j], 1);
                po[j] += __shfl_xor_sync(0xffffffffu, po[j], 2);
            }
            #pragma unroll
            for (int j=0;j<4;j++)
                sab[j] = Dp[j] + sab[j]*bg.x + vv[j]*bg.y;

            if ((tid & 3) == 0){
                size_t ob = base4 + (size_t)(tb+u)*256;
                int p = cg >> 2;
                #pragma unroll
                for (int j=0;j<4;j++)
                    O4[ob + (size_t)(rowBase + rg + 8*j)*4 + p] = po[j];
            }
        }
    }
}

// ---------------- post: sum partials + groupnorm + bonus + gate ----------------
__global__ __launch_bounds__(256) void post_kernel(
    const float* __restrict__ O4, const float* __restrict__ RB, const float* __restrict__ K2p,
    const float* __restrict__ Vp, const float* __restrict__ G,
    const float* __restrict__ r_k, const float* __restrict__ gn_w, const float* __restrict__ gn_b,
    float* __restrict__ Z)
{
    int gw = (blockIdx.x*256 + threadIdx.x) >> 5;
    int lane = threadIdx.x & 31;
    int h = gw & 15, t = (gw >> 4) & 1023, b = gw >> 14;
    size_t bhtd = ((size_t)((b*HH + h)*TT + t))*64 + lane*2;
    int c = h*64 + lane*2;
    size_t btc = ((size_t)(b*TT + t))*CC + c;

    size_t b4 = ((size_t)(b*HH + h))*TT*256 + (size_t)t*256 + (size_t)lane*8;
    float4 pa = *(const float4*)&O4[b4];
    float4 pb = *(const float4*)&O4[b4 + 4];
    float2 o = make_float2(pa.x+pa.y+pa.z+pa.w, pb.x+pb.y+pb.z+pb.w);

    float sm = o.x + o.y;
    #pragma unroll
    for (int off=16; off>0; off>>=1) sm += __shfl_xor_sync(0xffffffffu, sm, off);
    float mean = sm * (1.f/64.f);
    float dx = o.x - mean, dy = o.y - mean;
    float vs = dx*dx + dy*dy;
    #pragma unroll
    for (int off=16; off>0; off>>=1) vs += __shfl_xor_sync(0xffffffffu, vs, off);
    float inv = rsqrtf(vs*(1.f/64.f) + GN_EPS);

    float2 r  = *(const float2*)&RB[btc];
    float2 k2 = *(const float2*)&K2p[bhtd];
    float2 v  = *(const float2*)&Vp[bhtd];
    float2 rk = *(const float2*)&r_k[c];
    float bs = r.x*k2.x*rk.x + r.y*k2.y*rk.y;
    #pragma unroll
    for (int off=16; off>0; off>>=1) bs += __shfl_xor_sync(0xffffffffu, bs, off);

    float2 g  = *(const float2*)&G[btc];
    float2 w  = *(const float2*)&gn_w[c];
    float2 bb = *(const float2*)&gn_b[c];
    float z0 = ((dx*inv)*w.x + bb.x + bs*v.x) * g.x;
    float z1 = ((dy*inv)*w.y + bb.y + bs*v.y) * g.y;
    *(float2*)&Z[btc] = make_float2(to_tf32(z0), to_tf32(z1));
}

// ---------------- driver ----------------
static inline GJob mkjob(const float* A, int lda, const float* B, int ldb, float* C, int ldc,
                         int N, int K, const float* bias, int mode, float scale, int ro,
                         int nrep, int ny){
    GJob j; j.A=A; j.B=B; j.C=C; j.bias=bias; j.lda=lda; j.ldb=ldb; j.ldc=ldc;
    j.N=N; j.K=K; j.mode=mode; j.scale=scale; j.round_out=ro; j.nrep=nrep; j.ny=ny; return j;
}

extern "C" void kernel_launch(void* const* d_in, const int* in_sizes, int n_in,
                              void* d_out, int out_size) {
    const float* x   = (const float*)d_in[0];
    const float* vfi = (const float*)d_in[1];
    const float* x_r = (const float*)d_in[2];
    const float* x_w = (const float*)d_in[3];
    const float* x_k = (const float*)d_in[4];
    const float* x_v = (const float*)d_in[5];
    const float* x_a = (const float*)d_in[6];
    const float* x_g = (const float*)d_in[7];
    const float* Wr  = (const float*)d_in[8];
    const float* Wk  = (const float*)d_in[9];
    const float* Wv  = (const float*)d_in[10];
    const float* Wo  = (const float*)d_in[11];
    const float* w0  = (const float*)d_in[12];
    const float* w1  = (const float*)d_in[13];
    const float* w2  = (const float*)d_in[14];
    const float* a0  = (const float*)d_in[15];
    const float* a1  = (const float*)d_in[16];
    const float* a2  = (const float*)d_in[17];
    const float* v0  = (const float*)d_in[18];
    const float* v1  = (const float*)d_in[19];
    const float* v2  = (const float*)d_in[20];
    const float* g1  = (const float*)d_in[21];
    const float* g2  = (const float*)d_in[22];
    const float* k_k = (const float*)d_in[23];
    const float* k_a = (const float*)d_in[24];
    const float* r_k = (const float*)d_in[25];
    const float* gnw = (const float*)d_in[26];
    const float* gnb = (const float*)d_in[27];
    float* out = (float*)d_out;

    float* S;
    cudaGetSymbolAddress((void**)&S, gScratch);

    const int SM128 = 3*(128+128)*32*4;   // 98304
    const int SM64  = 3*(128+64)*32*4;    // 73728
    cudaFuncSetAttribute(gemm_mma<128>, cudaFuncAttributeMaxDynamicSharedMemorySize, SM128);
    cudaFuncSetAttribute(gemm_mma<64>,  cudaFuncAttributeMaxDynamicSharedMemorySize, SM64);

    const int M = BB*TT;
    float* H = S + OHST;

    // 0: fused elementwise prep (weights vec4 + BU + transposes + mix)
    elem_prep<<<4096+2560+1152+4096, 256>>>(Wr, Wk, Wv, Wo, w1, a1, v1, g1, w2, a2, v2, g2,
                                            x_w, x_a, x_v, x_g, x, x_r, x_k, x_v, S);
    // 1: stage-1 split-K halves
    {
        GPack p{};
        p.j[0] = mkjob(S+OXC,      2048, S+OBU,      2048, S+OHLO, 320, 320, 1024, nullptr, 0, 1.f, 0, 1, 5);
        p.j[1] = mkjob(S+OXC+1024, 2048, S+OBU+1024, 2048, S+OHHI, 320, 320, 1024, nullptr, 0, 1.f, 0, 1, 5);
        gemm_mma<64><<<dim3(M/128,5,2), 256, SM64>>>(p);
    }
    // 2: H = act(Hlo + Hhi)
    hsum_act<<<1280, 256>>>(S+OHLO, S+OHHI, H);
    // 3: MERGED: R/K/V projections + stage-2 low-rank outputs (7 jobs)  <-- profiled (idx 3)
    {
        GPack p{};
        p.j[0] = mkjob(S+OXR, 1024, S+OWRr, 1024, S+ORB, 1024, 1024, 1024, nullptr, 0, 1.f, 0, 1, 8);
        p.j[1] = mkjob(S+OXK, 1024, S+OWKr, 1024, S+OKB, 1024, 1024, 1024, nullptr, 0, 1.f, 0, 1, 8);
        p.j[2] = mkjob(S+OXV, 1024, S+OWVr, 1024, S+OVB, 1024, 1024, 1024, nullptr, 0, 1.f, 0, 1, 8);
        p.j[3] = mkjob(H+0,   320, S+OW2T, 64,  S+OWL,  1024, 1024, 64,  w0, 2, LOG_DECAY, 0, 4, 2);
        p.j[4] = mkjob(H+64,  320, S+OA2T, 64,  S+OAB,  1024, 1024, 64,  a0, 2, 1.f, 0, 4, 2);
        p.j[5] = mkjob(H+128, 320, S+OV2T, 32,  S+OVMX, 1024, 1024, 32,  v0, 2, 1.f, 0, 4, 2);
        p.j[6] = mkjob(H+192, 320, S+OG2T, 128, S+OGB,  1024, 1024, 128, nullptr, 0, 1.f, 0, 4, 2);
        gemm_mma<128><<<dim3(M/128,8,7), 256, SM128>>>(p);
    }
    // 4: scan operand prep (fused look-ahead MA/BG)
    prep_kernel<<<(BB*TT*HH*32)/256, 256>>>(S+OKB, S+OAB, S+OVB, S+OWL, S+OVMX, vfi,
                                            k_k, k_a,
                                            S+OEW, S+OBBA, S+OKK2, S+OVVA, S+OMA, S+OBG);
    // 5: sequential scan v4
    scan_kernel<<<BB*HH*2, 128>>>(S+OEW, S+OBBA, S+OMA, S+OKK2, S+ORB, S+OVVA, S+OBG, S+OO4);
    // 6: sum partials + groupnorm + bonus + gate
    post_kernel<<<(BB*TT*HH*32)/256, 256>>>(S+OO4, S+ORB, S+OKK2, S+OVVA, S+OGB,
                                            r_k, gnw, gnb, S+OZB);
    // 7: out = Z @ Wo^T
    {
        GPack p{};
        p.j[0] = mkjob(S+OZB, 1024, S+OWOr, 1024, out, 1024, 1024, 1024, nullptr, 0, 1.f, 0, 1, 8);
        gemm_mma<128><<<dim3(M/128,8,1), 256, SM128>>>(p);
    }
    // v_first passthrough
    if (out_size >= 2*NE){
        cudaMemcpyAsync(out + NE, vfi, (size_t)NE*sizeof(float), cudaMemcpyDeviceToDevice);
    }
}